// round 1
// baseline (speedup 1.0000x reference)
#include <cuda_runtime.h>

// ---------------------------------------------------------------------------
// Deformation network, fused single kernel.
//   hidden[255] = concat(point3, rot4, scl3, opa1, shs48, sem128, dx3, t1, tpe64)
//   per head: h = relu(hidden); h1 = relu(h @ W1 + b1); out = h1 @ W2 + b2
//   mask = sigmoid(head_mask); outputs combined with mask.
// One CTA per 64 points (200000 = 64 * 3125). 256 threads.
// GEMM1 register-tiled 8x8 per thread, packed fma.rn.f32x2 (2 FLOP/instr).
// ---------------------------------------------------------------------------

#define DEVI __device__ __forceinline__

DEVI unsigned long long pack2(float x, float y) {
    unsigned long long r;
    asm("mov.b64 %0, {%1, %2};" : "=l"(r) : "f"(x), "f"(y));
    return r;
}
DEVI void unpack2(unsigned long long v, float& x, float& y) {
    asm("mov.b64 {%0, %1}, %2;" : "=f"(x), "=f"(y) : "l"(v));
}
DEVI void fma2(unsigned long long& c, unsigned long long a, unsigned long long b) {
    asm("fma.rn.f32x2 %0, %1, %2, %0;" : "+l"(c) : "l"(a), "l"(b));
}

struct Params {
    const float* opa;   // [N,1]
    const float* shs;   // [N,48]
    const float* tim;   // [N,1]
    const float* sem;   // [N,128]
    const float* pnt;   // [N,3]
    const float* scl;   // [N,3]
    const float* rot;   // [N,4]
    const float* dx;    // [N,3]
    const float* w1[5]; // [255,255] each (mask,pos,scl,rot,shs)
    const float* b1[5]; // [255]
    const float* w2[5]; // [255,od]
    const float* b2[5]; // [od]
    float* out;
    int n;
};

// smem layout (floats)
//  As   [255][64]   relu(hidden)^T                    16320
//  H1   [64][257]   layer-1 activations (padded)      16448
//  Ws   [16][256]   W1 k-tile                          4096
//  W2s  [255*48]    full W2 for current head          12240
//  maskS[64], tpeS[64]
#define OFF_AS    0
#define OFF_H1    16320
#define OFF_WS    (16320 + 16448)
#define OFF_W2S   (16320 + 16448 + 4096)
#define OFF_MASK  (16320 + 16448 + 4096 + 12240)
#define OFF_TPE   (16320 + 16448 + 4096 + 12240 + 64)
#define SMEM_FLOATS (16320 + 16448 + 4096 + 12240 + 64 + 64)

__global__ __launch_bounds__(256, 1)
void deform_kernel(Params p) {
    extern __shared__ float sm[];
    float* As    = sm + OFF_AS;
    float* H1    = sm + OFF_H1;
    float* Ws    = sm + OFF_WS;
    float* W2s   = sm + OFF_W2S;
    float* maskS = sm + OFF_MASK;
    float* tpeS  = sm + OFF_TPE;

    const int tid = threadIdx.x;
    const int g0  = blockIdx.x * 64;
    const int n   = p.n;

    const int pN   = 0;
    const int oPTS = 0;
    const int oSCL = 3 * n;
    const int oROT = 6 * n;
    const int oOP  = 10 * n;
    const int oSHS = 11 * n;
    const int oDX  = 59 * n;
    const int oDSH = 62 * n;
    (void)pN;

    // --- time positional encoding (constant across rows) ---
    if (tid < 32) {
        float t    = p.tim[0];
        float fi   = (float)(2 * tid);
        // freq = 10000^(i/32) = 2^(i * log2(10000)/32)
        float freq = exp2f(fi * (13.287712379549449f / 32.0f));
        float a    = t / freq;
        tpeS[2 * tid]     = sinf(a);
        tpeS[2 * tid + 1] = cosf(a);
    }
    __syncthreads();

    // --- build As[k][m] = relu(hidden[m][k]) ---
    for (int idx = tid; idx < 255 * 64; idx += 256) {
        int m = idx & 63;
        int k = idx >> 6;
        int g = g0 + m;
        float v;
        if      (k < 3)    v = p.pnt[g * 3 + k];
        else if (k < 7)    v = p.rot[g * 4 + (k - 3)];
        else if (k < 10)   v = p.scl[g * 3 + (k - 7)];
        else if (k == 10)  v = p.opa[g];
        else if (k < 59)   v = p.shs[g * 48 + (k - 11)];
        else if (k < 187)  v = p.sem[g * 128 + (k - 59)];
        else if (k < 190)  v = p.dx[g * 3 + (k - 187)];
        else if (k == 190) v = p.tim[g];
        else               v = tpeS[k - 191];
        As[k * 64 + m] = fmaxf(v, 0.0f);
    }

    // opacity pass-through output
    if (tid < 64) p.out[oOP + g0 + tid] = p.opa[g0 + tid];

    __syncthreads();

    const int tn = tid & 31;   // 0..31 -> columns tn*4 and 128+tn*4
    const int tm = tid >> 5;   // 0..7  -> rows tm*8 .. tm*8+7
    const int ODS[5] = {1, 3, 3, 4, 48};

    #pragma unroll 1
    for (int h = 0; h < 5; h++) {
        const float* w1 = p.w1[h];
        const float* b1 = p.b1[h];
        const int od = ODS[h];

        // kick off W2 copy for this head (W2s is free: previous gemm2 synced).
        // LDG latency hides under GEMM1 below.
        for (int idx = tid; idx < 255 * od; idx += 256)
            W2s[idx] = p.w2[h][idx];

        // ---------- GEMM1: C[64,255] = As^T @ W1 ----------
        unsigned long long acc[8][4];
        #pragma unroll
        for (int i = 0; i < 8; i++)
            #pragma unroll
            for (int j = 0; j < 4; j++) acc[i][j] = 0ull;

        // prefetch k-tile 0 into registers
        float pre[16];
        {
            const int cnt = 16 * 255;
            #pragma unroll
            for (int u = 0; u < 16; u++) {
                int idx = tid + u * 256;
                pre[u] = (idx < cnt) ? w1[idx] : 0.0f;
            }
        }

        #pragma unroll 1
        for (int kt = 0; kt < 16; kt++) {
            const int ksz = (kt == 15) ? 15 : 16;
            __syncthreads();   // Ws free (previous inner loop done)
            {
                const int cnt = ksz * 255;
                #pragma unroll
                for (int u = 0; u < 16; u++) {
                    int idx = tid + u * 256;
                    if (idx < cnt) {
                        int r = idx / 255;
                        int c = idx - r * 255;
                        Ws[r * 256 + c] = pre[u];
                    }
                }
            }
            if (kt < 15) {   // prefetch next tile
                const int nksz = (kt == 14) ? 15 : 16;
                const int base = (kt + 1) * 16 * 255;
                const int cnt  = nksz * 255;
                #pragma unroll
                for (int u = 0; u < 16; u++) {
                    int idx = tid + u * 256;
                    pre[u] = (idx < cnt) ? w1[base + idx] : 0.0f;
                }
            }
            __syncthreads();

            const float* ap = As + kt * 16 * 64 + tm * 8;
            const float* bp = Ws + tn * 4;
            #pragma unroll 4
            for (int kk = 0; kk < ksz; kk++) {
                float4 av0 = *(const float4*)(ap + kk * 64);
                float4 av1 = *(const float4*)(ap + kk * 64 + 4);
                float4 bv0 = *(const float4*)(bp + kk * 256);
                float4 bv1 = *(const float4*)(bp + kk * 256 + 128);
                unsigned long long b00 = pack2(bv0.x, bv0.y);
                unsigned long long b01 = pack2(bv0.z, bv0.w);
                unsigned long long b10 = pack2(bv1.x, bv1.y);
                unsigned long long b11 = pack2(bv1.z, bv1.w);
                float a_[8] = {av0.x, av0.y, av0.z, av0.w,
                               av1.x, av1.y, av1.z, av1.w};
                #pragma unroll
                for (int i = 0; i < 8; i++) {
                    unsigned long long a2 = pack2(a_[i], a_[i]);
                    fma2(acc[i][0], a2, b00);
                    fma2(acc[i][1], a2, b01);
                    fma2(acc[i][2], a2, b10);
                    fma2(acc[i][3], a2, b11);
                }
            }
        }

        // ---------- H1 = relu(C + b1)  (scalar stores, stride 257) ----------
        #pragma unroll
        for (int grp = 0; grp < 2; grp++) {
            const int c0 = grp * 128 + tn * 4;
            float bb[4];
            #pragma unroll
            for (int jj = 0; jj < 4; jj++)
                bb[jj] = (c0 + jj < 255) ? b1[c0 + jj] : 0.0f;
            #pragma unroll
            for (int i = 0; i < 8; i++) {
                const int r = tm * 8 + i;
                float x, y, z, w;
                unpack2(acc[i][grp * 2 + 0], x, y);
                unpack2(acc[i][grp * 2 + 1], z, w);
                H1[r * 257 + c0 + 0] = fmaxf(x + bb[0], 0.0f);
                H1[r * 257 + c0 + 1] = fmaxf(y + bb[1], 0.0f);
                H1[r * 257 + c0 + 2] = fmaxf(z + bb[2], 0.0f);
                H1[r * 257 + c0 + 3] = fmaxf(w + bb[3], 0.0f);
            }
        }
        __syncthreads();   // H1 and W2s ready

        // ---------- GEMM2 + epilogue ----------
        if (h == 0) {
            // mask head: od = 1, sigmoid -> maskS
            if (tid < 64) {
                const int m = tid;
                const float* hp = H1 + m * 257;
                float s = 0.0f;
                #pragma unroll 5
                for (int k = 0; k < 255; k++) s += hp[k] * W2s[k];
                s += p.b2[0][0];
                maskS[m] = 1.0f / (1.0f + expf(-s));
            }
        } else if (od <= 4) {
            if (tid < 64 * od) {
                const int m = tid & 63;
                const int o = tid >> 6;
                const float* hp = H1 + m * 257;
                const float* wp = W2s + o;
                float s = 0.0f;
                #pragma unroll 5
                for (int k = 0; k < 255; k++) s += hp[k] * wp[k * od];
                s += p.b2[h][o];
                const int g = g0 + m;
                const float mk = maskS[m];
                if (h == 1) {          // pos: dx_out and pts
                    p.out[oDX  + g * 3 + o] = s;
                    p.out[oPTS + g * 3 + o] = p.pnt[g * 3 + o] + s * mk;
                } else if (h == 2) {   // scales
                    p.out[oSCL + g * 3 + o] = p.scl[g * 3 + o] + s * mk;
                } else {               // rotations
                    p.out[oROT + g * 4 + o] = p.rot[g * 4 + o] + s * mk;
                }
            }
        } else {
            // shs head: od = 48. thread -> (m = tid/4, og = tid%4), 12 outputs.
            const int m  = tid >> 2;
            const int og = tid & 3;
            float s[12];
            #pragma unroll
            for (int j = 0; j < 12; j++) s[j] = 0.0f;
            const float* hp = H1 + m * 257;
            const float4* wp = (const float4*)W2s + og * 3;
            #pragma unroll 3
            for (int k = 0; k < 255; k++) {
                const float hv = hp[k];
                #pragma unroll
                for (int jj = 0; jj < 3; jj++) {
                    float4 wv = wp[k * 12 + jj];
                    s[4 * jj + 0] += hv * wv.x;
                    s[4 * jj + 1] += hv * wv.y;
                    s[4 * jj + 2] += hv * wv.z;
                    s[4 * jj + 3] += hv * wv.w;
                }
            }
            const int g = g0 + m;
            const float mk = maskS[m];
            #pragma unroll
            for (int jj = 0; jj < 3; jj++) {
                #pragma unroll
                for (int e = 0; e < 4; e++) {
                    const int o = og * 12 + 4 * jj + e;
                    const float v = s[4 * jj + e] + p.b2[4][o];
                    p.out[oDSH + g * 48 + o] = v;
                    p.out[oSHS + g * 48 + o] = p.shs[g * 48 + o] + v * mk;
                }
            }
        }
        __syncthreads();   // gemm2 done: W2s/H1 free, maskS visible
    }
}

extern "C" void kernel_launch(void* const* d_in, const int* in_sizes, int n_in,
                              void* d_out, int out_size) {
    Params p;
    p.opa = (const float*)d_in[0];
    p.shs = (const float*)d_in[1];
    p.tim = (const float*)d_in[2];
    p.sem = (const float*)d_in[3];
    p.pnt = (const float*)d_in[4];
    p.scl = (const float*)d_in[5];
    p.rot = (const float*)d_in[6];
    p.dx  = (const float*)d_in[7];
    for (int h = 0; h < 5; h++) {
        p.w1[h] = (const float*)d_in[8 + h * 4 + 0];
        p.b1[h] = (const float*)d_in[8 + h * 4 + 1];
        p.w2[h] = (const float*)d_in[8 + h * 4 + 2];
        p.b2[h] = (const float*)d_in[8 + h * 4 + 3];
    }
    p.out = (float*)d_out;
    p.n   = in_sizes[0];   // 200000

    const int smem_bytes = SMEM_FLOATS * (int)sizeof(float);
    cudaFuncSetAttribute(deform_kernel,
                         cudaFuncAttributeMaxDynamicSharedMemorySize, smem_bytes);
    const int grid = (p.n + 63) / 64;   // 3125, exact
    deform_kernel<<<grid, 256, smem_bytes>>>(p);
}

// round 2
// speedup vs baseline: 1.0546x; 1.0546x over previous
#include <cuda_runtime.h>

// ---------------------------------------------------------------------------
// Deformation network, fused single kernel.
//   hidden[255] = concat(point3, rot4, scl3, opa1, shs48, sem128, dx3, t1, tpe64)
//   per head: h = relu(hidden); h1 = relu(h @ W1 + b1); out = h1 @ W2 + b2
//   mask = sigmoid(head_mask); outputs combined with mask.
// One CTA per 64 points (200000 = 64 * 3125). 256 threads.
// GEMM1 register-tiled 8x8 per thread, packed fma.rn.f32x2 (2 FLOP/instr).
// ---------------------------------------------------------------------------

#define DEVI __device__ __forceinline__

DEVI unsigned long long pack2(float x, float y) {
    unsigned long long r;
    asm("mov.b64 %0, {%1, %2};" : "=l"(r) : "f"(x), "f"(y));
    return r;
}
DEVI void unpack2(unsigned long long v, float& x, float& y) {
    asm("mov.b64 {%0, %1}, %2;" : "=f"(x), "=f"(y) : "l"(v));
}
DEVI void fma2(unsigned long long& c, unsigned long long a, unsigned long long b) {
    asm("fma.rn.f32x2 %0, %1, %2, %0;" : "+l"(c) : "l"(a), "l"(b));
}

struct Params {
    const float* opa;   // [N,1]
    const float* shs;   // [N,48]
    const float* tim;   // [N,1]
    const float* sem;   // [N,128]
    const float* pnt;   // [N,3]
    const float* scl;   // [N,3]
    const float* rot;   // [N,4]
    const float* dx;    // [N,3]
    const float* w1[5]; // [255,255] each (mask,pos,scl,rot,shs)
    const float* b1[5]; // [255]
    const float* w2[5]; // [255,od]
    const float* b2[5]; // [od]
    float* out;
    int n;
};

// smem layout (floats)
//  As   [255][64]   relu(hidden)^T                    16320
//  H1   [64][257]   layer-1 activations (padded)      16448
//  Ws   [16][256]   W1 k-tile                          4096
//  W2s  [255*48]    full W2 for current head          12240
//  maskS[64], tpeS[64]
#define OFF_AS    0
#define OFF_H1    16320
#define OFF_WS    (16320 + 16448)
#define OFF_W2S   (16320 + 16448 + 4096)
#define OFF_MASK  (16320 + 16448 + 4096 + 12240)
#define OFF_TPE   (16320 + 16448 + 4096 + 12240 + 64)
#define SMEM_FLOATS (16320 + 16448 + 4096 + 12240 + 64 + 64)

__global__ __launch_bounds__(256, 1)
void deform_kernel(Params p) {
    extern __shared__ float sm[];
    float* As    = sm + OFF_AS;
    float* H1    = sm + OFF_H1;
    float* Ws    = sm + OFF_WS;
    float* W2s   = sm + OFF_W2S;
    float* maskS = sm + OFF_MASK;
    float* tpeS  = sm + OFF_TPE;

    const int tid = threadIdx.x;
    const int g0  = blockIdx.x * 64;
    const int n   = p.n;

    const int pN   = 0;
    const int oPTS = 0;
    const int oSCL = 3 * n;
    const int oROT = 6 * n;
    const int oOP  = 10 * n;
    const int oSHS = 11 * n;
    const int oDX  = 59 * n;
    const int oDSH = 62 * n;
    (void)pN;

    // --- time positional encoding (constant across rows) ---
    if (tid < 32) {
        float t    = p.tim[0];
        float fi   = (float)(2 * tid);
        // freq = 10000^(i/32) = 2^(i * log2(10000)/32)
        float freq = exp2f(fi * (13.287712379549449f / 32.0f));
        float a    = t / freq;
        tpeS[2 * tid]     = sinf(a);
        tpeS[2 * tid + 1] = cosf(a);
    }
    __syncthreads();

    // --- build As[k][m] = relu(hidden[m][k]) ---
    for (int idx = tid; idx < 255 * 64; idx += 256) {
        int m = idx & 63;
        int k = idx >> 6;
        int g = g0 + m;
        float v;
        if      (k < 3)    v = p.pnt[g * 3 + k];
        else if (k < 7)    v = p.rot[g * 4 + (k - 3)];
        else if (k < 10)   v = p.scl[g * 3 + (k - 7)];
        else if (k == 10)  v = p.opa[g];
        else if (k < 59)   v = p.shs[g * 48 + (k - 11)];
        else if (k < 187)  v = p.sem[g * 128 + (k - 59)];
        else if (k < 190)  v = p.dx[g * 3 + (k - 187)];
        else if (k == 190) v = p.tim[g];
        else               v = tpeS[k - 191];
        As[k * 64 + m] = fmaxf(v, 0.0f);
    }

    // opacity pass-through output
    if (tid < 64) p.out[oOP + g0 + tid] = p.opa[g0 + tid];

    __syncthreads();

    const int tn = tid & 31;   // 0..31 -> columns tn*4 and 128+tn*4
    const int tm = tid >> 5;   // 0..7  -> rows tm*8 .. tm*8+7
    const int ODS[5] = {1, 3, 3, 4, 48};

    #pragma unroll 1
    for (int h = 0; h < 5; h++) {
        const float* w1 = p.w1[h];
        const float* b1 = p.b1[h];
        const int od = ODS[h];

        // kick off W2 copy for this head (W2s is free: previous gemm2 synced).
        // LDG latency hides under GEMM1 below.
        for (int idx = tid; idx < 255 * od; idx += 256)
            W2s[idx] = p.w2[h][idx];

        // ---------- GEMM1: C[64,255] = As^T @ W1 ----------
        unsigned long long acc[8][4];
        #pragma unroll
        for (int i = 0; i < 8; i++)
            #pragma unroll
            for (int j = 0; j < 4; j++) acc[i][j] = 0ull;

        // prefetch k-tile 0 into registers
        float pre[16];
        {
            const int cnt = 16 * 255;
            #pragma unroll
            for (int u = 0; u < 16; u++) {
                int idx = tid + u * 256;
                pre[u] = (idx < cnt) ? w1[idx] : 0.0f;
            }
        }

        #pragma unroll 1
        for (int kt = 0; kt < 16; kt++) {
            const int ksz = (kt == 15) ? 15 : 16;
            __syncthreads();   // Ws free (previous inner loop done)
            {
                const int cnt = ksz * 255;
                #pragma unroll
                for (int u = 0; u < 16; u++) {
                    int idx = tid + u * 256;
                    if (idx < cnt) {
                        int r = idx / 255;
                        int c = idx - r * 255;
                        Ws[r * 256 + c] = pre[u];
                    }
                }
            }
            if (kt < 15) {   // prefetch next tile
                const int nksz = (kt == 14) ? 15 : 16;
                const int base = (kt + 1) * 16 * 255;
                const int cnt  = nksz * 255;
                #pragma unroll
                for (int u = 0; u < 16; u++) {
                    int idx = tid + u * 256;
                    pre[u] = (idx < cnt) ? w1[base + idx] : 0.0f;
                }
            }
            __syncthreads();

            const float* ap = As + kt * 16 * 64 + tm * 8;
            const float* bp = Ws + tn * 4;
            #pragma unroll 4
            for (int kk = 0; kk < ksz; kk++) {
                float4 av0 = *(const float4*)(ap + kk * 64);
                float4 av1 = *(const float4*)(ap + kk * 64 + 4);
                float4 bv0 = *(const float4*)(bp + kk * 256);
                float4 bv1 = *(const float4*)(bp + kk * 256 + 128);
                unsigned long long b00 = pack2(bv0.x, bv0.y);
                unsigned long long b01 = pack2(bv0.z, bv0.w);
                unsigned long long b10 = pack2(bv1.x, bv1.y);
                unsigned long long b11 = pack2(bv1.z, bv1.w);
                float a_[8] = {av0.x, av0.y, av0.z, av0.w,
                               av1.x, av1.y, av1.z, av1.w};
                #pragma unroll
                for (int i = 0; i < 8; i++) {
                    unsigned long long a2 = pack2(a_[i], a_[i]);
                    fma2(acc[i][0], a2, b00);
                    fma2(acc[i][1], a2, b01);
                    fma2(acc[i][2], a2, b10);
                    fma2(acc[i][3], a2, b11);
                }
            }
        }

        // ---------- H1 = relu(C + b1)  (scalar stores, stride 257) ----------
        #pragma unroll
        for (int grp = 0; grp < 2; grp++) {
            const int c0 = grp * 128 + tn * 4;
            float bb[4];
            #pragma unroll
            for (int jj = 0; jj < 4; jj++)
                bb[jj] = (c0 + jj < 255) ? b1[c0 + jj] : 0.0f;
            #pragma unroll
            for (int i = 0; i < 8; i++) {
                const int r = tm * 8 + i;
                float x, y, z, w;
                unpack2(acc[i][grp * 2 + 0], x, y);
                unpack2(acc[i][grp * 2 + 1], z, w);
                H1[r * 257 + c0 + 0] = fmaxf(x + bb[0], 0.0f);
                H1[r * 257 + c0 + 1] = fmaxf(y + bb[1], 0.0f);
                H1[r * 257 + c0 + 2] = fmaxf(z + bb[2], 0.0f);
                H1[r * 257 + c0 + 3] = fmaxf(w + bb[3], 0.0f);
            }
        }
        __syncthreads();   // H1 and W2s ready

        // ---------- GEMM2 + epilogue ----------
        if (h == 0) {
            // mask head: od = 1, sigmoid -> maskS
            if (tid < 64) {
                const int m = tid;
                const float* hp = H1 + m * 257;
                float s = 0.0f;
                #pragma unroll 5
                for (int k = 0; k < 255; k++) s += hp[k] * W2s[k];
                s += p.b2[0][0];
                maskS[m] = 1.0f / (1.0f + expf(-s));
            }
        } else if (od <= 4) {
            if (tid < 64 * od) {
                const int m = tid & 63;
                const int o = tid >> 6;
                const float* hp = H1 + m * 257;
                const float* wp = W2s + o;
                float s = 0.0f;
                #pragma unroll 5
                for (int k = 0; k < 255; k++) s += hp[k] * wp[k * od];
                s += p.b2[h][o];
                const int g = g0 + m;
                const float mk = maskS[m];
                if (h == 1) {          // pos: dx_out and pts
                    p.out[oDX  + g * 3 + o] = s;
                    p.out[oPTS + g * 3 + o] = p.pnt[g * 3 + o] + s * mk;
                } else if (h == 2) {   // scales
                    p.out[oSCL + g * 3 + o] = p.scl[g * 3 + o] + s * mk;
                } else {               // rotations
                    p.out[oROT + g * 4 + o] = p.rot[g * 4 + o] + s * mk;
                }
            }
        } else {
            // shs head: od = 48. thread -> (m = tid/4, og = tid%4), 12 outputs.
            const int m  = tid >> 2;
            const int og = tid & 3;
            float s[12];
            #pragma unroll
            for (int j = 0; j < 12; j++) s[j] = 0.0f;
            const float* hp = H1 + m * 257;
            const float4* wp = (const float4*)W2s + og * 3;
            #pragma unroll 3
            for (int k = 0; k < 255; k++) {
                const float hv = hp[k];
                #pragma unroll
                for (int jj = 0; jj < 3; jj++) {
                    float4 wv = wp[k * 12 + jj];
                    s[4 * jj + 0] += hv * wv.x;
                    s[4 * jj + 1] += hv * wv.y;
                    s[4 * jj + 2] += hv * wv.z;
                    s[4 * jj + 3] += hv * wv.w;
                }
            }
            const int g = g0 + m;
            const float mk = maskS[m];
            #pragma unroll
            for (int jj = 0; jj < 3; jj++) {
                #pragma unroll
                for (int e = 0; e < 4; e++) {
                    const int o = og * 12 + 4 * jj + e;
                    const float v = s[4 * jj + e] + p.b2[4][o];
                    p.out[oDSH + g * 48 + o] = v;
                    p.out[oSHS + g * 48 + o] = p.shs[g * 48 + o] + v * mk;
                }
            }
        }
        __syncthreads();   // gemm2 done: W2s/H1 free, maskS visible
    }
}

extern "C" void kernel_launch(void* const* d_in, const int* in_sizes, int n_in,
                              void* d_out, int out_size) {
    Params p;
    p.opa = (const float*)d_in[0];
    p.shs = (const float*)d_in[1];
    p.tim = (const float*)d_in[2];
    p.sem = (const float*)d_in[3];
    p.pnt = (const float*)d_in[4];
    p.scl = (const float*)d_in[5];
    p.rot = (const float*)d_in[6];
    p.dx  = (const float*)d_in[7];
    for (int h = 0; h < 5; h++) {
        p.w1[h] = (const float*)d_in[8 + h * 4 + 0];
        p.b1[h] = (const float*)d_in[8 + h * 4 + 1];
        p.w2[h] = (const float*)d_in[8 + h * 4 + 2];
        p.b2[h] = (const float*)d_in[8 + h * 4 + 3];
    }
    p.out = (float*)d_out;
    p.n   = in_sizes[0];   // 200000

    const int smem_bytes = SMEM_FLOATS * (int)sizeof(float);
    cudaFuncSetAttribute(deform_kernel,
                         cudaFuncAttributeMaxDynamicSharedMemorySize, smem_bytes);
    const int grid = (p.n + 63) / 64;   // 3125, exact
    deform_kernel<<<grid, 256, smem_bytes>>>(p);
}

// round 4
// speedup vs baseline: 1.3688x; 1.2979x over previous
#include <cuda_runtime.h>
#include <cuda_bf16.h>
#include <cstdint>

// ============================================================================
// Deformation net: GEMM1 on HMMA (mma.sync m16n8k16 bf16, bf16x3 split, fp32
// accum). CTA = 64 points, 256 threads (8 warps). A fragments packed in smem,
// W1 pre-packed to per-thread B-fragment images in global by prep kernel,
// streamed with cp.async double buffering. GEMM2 SIMT fp32 from smem H1.
// ============================================================================

#define DEVI __device__ __forceinline__

// ---- pre-packed W1 fragments: [head][ks 0..15][16KB tile] ------------------
// tile internal layout: [split 0/1][nt 0..31][lane 0..31][2 x u32]
__device__ __align__(16) unsigned char g_w1pk[5][16][16384];

__global__ void prep_kernel(const float* w0, const float* w1, const float* w2,
                            const float* w3, const float* w4) {
    const float* ws[5] = {w0, w1, w2, w3, w4};
    int idx = blockIdx.x * blockDim.x + threadIdx.x;   // 5*16*32*32 = 81920
    if (idx >= 81920) return;
    int lane = idx & 31;
    int nt   = (idx >> 5) & 31;
    int ks   = (idx >> 10) & 15;
    int h    = idx >> 14;
    int nn = nt * 8 + (lane >> 2);        // 0..255
    int c  = (lane & 3) * 2;
    int k0 = ks * 16 + c;
    const float* w = ws[h];
    float v[4];
    int kk[4] = {k0, k0 + 1, k0 + 8, k0 + 9};
#pragma unroll
    for (int j = 0; j < 4; j++)
        v[j] = (kk[j] < 255 && nn < 255) ? w[kk[j] * 255 + nn] : 0.0f;
    uint32_t hi[2], lo[2];
#pragma unroll
    for (int r = 0; r < 2; r++) {
        __nv_bfloat16 h0 = __float2bfloat16(v[2 * r]);
        __nv_bfloat16 h1 = __float2bfloat16(v[2 * r + 1]);
        __nv_bfloat16 l0 = __float2bfloat16(v[2 * r] - __bfloat162float(h0));
        __nv_bfloat16 l1 = __float2bfloat16(v[2 * r + 1] - __bfloat162float(h1));
        hi[r] = ((uint32_t)__bfloat16_as_ushort(h1) << 16) | __bfloat16_as_ushort(h0);
        lo[r] = ((uint32_t)__bfloat16_as_ushort(l1) << 16) | __bfloat16_as_ushort(l0);
    }
    unsigned char* base = &g_w1pk[h][ks][0];
    *(uint2*)(base + (((0 * 32 + nt) * 32) + lane) * 8) = make_uint2(hi[0], hi[1]);
    *(uint2*)(base + (((1 * 32 + nt) * 32) + lane) * 8) = make_uint2(lo[0], lo[1]);
}

// ---- helpers ----------------------------------------------------------------
DEVI uint32_t smem_u32(const void* p) {
    uint32_t a;
    asm("{ .reg .u64 t; cvta.to.shared.u64 t, %1; cvt.u32.u64 %0, t; }"
        : "=r"(a) : "l"(p));
    return a;
}
DEVI void cpa16(uint32_t sdst, const void* gsrc) {
    asm volatile("cp.async.cg.shared.global [%0], [%1], 16;" :: "r"(sdst), "l"(gsrc));
}
DEVI void cpa_commit() { asm volatile("cp.async.commit_group;" ::: "memory"); }
DEVI void cpa_wait0()  { asm volatile("cp.async.wait_group 0;"  ::: "memory"); }

DEVI void mma16816(float* d, const uint32_t* a, const uint32_t b0, const uint32_t b1) {
    asm volatile(
        "mma.sync.aligned.m16n8k16.row.col.f32.bf16.bf16.f32 "
        "{%0,%1,%2,%3}, {%4,%5,%6,%7}, {%8,%9}, {%0,%1,%2,%3};"
        : "+f"(d[0]), "+f"(d[1]), "+f"(d[2]), "+f"(d[3])
        : "r"(a[0]), "r"(a[1]), "r"(a[2]), "r"(a[3]), "r"(b0), "r"(b1));
}

struct Params {
    const float* opa; const float* shs; const float* tim; const float* sem;
    const float* pnt; const float* scl; const float* rot; const float* dx;
    const float* w1[5]; const float* b1[5]; const float* w2[5]; const float* b2[5];
    float* out; int n;
};

// ---- smem layout (bytes) ------------------------------------------------------
#define OFF_APK  0           // 16ks x 2split x 4mt x 32lane x 16B = 65536
#define OFF_BT   65536       // 2 x 16384 double-buffered W1 k-tile
#define OFF_H1   98304       // 64 x 257 f32 = 65792 (also raw-A scratch)
#define OFF_W2S  164096      // up to 255*48 f32 = 48960 -> pad 49152
#define OFF_MASK 213248      // 64 f32
#define OFF_TPE  213504      // 64 f32
#define SMEM_BYTES 213760

__global__ __launch_bounds__(256, 1)
void deform_mma(Params p) {
    extern __shared__ __align__(16) unsigned char sm[];
    const uint32_t smb = smem_u32(sm);
    float* H1S   = (float*)(sm + OFF_H1);
    float* W2s   = (float*)(sm + OFF_W2S);
    float* maskS = (float*)(sm + OFF_MASK);
    float* tpeS  = (float*)(sm + OFF_TPE);

    const int tid = threadIdx.x, w = tid >> 5, lane = tid & 31;
    const int n = p.n, g0 = blockIdx.x * 64;
    const int oPTS = 0, oSCL = 3 * n, oROT = 6 * n, oOP = 10 * n,
              oSHS = 11 * n, oDX = 59 * n, oDSH = 62 * n;

    // prefetch head0 tile0
#pragma unroll
    for (int i = 0; i < 4; i++)
        cpa16(smb + OFF_BT + tid * 16 + i * 4096, &g_w1pk[0][0][0] + tid * 16 + i * 4096);
    cpa_commit();

    // time positional encoding
    if (tid < 32) {
        float t = p.tim[0];
        float freq = exp2f((float)(2 * tid) * (13.287712379549449f / 32.0f));
        float a = t / freq;
        tpeS[2 * tid] = sinf(a);
        tpeS[2 * tid + 1] = cosf(a);
    }
    __syncthreads();

    // ---- raw A = relu(hidden) into H1S scratch [64][257] ----
    for (int idx = tid; idx < 64 * 256; idx += 256) {
        int m = idx >> 8, k = idx & 255;
        int g = g0 + m;
        float v = 0.0f;
        if (g < n && k < 255) {
            if      (k < 3)    v = p.pnt[g * 3 + k];
            else if (k < 7)    v = p.rot[g * 4 + (k - 3)];
            else if (k < 10)   v = p.scl[g * 3 + (k - 7)];
            else if (k == 10)  v = p.opa[g];
            else if (k < 59)   v = p.shs[g * 48 + (k - 11)];
            else if (k < 187)  v = p.sem[g * 128 + (k - 59)];
            else if (k < 190)  v = p.dx[g * 3 + (k - 187)];
            else if (k == 190) v = p.tim[g];
            else               v = tpeS[k - 191];
        }
        H1S[m * 257 + k] = fmaxf(v, 0.0f);
    }
    if (tid < 64) { int g = g0 + tid; if (g < n) p.out[oOP + g] = p.opa[g]; }
    __syncthreads();

    // ---- pack A fragments (hi/lo) into Apk ----
    {
        const int gq = lane >> 2, c = (lane & 3) * 2;
#pragma unroll 1
        for (int j = 0; j < 8; j++) {
            int f  = w * 8 + j;          // 0..63
            int ks = f >> 2, mt = f & 3;
            int r0 = mt * 16 + gq, r1 = r0 + 8;
            int k0 = ks * 16 + c;
            float a00 = H1S[r0 * 257 + k0],     a01 = H1S[r0 * 257 + k0 + 1];
            float a10 = H1S[r1 * 257 + k0],     a11 = H1S[r1 * 257 + k0 + 1];
            float a02 = H1S[r0 * 257 + k0 + 8], a03 = H1S[r0 * 257 + k0 + 9];
            float a12 = H1S[r1 * 257 + k0 + 8], a13 = H1S[r1 * 257 + k0 + 9];
            uint4 hi, lo;
            {
                __nv_bfloat16 h0, h1;
                float e0, e1;
                h0 = __float2bfloat16(a00); h1 = __float2bfloat16(a01);
                e0 = a00 - __bfloat162float(h0); e1 = a01 - __bfloat162float(h1);
                hi.x = ((uint32_t)__bfloat16_as_ushort(h1) << 16) | __bfloat16_as_ushort(h0);
                lo.x = ((uint32_t)__bfloat16_as_ushort(__float2bfloat16(e1)) << 16) |
                       __bfloat16_as_ushort(__float2bfloat16(e0));
                h0 = __float2bfloat16(a10); h1 = __float2bfloat16(a11);
                e0 = a10 - __bfloat162float(h0); e1 = a11 - __bfloat162float(h1);
                hi.y = ((uint32_t)__bfloat16_as_ushort(h1) << 16) | __bfloat16_as_ushort(h0);
                lo.y = ((uint32_t)__bfloat16_as_ushort(__float2bfloat16(e1)) << 16) |
                       __bfloat16_as_ushort(__float2bfloat16(e0));
                h0 = __float2bfloat16(a02); h1 = __float2bfloat16(a03);
                e0 = a02 - __bfloat162float(h0); e1 = a03 - __bfloat162float(h1);
                hi.z = ((uint32_t)__bfloat16_as_ushort(h1) << 16) | __bfloat16_as_ushort(h0);
                lo.z = ((uint32_t)__bfloat16_as_ushort(__float2bfloat16(e1)) << 16) |
                       __bfloat16_as_ushort(__float2bfloat16(e0));
                h0 = __float2bfloat16(a12); h1 = __float2bfloat16(a13);
                e0 = a12 - __bfloat162float(h0); e1 = a13 - __bfloat162float(h1);
                hi.w = ((uint32_t)__bfloat16_as_ushort(h1) << 16) | __bfloat16_as_ushort(h0);
                lo.w = ((uint32_t)__bfloat16_as_ushort(__float2bfloat16(e1)) << 16) |
                       __bfloat16_as_ushort(__float2bfloat16(e0));
            }
            *(uint4*)(sm + OFF_APK + (((ks * 2 + 0) * 4 + mt) * 32 + lane) * 16) = hi;
            *(uint4*)(sm + OFF_APK + (((ks * 2 + 1) * 4 + mt) * 32 + lane) * 16) = lo;
        }
    }
    __syncthreads();

    const int ODS[5] = {1, 3, 3, 4, 48};

#pragma unroll 1
    for (int h = 0; h < 5; h++) {
        const int od = ODS[h];
        // bias regs for this warp's n-slice
        float b1r[8];
#pragma unroll
        for (int nt = 0; nt < 4; nt++)
#pragma unroll
            for (int e = 0; e < 2; e++) {
                int nn = (w * 4 + nt) * 8 + (lane & 3) * 2 + e;
                b1r[nt * 2 + e] = (nn < 255) ? p.b1[h][nn] : 0.0f;
            }

        float acc[4][4][4];
#pragma unroll
        for (int a = 0; a < 4; a++)
#pragma unroll
            for (int b = 0; b < 4; b++)
#pragma unroll
                for (int e = 0; e < 4; e++) acc[a][b][e] = 0.0f;

        cpa_wait0();            // tile (h,0) arrived
        __syncthreads();

        // preload B frags for ks=0
        uint32_t curB[2][4][2];
#pragma unroll
        for (int s = 0; s < 2; s++)
#pragma unroll
            for (int nt = 0; nt < 4; nt++) {
                uint2 v = *(uint2*)(sm + OFF_BT +
                    (((s * 32 + (w * 4 + nt)) * 32) + lane) * 8);
                curB[s][nt][0] = v.x; curB[s][nt][1] = v.y;
            }

#pragma unroll 1
        for (int ks = 0; ks < 16; ks++) {
            const int nbuf = (ks + 1) & 1;
            if (ks < 15) {
                const unsigned char* src = &g_w1pk[h][ks + 1][0];
#pragma unroll
                for (int i = 0; i < 4; i++)
                    cpa16(smb + OFF_BT + nbuf * 16384 + tid * 16 + i * 4096,
                          src + tid * 16 + i * 4096);
                cpa_commit();
            }
            // MMA on current regs + A from smem
#pragma unroll
            for (int mt = 0; mt < 4; mt++) {
                uint4 ahi = *(uint4*)(sm + OFF_APK + (((ks * 2 + 0) * 4 + mt) * 32 + lane) * 16);
                uint4 alo = *(uint4*)(sm + OFF_APK + (((ks * 2 + 1) * 4 + mt) * 32 + lane) * 16);
                uint32_t ah[4] = {ahi.x, ahi.y, ahi.z, ahi.w};
                uint32_t al[4] = {alo.x, alo.y, alo.z, alo.w};
#pragma unroll
                for (int nt = 0; nt < 4; nt++) {
                    mma16816(acc[mt][nt], ah, curB[0][nt][0], curB[0][nt][1]);
                    mma16816(acc[mt][nt], ah, curB[1][nt][0], curB[1][nt][1]);
                    mma16816(acc[mt][nt], al, curB[0][nt][0], curB[0][nt][1]);
                }
            }
            if (ks < 15) {
                cpa_wait0();
                __syncthreads();
#pragma unroll
                for (int s = 0; s < 2; s++)
#pragma unroll
                    for (int nt = 0; nt < 4; nt++) {
                        uint2 v = *(uint2*)(sm + OFF_BT + nbuf * 16384 +
                            (((s * 32 + (w * 4 + nt)) * 32) + lane) * 8);
                        curB[s][nt][0] = v.x; curB[s][nt][1] = v.y;
                    }
            }
        }
        __syncthreads();   // all mma reads of H1S-scratch / buffers done

        // prefetch next head's tile0 (overlaps epilogue + GEMM2)
        if (h < 4) {
            const unsigned char* src = &g_w1pk[h + 1][0][0];
#pragma unroll
            for (int i = 0; i < 4; i++)
                cpa16(smb + OFF_BT + tid * 16 + i * 4096, src + tid * 16 + i * 4096);
            cpa_commit();
        }

        // ---- H1 = relu(acc + b1) -> H1S ----
#pragma unroll
        for (int mt = 0; mt < 4; mt++)
#pragma unroll
            for (int nt = 0; nt < 4; nt++)
#pragma unroll
                for (int e = 0; e < 4; e++) {
                    int m  = mt * 16 + (lane >> 2) + ((e >> 1) << 3);
                    int nn = (w * 4 + nt) * 8 + (lane & 3) * 2 + (e & 1);
                    H1S[m * 257 + nn] = fmaxf(acc[mt][nt][e] + b1r[nt * 2 + (e & 1)], 0.0f);
                }

        // stage W2 fp32
        for (int i = tid; i < 255 * od; i += 256) W2s[i] = p.w2[h][i];
        __syncthreads();

        // ---- GEMM2 (SIMT fp32) + output epilogue ----
        if (h == 0) {
            if (tid < 64) {
                const float* hp = H1S + tid * 257;
                float s = 0.0f;
#pragma unroll 5
                for (int k = 0; k < 255; k++) s += hp[k] * W2s[k];
                s += p.b2[0][0];
                maskS[tid] = 1.0f / (1.0f + expf(-s));
            }
        } else if (od <= 4) {
            if (tid < 64 * od) {
                const int m = tid & 63, o = tid >> 6;
                const float* hp = H1S + m * 257;
                float s = 0.0f;
#pragma unroll 5
                for (int k = 0; k < 255; k++) s += hp[k] * W2s[k * od + o];
                s += p.b2[h][o];
                const int g = g0 + m;
                if (g < n) {
                    const float mk = maskS[m];
                    if (h == 1) {
                        p.out[oDX + g * 3 + o]  = s;
                        p.out[oPTS + g * 3 + o] = p.pnt[g * 3 + o] + s * mk;
                    } else if (h == 2) {
                        p.out[oSCL + g * 3 + o] = p.scl[g * 3 + o] + s * mk;
                    } else {
                        p.out[oROT + g * 4 + o] = p.rot[g * 4 + o] + s * mk;
                    }
                }
            }
        } else {
            const int m = tid >> 2, og = tid & 3;
            float s[12];
#pragma unroll
            for (int j = 0; j < 12; j++) s[j] = 0.0f;
            const float* hp = H1S + m * 257;
            const float4* wp = (const float4*)W2s + og * 3;
#pragma unroll 3
            for (int k = 0; k < 255; k++) {
                const float hv = hp[k];
#pragma unroll
                for (int jj = 0; jj < 3; jj++) {
                    float4 wv = wp[k * 12 + jj];
                    s[4 * jj + 0] += hv * wv.x;
                    s[4 * jj + 1] += hv * wv.y;
                    s[4 * jj + 2] += hv * wv.z;
                    s[4 * jj + 3] += hv * wv.w;
                }
            }
            const int g = g0 + m;
            if (g < n) {
                const float mk = maskS[m];
#pragma unroll
                for (int jj = 0; jj < 3; jj++)
#pragma unroll
                    for (int e = 0; e < 4; e++) {
                        const int o = og * 12 + 4 * jj + e;
                        const float v = s[4 * jj + e] + p.b2[4][o];
                        p.out[oDSH + g * 48 + o] = v;
                        p.out[oSHS + g * 48 + o] = p.shs[g * 48 + o] + v * mk;
                    }
            }
        }
        __syncthreads();   // maskS visible / H1S & W2s reusable
    }
}

extern "C" void kernel_launch(void* const* d_in, const int* in_sizes, int n_in,
                              void* d_out, int out_size) {
    Params p;
    p.opa = (const float*)d_in[0];
    p.shs = (const float*)d_in[1];
    p.tim = (const float*)d_in[2];
    p.sem = (const float*)d_in[3];
    p.pnt = (const float*)d_in[4];
    p.scl = (const float*)d_in[5];
    p.rot = (const float*)d_in[6];
    p.dx  = (const float*)d_in[7];
    for (int h = 0; h < 5; h++) {
        p.w1[h] = (const float*)d_in[8 + h * 4 + 0];
        p.b1[h] = (const float*)d_in[8 + h * 4 + 1];
        p.w2[h] = (const float*)d_in[8 + h * 4 + 2];
        p.b2[h] = (const float*)d_in[8 + h * 4 + 3];
    }
    p.out = (float*)d_out;
    p.n   = in_sizes[0];

    prep_kernel<<<(81920 + 255) / 256, 256>>>(p.w1[0], p.w1[1], p.w1[2], p.w1[3], p.w1[4]);

    cudaFuncSetAttribute(deform_mma, cudaFuncAttributeMaxDynamicSharedMemorySize, SMEM_BYTES);
    const int grid = (p.n + 63) / 64;
    deform_mma<<<grid, 256, SMEM_BYTES>>>(p);
}

// round 5
// speedup vs baseline: 1.8054x; 1.3190x over previous
#include <cuda_runtime.h>
#include <cuda_bf16.h>
#include <cstdint>

// ============================================================================
// Deformation net, all-GEMM-on-HMMA (mma.sync m16n8k16 bf16, bf16x3 split,
// fp32 accum). CTA = 64 points, 256 threads (8 warps).
//  - A = relu(hidden) packed once into smem A-fragments (hi/lo).
//  - W1 pre-packed per-thread B-fragment images in global: mainloop B comes
//    via coalesced LDG.128 straight to registers. NO syncthreads in mainloop.
//  - GEMM2 also on HMMA: H1 fragments converted in-register from GEMM1
//    accumulators (C-frag == A-frag layout), exchanged once through smem.
// ============================================================================

#define DEVI __device__ __forceinline__

// W1 packed frags: [head][ks][i 0..3][tid 0..255][16B] = 5*16*4*256*16 = 1.25MB
__device__ __align__(16) unsigned char g_w1pk[5 * 16 * 4 * 256 * 16];
// W2 packed frags: [slot 0..9][ks2 0..15][lane 0..31][16B] = 80KB
//   slots: 0..3 -> heads 0..3 (nt2=0), 4..9 -> head 4 nt2 0..5
__device__ __align__(16) unsigned char g_w2pk[10 * 16 * 32 * 16];

DEVI void bsplit(float x, float y, uint32_t& hi, uint32_t& lo) {
    __nv_bfloat16 hx = __float2bfloat16(x), hy = __float2bfloat16(y);
    __nv_bfloat16 lx = __float2bfloat16(x - __bfloat162float(hx));
    __nv_bfloat16 ly = __float2bfloat16(y - __bfloat162float(hy));
    hi = ((uint32_t)__bfloat16_as_ushort(hy) << 16) | __bfloat16_as_ushort(hx);
    lo = ((uint32_t)__bfloat16_as_ushort(ly) << 16) | __bfloat16_as_ushort(lx);
}

__global__ void prep_w1(const float* w0, const float* w1, const float* w2,
                        const float* w3, const float* w4) {
    const float* ws[5] = {w0, w1, w2, w3, w4};
    int idx = blockIdx.x * blockDim.x + threadIdx.x;   // 5*16*256 = 20480
    if (idx >= 20480) return;
    int h = idx >> 12, ks = (idx >> 8) & 15, tid = idx & 255;
    int w = tid >> 5, lane = tid & 31;
    const float* W = ws[h];
    uint32_t hb[4][2], lb[4][2];
#pragma unroll
    for (int ntl = 0; ntl < 4; ntl++) {
        int nn = (w * 4 + ntl) * 8 + (lane >> 2);
        int k0 = ks * 16 + (lane & 3) * 2;
        float v[4];
        int kk[4] = {k0, k0 + 1, k0 + 8, k0 + 9};
#pragma unroll
        for (int j = 0; j < 4; j++)
            v[j] = (kk[j] < 255 && nn < 255) ? W[kk[j] * 255 + nn] : 0.0f;
        bsplit(v[0], v[1], hb[ntl][0], lb[ntl][0]);
        bsplit(v[2], v[3], hb[ntl][1], lb[ntl][1]);
    }
    uint4* base = (uint4*)(g_w1pk + (size_t)(h * 16 + ks) * 16384);
    base[0 * 256 + tid] = make_uint4(hb[0][0], hb[0][1], hb[1][0], hb[1][1]);
    base[1 * 256 + tid] = make_uint4(hb[2][0], hb[2][1], hb[3][0], hb[3][1]);
    base[2 * 256 + tid] = make_uint4(lb[0][0], lb[0][1], lb[1][0], lb[1][1]);
    base[3 * 256 + tid] = make_uint4(lb[2][0], lb[2][1], lb[3][0], lb[3][1]);
}

__global__ void prep_w2(const float* w0, const float* w1, const float* w2,
                        const float* w3, const float* w4) {
    const float* ws[5] = {w0, w1, w2, w3, w4};
    const int ods[5] = {1, 3, 3, 4, 48};
    int idx = blockIdx.x * blockDim.x + threadIdx.x;   // 10*16*32 = 5120
    if (idx >= 5120) return;
    int slot = idx >> 9, ks2 = (idx >> 5) & 15, lane = idx & 31;
    int head = (slot < 4) ? slot : 4;
    int nt2  = (slot < 4) ? 0 : slot - 4;
    int od = ods[head];
    const float* W = ws[head];
    int nn = nt2 * 8 + (lane >> 2);
    int k0 = ks2 * 16 + (lane & 3) * 2;
    float v[4];
    int kk[4] = {k0, k0 + 1, k0 + 8, k0 + 9};
#pragma unroll
    for (int j = 0; j < 4; j++)
        v[j] = (kk[j] < 255 && nn < od) ? W[kk[j] * od + nn] : 0.0f;
    uint32_t h0, h1, l0, l1;
    bsplit(v[0], v[1], h0, l0);
    bsplit(v[2], v[3], h1, l1);
    ((uint4*)g_w2pk)[(slot * 16 + ks2) * 32 + lane] = make_uint4(h0, h1, l0, l1);
}

// ---- helpers ----------------------------------------------------------------
DEVI void mma16816(float* d, const uint32_t* a, uint32_t b0, uint32_t b1) {
    asm volatile(
        "mma.sync.aligned.m16n8k16.row.col.f32.bf16.bf16.f32 "
        "{%0,%1,%2,%3}, {%4,%5,%6,%7}, {%8,%9}, {%0,%1,%2,%3};"
        : "+f"(d[0]), "+f"(d[1]), "+f"(d[2]), "+f"(d[3])
        : "r"(a[0]), "r"(a[1]), "r"(a[2]), "r"(a[3]), "r"(b0), "r"(b1));
}

struct Params {
    const float* opa; const float* shs; const float* tim; const float* sem;
    const float* pnt; const float* scl; const float* rot; const float* dx;
    const float* w1[5]; const float* b1[5]; const float* w2[5]; const float* b2[5];
    float* out; int n;
};

// ---- smem layout (bytes) -----------------------------------------------------
#define OFF_APK   0          // A frags: 16ks x 2split x 4mt x 32lane x 16B = 65536
#define OFF_APK2  65536      // H1 frags (same layout) / raw staging 64x257 f32
#define OFF_MASK  (65536 + 66048)
#define OFF_TPE   (OFF_MASK + 256)
#define SMEM_BYTES (OFF_TPE + 256)

DEVI uint32_t apk_off(int ks, int s, int mt, int lane) {
    return (uint32_t)((((ks * 2 + s) * 4 + mt) * 32 + lane) * 16);
}

__global__ __launch_bounds__(256, 1)
void deform2(Params p) {
    extern __shared__ __align__(16) unsigned char sm[];
    float* H1raw = (float*)(sm + OFF_APK2);    // staging, stride 257
    float* maskS = (float*)(sm + OFF_MASK);
    float* tpeS  = (float*)(sm + OFF_TPE);

    const int tid = threadIdx.x, w = tid >> 5, lane = tid & 31;
    const int gq = lane >> 2, cc = lane & 3;
    const int n = p.n, g0 = blockIdx.x * 64;
    const int oPTS = 0, oSCL = 3 * n, oROT = 6 * n, oOP = 10 * n,
              oSHS = 11 * n, oDX = 59 * n, oDSH = 62 * n;

    if (tid < 32) {
        float t = p.tim[0];
        float freq = exp2f((float)(2 * tid) * (13.287712379549449f / 32.0f));
        float a = t / freq;
        tpeS[2 * tid] = sinf(a);
        tpeS[2 * tid + 1] = cosf(a);
    }
    __syncthreads();

    // ---- raw A = relu(hidden) staging ----
    for (int idx = tid; idx < 64 * 256; idx += 256) {
        int m = idx >> 8, k = idx & 255;
        int g = g0 + m;
        float v = 0.0f;
        if (g < n && k < 255) {
            if      (k < 3)    v = p.pnt[g * 3 + k];
            else if (k < 7)    v = p.rot[g * 4 + (k - 3)];
            else if (k < 10)   v = p.scl[g * 3 + (k - 7)];
            else if (k == 10)  v = p.opa[g];
            else if (k < 59)   v = p.shs[g * 48 + (k - 11)];
            else if (k < 187)  v = p.sem[g * 128 + (k - 59)];
            else if (k < 190)  v = p.dx[g * 3 + (k - 187)];
            else if (k == 190) v = p.tim[g];
            else               v = tpeS[k - 191];
        }
        H1raw[m * 257 + k] = fmaxf(v, 0.0f);
    }
    if (tid < 64) { int g = g0 + tid; if (g < n) p.out[oOP + g] = p.opa[g]; }
    __syncthreads();

    // ---- pack A fragments (hi/lo) into Apk ----
#pragma unroll 1
    for (int j = 0; j < 8; j++) {
        int f = w * 8 + j;                 // 0..63
        int ks = f >> 2, mt = f & 3;
        int r0 = mt * 16 + gq, r1 = r0 + 8;
        int k0 = ks * 16 + cc * 2;
        uint4 hi, lo;
        bsplit(H1raw[r0 * 257 + k0],     H1raw[r0 * 257 + k0 + 1], hi.x, lo.x);
        bsplit(H1raw[r1 * 257 + k0],     H1raw[r1 * 257 + k0 + 1], hi.y, lo.y);
        bsplit(H1raw[r0 * 257 + k0 + 8], H1raw[r0 * 257 + k0 + 9], hi.z, lo.z);
        bsplit(H1raw[r1 * 257 + k0 + 8], H1raw[r1 * 257 + k0 + 9], hi.w, lo.w);
        *(uint4*)(sm + OFF_APK + apk_off(ks, 0, mt, lane)) = hi;
        *(uint4*)(sm + OFF_APK + apk_off(ks, 1, mt, lane)) = lo;
    }
    __syncthreads();

    // prefetch B(h=0, ks=0) into regs
    uint4 cb[4];
    {
        const uint4* b = (const uint4*)g_w1pk;   // (h=0,ks=0)
#pragma unroll
        for (int i = 0; i < 4; i++) cb[i] = b[i * 256 + tid];
    }

#pragma unroll 1
    for (int h = 0; h < 5; h++) {
        // bias regs for this warp's n-slice
        float b1r[8];
#pragma unroll
        for (int nt = 0; nt < 4; nt++)
#pragma unroll
            for (int e = 0; e < 2; e++) {
                int nn = (w * 4 + nt) * 8 + cc * 2 + e;
                b1r[nt * 2 + e] = (nn < 255) ? p.b1[h][nn] : 0.0f;
            }

        float acc[4][4][4];
#pragma unroll
        for (int a = 0; a < 4; a++)
#pragma unroll
            for (int b = 0; b < 4; b++)
#pragma unroll
                for (int e = 0; e < 4; e++) acc[a][b][e] = 0.0f;

        // ---------- GEMM1: no syncs, B via LDG double-buffer ----------
#pragma unroll 1
        for (int ks = 0; ks < 16; ks++) {
            uint4 nb[4];
            if (ks < 15) {
                const uint4* b = (const uint4*)(g_w1pk + (size_t)(h * 16 + ks + 1) * 16384);
#pragma unroll
                for (int i = 0; i < 4; i++) nb[i] = b[i * 256 + tid];
            }
#pragma unroll
            for (int mt = 0; mt < 4; mt++) {
                uint4 ahi = *(const uint4*)(sm + OFF_APK + apk_off(ks, 0, mt, lane));
                uint4 alo = *(const uint4*)(sm + OFF_APK + apk_off(ks, 1, mt, lane));
                uint32_t ah[4] = {ahi.x, ahi.y, ahi.z, ahi.w};
                uint32_t al[4] = {alo.x, alo.y, alo.z, alo.w};
                // nt0: hi pair (cb[0].x,.y), lo pair (cb[2].x,.y)
                mma16816(acc[mt][0], ah, cb[0].x, cb[0].y);
                mma16816(acc[mt][0], ah, cb[2].x, cb[2].y);
                mma16816(acc[mt][0], al, cb[0].x, cb[0].y);
                mma16816(acc[mt][1], ah, cb[0].z, cb[0].w);
                mma16816(acc[mt][1], ah, cb[2].z, cb[2].w);
                mma16816(acc[mt][1], al, cb[0].z, cb[0].w);
                mma16816(acc[mt][2], ah, cb[1].x, cb[1].y);
                mma16816(acc[mt][2], ah, cb[3].x, cb[3].y);
                mma16816(acc[mt][2], al, cb[1].x, cb[1].y);
                mma16816(acc[mt][3], ah, cb[1].z, cb[1].w);
                mma16816(acc[mt][3], ah, cb[3].z, cb[3].w);
                mma16816(acc[mt][3], al, cb[1].z, cb[1].w);
            }
            if (ks < 15) {
#pragma unroll
                for (int i = 0; i < 4; i++) cb[i] = nb[i];
            }
        }
        // prefetch next head's B(ks=0) — latency covered by pack + GEMM2
        if (h < 4) {
            const uint4* b = (const uint4*)(g_w1pk + (size_t)((h + 1) * 16) * 16384);
#pragma unroll
            for (int i = 0; i < 4; i++) cb[i] = b[i * 256 + tid];
        }

        // ---------- pack H1 frags (bias+relu+split) into Apk2 ----------
        __syncthreads();   // previous GEMM2 done reading Apk2
#pragma unroll
        for (int mt = 0; mt < 4; mt++)
#pragma unroll
            for (int q = 0; q < 2; q++) {
                const int ks2 = 2 * w + q;
                float v00 = fmaxf(acc[mt][2 * q][0] + b1r[4 * q + 0], 0.0f);
                float v01 = fmaxf(acc[mt][2 * q][1] + b1r[4 * q + 1], 0.0f);
                float v10 = fmaxf(acc[mt][2 * q][2] + b1r[4 * q + 0], 0.0f);
                float v11 = fmaxf(acc[mt][2 * q][3] + b1r[4 * q + 1], 0.0f);
                float v20 = fmaxf(acc[mt][2 * q + 1][0] + b1r[4 * q + 2], 0.0f);
                float v21 = fmaxf(acc[mt][2 * q + 1][1] + b1r[4 * q + 3], 0.0f);
                float v30 = fmaxf(acc[mt][2 * q + 1][2] + b1r[4 * q + 2], 0.0f);
                float v31 = fmaxf(acc[mt][2 * q + 1][3] + b1r[4 * q + 3], 0.0f);
                uint4 hi, lo;
                bsplit(v00, v01, hi.x, lo.x);
                bsplit(v10, v11, hi.y, lo.y);
                bsplit(v20, v21, hi.z, lo.z);
                bsplit(v30, v31, hi.w, lo.w);
                *(uint4*)(sm + OFF_APK2 + apk_off(ks2, 0, mt, lane)) = hi;
                *(uint4*)(sm + OFF_APK2 + apk_off(ks2, 1, mt, lane)) = lo;
            }
        __syncthreads();

        // ---------- GEMM2 on HMMA + epilogue ----------
        const int ntc   = (h == 4) ? 6 : 1;
        const int slotb = (h == 4) ? 4 : h;
        const int njob  = (h == 4) ? 3 : 1;
        const int od    = (h == 4) ? 48 : ((h == 3) ? 4 : ((h == 0) ? 1 : 3));
#pragma unroll 1
        for (int jb = 0; jb < njob; jb++) {
            int t = w + 8 * jb;
            if (t >= 4 * ntc) continue;
            int mt = t / ntc, nt2 = t % ntc;
            float d[4] = {0.0f, 0.0f, 0.0f, 0.0f};
            const uint4* wb = (const uint4*)g_w2pk + (slotb + nt2) * 16 * 32;
            uint4 B = wb[lane];
#pragma unroll 1
            for (int ks2 = 0; ks2 < 16; ks2++) {
                uint4 Bn;
                if (ks2 < 15) Bn = wb[(ks2 + 1) * 32 + lane];
                uint4 ahi = *(const uint4*)(sm + OFF_APK2 + apk_off(ks2, 0, mt, lane));
                uint4 alo = *(const uint4*)(sm + OFF_APK2 + apk_off(ks2, 1, mt, lane));
                uint32_t ah[4] = {ahi.x, ahi.y, ahi.z, ahi.w};
                uint32_t al[4] = {alo.x, alo.y, alo.z, alo.w};
                mma16816(d, ah, B.x, B.y);   // Ahi*Bhi
                mma16816(d, ah, B.z, B.w);   // Ahi*Blo
                mma16816(d, al, B.x, B.y);   // Alo*Bhi
                if (ks2 < 15) B = Bn;
            }
            // epilogue from D frags
            if (h == 0) {
                if (cc == 0) {
                    float b20 = p.b2[0][0];
                    int m0 = mt * 16 + gq;
                    maskS[m0]     = 1.0f / (1.0f + expf(-(d[0] + b20)));
                    maskS[m0 + 8] = 1.0f / (1.0f + expf(-(d[2] + b20)));
                }
            } else {
#pragma unroll
                for (int e = 0; e < 4; e++) {
                    int o = nt2 * 8 + cc * 2 + (e & 1);
                    if (o < od) {
                        int m = mt * 16 + gq + ((e >> 1) << 3);
                        int g = g0 + m;
                        if (g < n) {
                            float val = d[e] + p.b2[h][o];
                            float mk = maskS[m];
                            if (h == 1) {
                                p.out[oDX + g * 3 + o]  = val;
                                p.out[oPTS + g * 3 + o] = p.pnt[g * 3 + o] + val * mk;
                            } else if (h == 2) {
                                p.out[oSCL + g * 3 + o] = p.scl[g * 3 + o] + val * mk;
                            } else if (h == 3) {
                                p.out[oROT + g * 4 + o] = p.rot[g * 4 + o] + val * mk;
                            } else {
                                p.out[oDSH + g * 48 + o] = val;
                                p.out[oSHS + g * 48 + o] = p.shs[g * 48 + o] + val * mk;
                            }
                        }
                    }
                }
            }
        }
        // NOTE: maskS written by h=0 is ordered before h>=1 reads by the two
        // __syncthreads in each head's pack phase.
    }
}

extern "C" void kernel_launch(void* const* d_in, const int* in_sizes, int n_in,
                              void* d_out, int out_size) {
    Params p;
    p.opa = (const float*)d_in[0];
    p.shs = (const float*)d_in[1];
    p.tim = (const float*)d_in[2];
    p.sem = (const float*)d_in[3];
    p.pnt = (const float*)d_in[4];
    p.scl = (const float*)d_in[5];
    p.rot = (const float*)d_in[6];
    p.dx  = (const float*)d_in[7];
    for (int h = 0; h < 5; h++) {
        p.w1[h] = (const float*)d_in[8 + h * 4 + 0];
        p.b1[h] = (const float*)d_in[8 + h * 4 + 1];
        p.w2[h] = (const float*)d_in[8 + h * 4 + 2];
        p.b2[h] = (const float*)d_in[8 + h * 4 + 3];
    }
    p.out = (float*)d_out;
    p.n   = in_sizes[0];

    prep_w1<<<80, 256>>>(p.w1[0], p.w1[1], p.w1[2], p.w1[3], p.w1[4]);
    prep_w2<<<20, 256>>>(p.w2[0], p.w2[1], p.w2[2], p.w2[3], p.w2[4]);

    cudaFuncSetAttribute(deform2, cudaFuncAttributeMaxDynamicSharedMemorySize, SMEM_BYTES);
    const int grid = (p.n + 63) / 64;
    deform2<<<grid, 256, SMEM_BYTES>>>(p);
}

// round 6
// speedup vs baseline: 1.8300x; 1.0136x over previous
#include <cuda_runtime.h>
#include <cuda_bf16.h>
#include <cstdint>

// ============================================================================
// Deformation net, all-GEMM-on-HMMA (mma.sync m16n8k16 bf16, bf16x3 split,
// fp32 accum). CTA = 64 points, 256 threads (8 warps).
//  - A = relu(hidden) packed once into smem A-fragments (hi/lo).
//  - W1 pre-packed per-thread B-fragment images in global; mainloop B via
//    coalesced LDG.128 straight to registers. No syncthreads in mainloop.
//  - MMA issue order: split-pass outermost -> 16 independent accumulators
//    between same-acc reuses (RAW latency hidden). mma asm is NON-volatile.
//  - GEMM2 on HMMA from in-register converted H1 fragments.
// ============================================================================

#define DEVI __device__ __forceinline__

// W1 packed frags: [head][ks][i 0..3][tid 0..255][16B] = 5*16*4*256*16 = 1.25MB
__device__ __align__(16) unsigned char g_w1pk[5 * 16 * 4 * 256 * 16];
// W2 packed frags: [slot 0..9][ks2 0..15][lane 0..31][16B] = 80KB
__device__ __align__(16) unsigned char g_w2pk[10 * 16 * 32 * 16];

DEVI void bsplit(float x, float y, uint32_t& hi, uint32_t& lo) {
    __nv_bfloat16 hx = __float2bfloat16(x), hy = __float2bfloat16(y);
    __nv_bfloat16 lx = __float2bfloat16(x - __bfloat162float(hx));
    __nv_bfloat16 ly = __float2bfloat16(y - __bfloat162float(hy));
    hi = ((uint32_t)__bfloat16_as_ushort(hy) << 16) | __bfloat16_as_ushort(hx);
    lo = ((uint32_t)__bfloat16_as_ushort(ly) << 16) | __bfloat16_as_ushort(lx);
}

__global__ void prep_all(const float* w10, const float* w11, const float* w12,
                         const float* w13, const float* w14,
                         const float* w20, const float* w21, const float* w22,
                         const float* w23, const float* w24) {
    int idx = blockIdx.x * blockDim.x + threadIdx.x;
    if (idx < 20480) {
        const float* ws[5] = {w10, w11, w12, w13, w14};
        int h = idx >> 12, ks = (idx >> 8) & 15, tid = idx & 255;
        int w = tid >> 5, lane = tid & 31;
        const float* W = ws[h];
        uint32_t hb[4][2], lb[4][2];
#pragma unroll
        for (int ntl = 0; ntl < 4; ntl++) {
            int nn = (w * 4 + ntl) * 8 + (lane >> 2);
            int k0 = ks * 16 + (lane & 3) * 2;
            float v[4];
            int kk[4] = {k0, k0 + 1, k0 + 8, k0 + 9};
#pragma unroll
            for (int j = 0; j < 4; j++)
                v[j] = (kk[j] < 255 && nn < 255) ? W[kk[j] * 255 + nn] : 0.0f;
            bsplit(v[0], v[1], hb[ntl][0], lb[ntl][0]);
            bsplit(v[2], v[3], hb[ntl][1], lb[ntl][1]);
        }
        uint4* base = (uint4*)(g_w1pk + (size_t)(h * 16 + ks) * 16384);
        base[0 * 256 + tid] = make_uint4(hb[0][0], hb[0][1], hb[1][0], hb[1][1]);
        base[1 * 256 + tid] = make_uint4(hb[2][0], hb[2][1], hb[3][0], hb[3][1]);
        base[2 * 256 + tid] = make_uint4(lb[0][0], lb[0][1], lb[1][0], lb[1][1]);
        base[3 * 256 + tid] = make_uint4(lb[2][0], lb[2][1], lb[3][0], lb[3][1]);
    } else if (idx < 20480 + 5120) {
        const float* ws[5] = {w20, w21, w22, w23, w24};
        const int ods[5] = {1, 3, 3, 4, 48};
        int j = idx - 20480;
        int slot = j >> 9, ks2 = (j >> 5) & 15, lane = j & 31;
        int head = (slot < 4) ? slot : 4;
        int nt2  = (slot < 4) ? 0 : slot - 4;
        int od = ods[head];
        const float* W = ws[head];
        int nn = nt2 * 8 + (lane >> 2);
        int k0 = ks2 * 16 + (lane & 3) * 2;
        float v[4];
        int kk[4] = {k0, k0 + 1, k0 + 8, k0 + 9};
#pragma unroll
        for (int q = 0; q < 4; q++)
            v[q] = (kk[q] < 255 && nn < od) ? W[kk[q] * od + nn] : 0.0f;
        uint32_t h0, h1, l0, l1;
        bsplit(v[0], v[1], h0, l0);
        bsplit(v[2], v[3], h1, l1);
        ((uint4*)g_w2pk)[(slot * 16 + ks2) * 32 + lane] = make_uint4(h0, h1, l0, l1);
    }
}

// ---- mma (non-volatile: let ptxas schedule) ---------------------------------
DEVI void mma16816(float* d, const uint32_t* a, uint32_t b0, uint32_t b1) {
    asm("mma.sync.aligned.m16n8k16.row.col.f32.bf16.bf16.f32 "
        "{%0,%1,%2,%3}, {%4,%5,%6,%7}, {%8,%9}, {%0,%1,%2,%3};"
        : "+f"(d[0]), "+f"(d[1]), "+f"(d[2]), "+f"(d[3])
        : "r"(a[0]), "r"(a[1]), "r"(a[2]), "r"(a[3]), "r"(b0), "r"(b1));
}

struct Params {
    const float* opa; const float* shs; const float* tim; const float* sem;
    const float* pnt; const float* scl; const float* rot; const float* dx;
    const float* w1[5]; const float* b1[5]; const float* w2[5]; const float* b2[5];
    float* out; int n;
};

// ---- smem layout (bytes) -----------------------------------------------------
#define OFF_APK   0          // A frags: 16ks x 2split x 4mt x 32lane x 16B = 65536
#define OFF_APK2  65536      // H1 frags (same layout) / raw staging 64x257 f32
#define OFF_MASK  (65536 + 66048)
#define OFF_TPE   (OFF_MASK + 256)
#define SMEM_BYTES (OFF_TPE + 256)

DEVI uint32_t apk_off(int ks, int s, int mt, int lane) {
    return (uint32_t)((((ks * 2 + s) * 4 + mt) * 32 + lane) * 16);
}

__global__ __launch_bounds__(256, 1)
void deform2(Params p) {
    extern __shared__ __align__(16) unsigned char sm[];
    float* H1raw = (float*)(sm + OFF_APK2);    // staging, stride 257
    float* maskS = (float*)(sm + OFF_MASK);
    float* tpeS  = (float*)(sm + OFF_TPE);

    const int tid = threadIdx.x, w = tid >> 5, lane = tid & 31;
    const int gq = lane >> 2, cc = lane & 3;
    const int n = p.n, g0 = blockIdx.x * 64;
    const int oPTS = 0, oSCL = 3 * n, oROT = 6 * n, oOP = 10 * n,
              oSHS = 11 * n, oDX = 59 * n, oDSH = 62 * n;

    if (tid < 32) {
        float t = p.tim[0];
        float freq = exp2f((float)(2 * tid) * (13.287712379549449f / 32.0f));
        float a = t / freq;
        tpeS[2 * tid] = sinf(a);
        tpeS[2 * tid + 1] = cosf(a);
    }
    __syncthreads();

    // ---- raw A = relu(hidden) staging ----
    for (int idx = tid; idx < 64 * 256; idx += 256) {
        int m = idx >> 8, k = idx & 255;
        int g = g0 + m;
        float v = 0.0f;
        if (g < n && k < 255) {
            if      (k < 3)    v = p.pnt[g * 3 + k];
            else if (k < 7)    v = p.rot[g * 4 + (k - 3)];
            else if (k < 10)   v = p.scl[g * 3 + (k - 7)];
            else if (k == 10)  v = p.opa[g];
            else if (k < 59)   v = p.shs[g * 48 + (k - 11)];
            else if (k < 187)  v = p.sem[g * 128 + (k - 59)];
            else if (k < 190)  v = p.dx[g * 3 + (k - 187)];
            else if (k == 190) v = p.tim[g];
            else               v = tpeS[k - 191];
        }
        H1raw[m * 257 + k] = fmaxf(v, 0.0f);
    }
    if (tid < 64) { int g = g0 + tid; if (g < n) p.out[oOP + g] = p.opa[g]; }
    __syncthreads();

    // ---- pack A fragments (hi/lo) into Apk ----
#pragma unroll 1
    for (int j = 0; j < 8; j++) {
        int f = w * 8 + j;                 // 0..63
        int ks = f >> 2, mt = f & 3;
        int r0 = mt * 16 + gq, r1 = r0 + 8;
        int k0 = ks * 16 + cc * 2;
        uint4 hi, lo;
        bsplit(H1raw[r0 * 257 + k0],     H1raw[r0 * 257 + k0 + 1], hi.x, lo.x);
        bsplit(H1raw[r1 * 257 + k0],     H1raw[r1 * 257 + k0 + 1], hi.y, lo.y);
        bsplit(H1raw[r0 * 257 + k0 + 8], H1raw[r0 * 257 + k0 + 9], hi.z, lo.z);
        bsplit(H1raw[r1 * 257 + k0 + 8], H1raw[r1 * 257 + k0 + 9], hi.w, lo.w);
        *(uint4*)(sm + OFF_APK + apk_off(ks, 0, mt, lane)) = hi;
        *(uint4*)(sm + OFF_APK + apk_off(ks, 1, mt, lane)) = lo;
    }
    __syncthreads();

    // prefetch B(h=0, ks=0) into regs
    uint4 cb[4];
    {
        const uint4* b = (const uint4*)g_w1pk;
#pragma unroll
        for (int i = 0; i < 4; i++) cb[i] = b[i * 256 + tid];
    }

#pragma unroll 1
    for (int h = 0; h < 5; h++) {
        float b1r[8];
#pragma unroll
        for (int nt = 0; nt < 4; nt++)
#pragma unroll
            for (int e = 0; e < 2; e++) {
                int nn = (w * 4 + nt) * 8 + cc * 2 + e;
                b1r[nt * 2 + e] = (nn < 255) ? p.b1[h][nn] : 0.0f;
            }

        float acc[4][4][4];
#pragma unroll
        for (int a = 0; a < 4; a++)
#pragma unroll
            for (int b = 0; b < 4; b++)
#pragma unroll
                for (int e = 0; e < 4; e++) acc[a][b][e] = 0.0f;

        // ---------- GEMM1 mainloop: split-pass outermost per k-step ----------
#pragma unroll 1
        for (int ks = 0; ks < 16; ks++) {
            uint4 nb[4];
            if (ks < 15) {
                const uint4* b = (const uint4*)(g_w1pk + (size_t)(h * 16 + ks + 1) * 16384);
#pragma unroll
                for (int i = 0; i < 4; i++) nb[i] = b[i * 256 + tid];
            }
            // load all A frags for this k-step
            uint32_t AH[4][4], AL[4][4];
#pragma unroll
            for (int mt = 0; mt < 4; mt++) {
                uint4 ahi = *(const uint4*)(sm + OFF_APK + apk_off(ks, 0, mt, lane));
                uint4 alo = *(const uint4*)(sm + OFF_APK + apk_off(ks, 1, mt, lane));
                AH[mt][0] = ahi.x; AH[mt][1] = ahi.y; AH[mt][2] = ahi.z; AH[mt][3] = ahi.w;
                AL[mt][0] = alo.x; AL[mt][1] = alo.y; AL[mt][2] = alo.z; AL[mt][3] = alo.w;
            }
            const uint32_t bh[4][2] = {{cb[0].x, cb[0].y}, {cb[0].z, cb[0].w},
                                       {cb[1].x, cb[1].y}, {cb[1].z, cb[1].w}};
            const uint32_t bl[4][2] = {{cb[2].x, cb[2].y}, {cb[2].z, cb[2].w},
                                       {cb[3].x, cb[3].y}, {cb[3].z, cb[3].w}};
            // pass 0: Ahi * Bhi  (16 independent accs)
#pragma unroll
            for (int mt = 0; mt < 4; mt++)
#pragma unroll
                for (int nt = 0; nt < 4; nt++)
                    mma16816(acc[mt][nt], AH[mt], bh[nt][0], bh[nt][1]);
            // pass 1: Ahi * Blo
#pragma unroll
            for (int mt = 0; mt < 4; mt++)
#pragma unroll
                for (int nt = 0; nt < 4; nt++)
                    mma16816(acc[mt][nt], AH[mt], bl[nt][0], bl[nt][1]);
            // pass 2: Alo * Bhi
#pragma unroll
            for (int mt = 0; mt < 4; mt++)
#pragma unroll
                for (int nt = 0; nt < 4; nt++)
                    mma16816(acc[mt][nt], AL[mt], bh[nt][0], bh[nt][1]);
            if (ks < 15) {
#pragma unroll
                for (int i = 0; i < 4; i++) cb[i] = nb[i];
            }
        }
        if (h < 4) {
            const uint4* b = (const uint4*)(g_w1pk + (size_t)((h + 1) * 16) * 16384);
#pragma unroll
            for (int i = 0; i < 4; i++) cb[i] = b[i * 256 + tid];
        }

        // ---------- pack H1 frags (bias+relu+split) into Apk2 ----------
        __syncthreads();   // previous GEMM2 done reading Apk2
#pragma unroll
        for (int mt = 0; mt < 4; mt++)
#pragma unroll
            for (int q = 0; q < 2; q++) {
                const int ks2 = 2 * w + q;
                float v00 = fmaxf(acc[mt][2 * q][0] + b1r[4 * q + 0], 0.0f);
                float v01 = fmaxf(acc[mt][2 * q][1] + b1r[4 * q + 1], 0.0f);
                float v10 = fmaxf(acc[mt][2 * q][2] + b1r[4 * q + 0], 0.0f);
                float v11 = fmaxf(acc[mt][2 * q][3] + b1r[4 * q + 1], 0.0f);
                float v20 = fmaxf(acc[mt][2 * q + 1][0] + b1r[4 * q + 2], 0.0f);
                float v21 = fmaxf(acc[mt][2 * q + 1][1] + b1r[4 * q + 3], 0.0f);
                float v30 = fmaxf(acc[mt][2 * q + 1][2] + b1r[4 * q + 2], 0.0f);
                float v31 = fmaxf(acc[mt][2 * q + 1][3] + b1r[4 * q + 3], 0.0f);
                uint4 hi, lo;
                bsplit(v00, v01, hi.x, lo.x);
                bsplit(v10, v11, hi.y, lo.y);
                bsplit(v20, v21, hi.z, lo.z);
                bsplit(v30, v31, hi.w, lo.w);
                *(uint4*)(sm + OFF_APK2 + apk_off(ks2, 0, mt, lane)) = hi;
                *(uint4*)(sm + OFF_APK2 + apk_off(ks2, 1, mt, lane)) = lo;
            }
        __syncthreads();

        // ---------- GEMM2 on HMMA + epilogue ----------
        const int ntc   = (h == 4) ? 6 : 1;
        const int slotb = (h == 4) ? 4 : h;
        const int njob  = (h == 4) ? 3 : 1;
        const int od    = (h == 4) ? 48 : ((h == 3) ? 4 : ((h == 0) ? 1 : 3));
#pragma unroll 1
        for (int jb = 0; jb < njob; jb++) {
            int t = w + 8 * jb;
            if (t >= 4 * ntc) continue;
            int mt = t / ntc, nt2 = t % ntc;
            float d0[4] = {0, 0, 0, 0}, d1[4] = {0, 0, 0, 0}, d2[4] = {0, 0, 0, 0};
            const uint4* wb = (const uint4*)g_w2pk + (slotb + nt2) * 16 * 32;
            uint4 B = wb[lane];
#pragma unroll 1
            for (int ks2 = 0; ks2 < 16; ks2++) {
                uint4 Bn;
                if (ks2 < 15) Bn = wb[(ks2 + 1) * 32 + lane];
                uint4 ahi = *(const uint4*)(sm + OFF_APK2 + apk_off(ks2, 0, mt, lane));
                uint4 alo = *(const uint4*)(sm + OFF_APK2 + apk_off(ks2, 1, mt, lane));
                uint32_t ah[4] = {ahi.x, ahi.y, ahi.z, ahi.w};
                uint32_t al[4] = {alo.x, alo.y, alo.z, alo.w};
                mma16816(d0, ah, B.x, B.y);   // Ahi*Bhi
                mma16816(d1, ah, B.z, B.w);   // Ahi*Blo
                mma16816(d2, al, B.x, B.y);   // Alo*Bhi
                if (ks2 < 15) B = Bn;
            }
            float d[4];
#pragma unroll
            for (int e = 0; e < 4; e++) d[e] = d0[e] + d1[e] + d2[e];

            if (h == 0) {
                if (cc == 0) {
                    float b20 = p.b2[0][0];
                    int m0 = mt * 16 + gq;
                    maskS[m0]     = 1.0f / (1.0f + expf(-(d[0] + b20)));
                    maskS[m0 + 8] = 1.0f / (1.0f + expf(-(d[2] + b20)));
                }
            } else {
#pragma unroll
                for (int e = 0; e < 4; e++) {
                    int o = nt2 * 8 + cc * 2 + (e & 1);
                    if (o < od) {
                        int m = mt * 16 + gq + ((e >> 1) << 3);
                        int g = g0 + m;
                        if (g < n) {
                            float val = d[e] + p.b2[h][o];
                            float mk = maskS[m];
                            if (h == 1) {
                                p.out[oDX + g * 3 + o]  = val;
                                p.out[oPTS + g * 3 + o] = p.pnt[g * 3 + o] + val * mk;
                            } else if (h == 2) {
                                p.out[oSCL + g * 3 + o] = p.scl[g * 3 + o] + val * mk;
                            } else if (h == 3) {
                                p.out[oROT + g * 4 + o] = p.rot[g * 4 + o] + val * mk;
                            } else {
                                p.out[oDSH + g * 48 + o] = val;
                                p.out[oSHS + g * 48 + o] = p.shs[g * 48 + o] + val * mk;
                            }
                        }
                    }
                }
            }
        }
    }
}

extern "C" void kernel_launch(void* const* d_in, const int* in_sizes, int n_in,
                              void* d_out, int out_size) {
    Params p;
    p.opa = (const float*)d_in[0];
    p.shs = (const float*)d_in[1];
    p.tim = (const float*)d_in[2];
    p.sem = (const float*)d_in[3];
    p.pnt = (const float*)d_in[4];
    p.scl = (const float*)d_in[5];
    p.rot = (const float*)d_in[6];
    p.dx  = (const float*)d_in[7];
    for (int h = 0; h < 5; h++) {
        p.w1[h] = (const float*)d_in[8 + h * 4 + 0];
        p.b1[h] = (const float*)d_in[8 + h * 4 + 1];
        p.w2[h] = (const float*)d_in[8 + h * 4 + 2];
        p.b2[h] = (const float*)d_in[8 + h * 4 + 3];
    }
    p.out = (float*)d_out;
    p.n   = in_sizes[0];

    prep_all<<<100, 256>>>(p.w1[0], p.w1[1], p.w1[2], p.w1[3], p.w1[4],
                           p.w2[0], p.w2[1], p.w2[2], p.w2[3], p.w2[4]);

    cudaFuncSetAttribute(deform2, cudaFuncAttributeMaxDynamicSharedMemorySize, SMEM_BYTES);
    const int grid = (p.n + 63) / 64;
    deform2<<<grid, 256, SMEM_BYTES>>>(p);
}

// round 7
// speedup vs baseline: 2.3260x; 1.2710x over previous
#include <cuda_runtime.h>
#include <cuda_bf16.h>
#include <cstdint>

// ============================================================================
// Deformation net, all-GEMM-on-HMMA (mma.sync m16n8k16 bf16, bf16x3 split,
// fp32 accum). CTA = 64 points, 512 threads (16 warps, 4/SMSP).
// Warp w owns output columns [w*16, w*16+16) of GEMM1 (nt=2 tiles).
//  - A = relu(hidden) packed once into smem A-fragments (hi/lo).
//  - W1 pre-packed per-thread B-fragment images in global; mainloop B via
//    coalesced LDG.128 straight to registers. No syncthreads in mainloop.
//  - GEMM2 on HMMA from in-register converted H1 fragments (C-frag==A-frag).
// ============================================================================

#define DEVI __device__ __forceinline__

// W1 packed frags: [head][ks][part 0..1][tid 0..511][16B] = 5*16*2*512*16 = 1.25MB
//   part0 = hi frags (nt0 2xu32, nt1 2xu32), part1 = lo frags.
__device__ __align__(16) unsigned char g_w1pk[5 * 16 * 2 * 512 * 16];
// W2 packed frags: [slot 0..9][ks2 0..15][lane 0..31][16B] = 80KB
__device__ __align__(16) unsigned char g_w2pk[10 * 16 * 32 * 16];

DEVI void bsplit(float x, float y, uint32_t& hi, uint32_t& lo) {
    __nv_bfloat16 hx = __float2bfloat16(x), hy = __float2bfloat16(y);
    __nv_bfloat16 lx = __float2bfloat16(x - __bfloat162float(hx));
    __nv_bfloat16 ly = __float2bfloat16(y - __bfloat162float(hy));
    hi = ((uint32_t)__bfloat16_as_ushort(hy) << 16) | __bfloat16_as_ushort(hx);
    lo = ((uint32_t)__bfloat16_as_ushort(ly) << 16) | __bfloat16_as_ushort(lx);
}

__global__ void prep_all(const float* w10, const float* w11, const float* w12,
                         const float* w13, const float* w14,
                         const float* w20, const float* w21, const float* w22,
                         const float* w23, const float* w24) {
    int idx = blockIdx.x * blockDim.x + threadIdx.x;
    if (idx < 40960) {                 // 5 heads * 16 ks * 512 tid
        const float* ws[5] = {w10, w11, w12, w13, w14};
        int h = idx >> 13, ks = (idx >> 9) & 15, tid = idx & 511;
        int w = tid >> 5, lane = tid & 31;
        const float* W = ws[h];
        uint32_t hb[2][2], lb[2][2];
#pragma unroll
        for (int ntl = 0; ntl < 2; ntl++) {
            int nn = (w * 2 + ntl) * 8 + (lane >> 2);
            int k0 = ks * 16 + (lane & 3) * 2;
            float v[4];
            int kk[4] = {k0, k0 + 1, k0 + 8, k0 + 9};
#pragma unroll
            for (int j = 0; j < 4; j++)
                v[j] = (kk[j] < 255 && nn < 255) ? W[kk[j] * 255 + nn] : 0.0f;
            bsplit(v[0], v[1], hb[ntl][0], lb[ntl][0]);
            bsplit(v[2], v[3], hb[ntl][1], lb[ntl][1]);
        }
        uint4* base = (uint4*)(g_w1pk + (size_t)(h * 16 + ks) * 16384);
        base[0 * 512 + tid] = make_uint4(hb[0][0], hb[0][1], hb[1][0], hb[1][1]);
        base[1 * 512 + tid] = make_uint4(lb[0][0], lb[0][1], lb[1][0], lb[1][1]);
    } else if (idx < 40960 + 5120) {
        const float* ws[5] = {w20, w21, w22, w23, w24};
        const int ods[5] = {1, 3, 3, 4, 48};
        int j = idx - 40960;
        int slot = j >> 9, ks2 = (j >> 5) & 15, lane = j & 31;
        int head = (slot < 4) ? slot : 4;
        int nt2  = (slot < 4) ? 0 : slot - 4;
        int od = ods[head];
        const float* W = ws[head];
        int nn = nt2 * 8 + (lane >> 2);
        int k0 = ks2 * 16 + (lane & 3) * 2;
        float v[4];
        int kk[4] = {k0, k0 + 1, k0 + 8, k0 + 9};
#pragma unroll
        for (int q = 0; q < 4; q++)
            v[q] = (kk[q] < 255 && nn < od) ? W[kk[q] * od + nn] : 0.0f;
        uint32_t h0, h1, l0, l1;
        bsplit(v[0], v[1], h0, l0);
        bsplit(v[2], v[3], h1, l1);
        ((uint4*)g_w2pk)[(slot * 16 + ks2) * 32 + lane] = make_uint4(h0, h1, l0, l1);
    }
}

// ---- mma (non-volatile: let ptxas schedule) ---------------------------------
DEVI void mma16816(float* d, const uint32_t* a, uint32_t b0, uint32_t b1) {
    asm("mma.sync.aligned.m16n8k16.row.col.f32.bf16.bf16.f32 "
        "{%0,%1,%2,%3}, {%4,%5,%6,%7}, {%8,%9}, {%0,%1,%2,%3};"
        : "+f"(d[0]), "+f"(d[1]), "+f"(d[2]), "+f"(d[3])
        : "r"(a[0]), "r"(a[1]), "r"(a[2]), "r"(a[3]), "r"(b0), "r"(b1));
}

struct Params {
    const float* opa; const float* shs; const float* tim; const float* sem;
    const float* pnt; const float* scl; const float* rot; const float* dx;
    const float* w1[5]; const float* b1[5]; const float* w2[5]; const float* b2[5];
    float* out; int n;
};

// ---- smem layout (bytes) -----------------------------------------------------
#define OFF_APK   0          // A frags: 16ks x 2split x 4mt x 32lane x 16B = 65536
#define OFF_APK2  65536      // H1 frags (same layout) / raw staging 64x257 f32
#define OFF_MASK  (65536 + 66048)
#define OFF_TPE   (OFF_MASK + 256)
#define SMEM_BYTES (OFF_TPE + 256)

DEVI uint32_t apk_off(int ks, int s, int mt, int lane) {
    return (uint32_t)((((ks * 2 + s) * 4 + mt) * 32 + lane) * 16);
}

__global__ __launch_bounds__(512, 1)
void deform3(Params p) {
    extern __shared__ __align__(16) unsigned char sm[];
    float* H1raw = (float*)(sm + OFF_APK2);    // staging, stride 257
    float* maskS = (float*)(sm + OFF_MASK);
    float* tpeS  = (float*)(sm + OFF_TPE);

    const int tid = threadIdx.x, w = tid >> 5, lane = tid & 31;
    const int gq = lane >> 2, cc = lane & 3;
    const int n = p.n, g0 = blockIdx.x * 64;
    const int oPTS = 0, oSCL = 3 * n, oROT = 6 * n, oOP = 10 * n,
              oSHS = 11 * n, oDX = 59 * n, oDSH = 62 * n;

    if (tid < 32) {
        float t = p.tim[0];
        float freq = exp2f((float)(2 * tid) * (13.287712379549449f / 32.0f));
        float a = t / freq;
        tpeS[2 * tid] = sinf(a);
        tpeS[2 * tid + 1] = cosf(a);
    }
    __syncthreads();

    // ---- raw A = relu(hidden) staging ----
    for (int idx = tid; idx < 64 * 256; idx += 512) {
        int m = idx >> 8, k = idx & 255;
        int g = g0 + m;
        float v = 0.0f;
        if (g < n && k < 255) {
            if      (k < 3)    v = p.pnt[g * 3 + k];
            else if (k < 7)    v = p.rot[g * 4 + (k - 3)];
            else if (k < 10)   v = p.scl[g * 3 + (k - 7)];
            else if (k == 10)  v = p.opa[g];
            else if (k < 59)   v = p.shs[g * 48 + (k - 11)];
            else if (k < 187)  v = p.sem[g * 128 + (k - 59)];
            else if (k < 190)  v = p.dx[g * 3 + (k - 187)];
            else if (k == 190) v = p.tim[g];
            else               v = tpeS[k - 191];
        }
        H1raw[m * 257 + k] = fmaxf(v, 0.0f);
    }
    if (tid < 64) { int g = g0 + tid; if (g < n) p.out[oOP + g] = p.opa[g]; }
    __syncthreads();

    // ---- pack A fragments (hi/lo) into Apk ----
#pragma unroll 1
    for (int j = 0; j < 4; j++) {
        int f = w * 4 + j;                 // 0..63
        int ks = f >> 2, mt = f & 3;
        int r0 = mt * 16 + gq, r1 = r0 + 8;
        int k0 = ks * 16 + cc * 2;
        uint4 hi, lo;
        bsplit(H1raw[r0 * 257 + k0],     H1raw[r0 * 257 + k0 + 1], hi.x, lo.x);
        bsplit(H1raw[r1 * 257 + k0],     H1raw[r1 * 257 + k0 + 1], hi.y, lo.y);
        bsplit(H1raw[r0 * 257 + k0 + 8], H1raw[r0 * 257 + k0 + 9], hi.z, lo.z);
        bsplit(H1raw[r1 * 257 + k0 + 8], H1raw[r1 * 257 + k0 + 9], hi.w, lo.w);
        *(uint4*)(sm + OFF_APK + apk_off(ks, 0, mt, lane)) = hi;
        *(uint4*)(sm + OFF_APK + apk_off(ks, 1, mt, lane)) = lo;
    }
    __syncthreads();

    // prefetch B(h=0, ks=0) into regs: cb[0]=hi frags (nt0,nt1), cb[1]=lo frags
    uint4 cb[2];
    {
        const uint4* b = (const uint4*)g_w1pk;
        cb[0] = b[0 * 512 + tid];
        cb[1] = b[1 * 512 + tid];
    }

#pragma unroll 1
    for (int h = 0; h < 5; h++) {
        float b1r[4];
#pragma unroll
        for (int nt = 0; nt < 2; nt++)
#pragma unroll
            for (int e = 0; e < 2; e++) {
                int nn = (w * 2 + nt) * 8 + cc * 2 + e;
                b1r[nt * 2 + e] = (nn < 255) ? p.b1[h][nn] : 0.0f;
            }

        float acc[4][2][4];
#pragma unroll
        for (int a = 0; a < 4; a++)
#pragma unroll
            for (int b = 0; b < 2; b++)
#pragma unroll
                for (int e = 0; e < 4; e++) acc[a][b][e] = 0.0f;

        // ---------- GEMM1 mainloop: split-pass outermost per k-step ----------
#pragma unroll 1
        for (int ks = 0; ks < 16; ks++) {
            uint4 nb[2];
            if (ks < 15) {
                const uint4* b = (const uint4*)(g_w1pk + (size_t)(h * 16 + ks + 1) * 16384);
                nb[0] = b[0 * 512 + tid];
                nb[1] = b[1 * 512 + tid];
            }
            uint32_t AH[4][4], AL[4][4];
#pragma unroll
            for (int mt = 0; mt < 4; mt++) {
                uint4 ahi = *(const uint4*)(sm + OFF_APK + apk_off(ks, 0, mt, lane));
                uint4 alo = *(const uint4*)(sm + OFF_APK + apk_off(ks, 1, mt, lane));
                AH[mt][0] = ahi.x; AH[mt][1] = ahi.y; AH[mt][2] = ahi.z; AH[mt][3] = ahi.w;
                AL[mt][0] = alo.x; AL[mt][1] = alo.y; AL[mt][2] = alo.z; AL[mt][3] = alo.w;
            }
            const uint32_t bh[2][2] = {{cb[0].x, cb[0].y}, {cb[0].z, cb[0].w}};
            const uint32_t bl[2][2] = {{cb[1].x, cb[1].y}, {cb[1].z, cb[1].w}};
            // pass 0: Ahi * Bhi  (8 independent accumulators)
#pragma unroll
            for (int mt = 0; mt < 4; mt++)
#pragma unroll
                for (int nt = 0; nt < 2; nt++)
                    mma16816(acc[mt][nt], AH[mt], bh[nt][0], bh[nt][1]);
            // pass 1: Ahi * Blo
#pragma unroll
            for (int mt = 0; mt < 4; mt++)
#pragma unroll
                for (int nt = 0; nt < 2; nt++)
                    mma16816(acc[mt][nt], AH[mt], bl[nt][0], bl[nt][1]);
            // pass 2: Alo * Bhi
#pragma unroll
            for (int mt = 0; mt < 4; mt++)
#pragma unroll
                for (int nt = 0; nt < 2; nt++)
                    mma16816(acc[mt][nt], AL[mt], bh[nt][0], bh[nt][1]);
            if (ks < 15) { cb[0] = nb[0]; cb[1] = nb[1]; }
        }
        if (h < 4) {
            const uint4* b = (const uint4*)(g_w1pk + (size_t)((h + 1) * 16) * 16384);
            cb[0] = b[0 * 512 + tid];
            cb[1] = b[1 * 512 + tid];
        }

        // ---------- pack H1 frags (bias+relu+split) into Apk2; ks2 = w --------
        __syncthreads();   // previous GEMM2 done reading Apk2
#pragma unroll
        for (int mt = 0; mt < 4; mt++) {
            float v00 = fmaxf(acc[mt][0][0] + b1r[0], 0.0f);
            float v01 = fmaxf(acc[mt][0][1] + b1r[1], 0.0f);
            float v10 = fmaxf(acc[mt][0][2] + b1r[0], 0.0f);
            float v11 = fmaxf(acc[mt][0][3] + b1r[1], 0.0f);
            float v20 = fmaxf(acc[mt][1][0] + b1r[2], 0.0f);
            float v21 = fmaxf(acc[mt][1][1] + b1r[3], 0.0f);
            float v30 = fmaxf(acc[mt][1][2] + b1r[2], 0.0f);
            float v31 = fmaxf(acc[mt][1][3] + b1r[3], 0.0f);
            uint4 hi, lo;
            bsplit(v00, v01, hi.x, lo.x);
            bsplit(v10, v11, hi.y, lo.y);
            bsplit(v20, v21, hi.z, lo.z);
            bsplit(v30, v31, hi.w, lo.w);
            *(uint4*)(sm + OFF_APK2 + apk_off(w, 0, mt, lane)) = hi;
            *(uint4*)(sm + OFF_APK2 + apk_off(w, 1, mt, lane)) = lo;
        }
        __syncthreads();

        // ---------- GEMM2 on HMMA + epilogue ----------
        const int ntc   = (h == 4) ? 6 : 1;
        const int slotb = (h == 4) ? 4 : h;
        const int njob  = (h == 4) ? 2 : 1;
        const int od    = (h == 4) ? 48 : ((h == 3) ? 4 : ((h == 0) ? 1 : 3));
#pragma unroll 1
        for (int jb = 0; jb < njob; jb++) {
            int t = w + 16 * jb;
            if (t >= 4 * ntc) continue;
            int mt = t / ntc, nt2 = t % ntc;
            float d0[4] = {0, 0, 0, 0}, d1[4] = {0, 0, 0, 0}, d2[4] = {0, 0, 0, 0};
            const uint4* wb = (const uint4*)g_w2pk + (slotb + nt2) * 16 * 32;
            uint4 B = wb[lane];
#pragma unroll 1
            for (int ks2 = 0; ks2 < 16; ks2++) {
                uint4 Bn;
                if (ks2 < 15) Bn = wb[(ks2 + 1) * 32 + lane];
                uint4 ahi = *(const uint4*)(sm + OFF_APK2 + apk_off(ks2, 0, mt, lane));
                uint4 alo = *(const uint4*)(sm + OFF_APK2 + apk_off(ks2, 1, mt, lane));
                uint32_t ah[4] = {ahi.x, ahi.y, ahi.z, ahi.w};
                uint32_t al[4] = {alo.x, alo.y, alo.z, alo.w};
                mma16816(d0, ah, B.x, B.y);   // Ahi*Bhi
                mma16816(d1, ah, B.z, B.w);   // Ahi*Blo
                mma16816(d2, al, B.x, B.y);   // Alo*Bhi
                if (ks2 < 15) B = Bn;
            }
            float d[4];
#pragma unroll
            for (int e = 0; e < 4; e++) d[e] = d0[e] + d1[e] + d2[e];

            if (h == 0) {
                if (cc == 0) {
                    float b20 = p.b2[0][0];
                    int m0 = mt * 16 + gq;
                    maskS[m0]     = 1.0f / (1.0f + expf(-(d[0] + b20)));
                    maskS[m0 + 8] = 1.0f / (1.0f + expf(-(d[2] + b20)));
                }
            } else {
#pragma unroll
                for (int e = 0; e < 4; e++) {
                    int o = nt2 * 8 + cc * 2 + (e & 1);
                    if (o < od) {
                        int m = mt * 16 + gq + ((e >> 1) << 3);
                        int g = g0 + m;
                        if (g < n) {
                            float val = d[e] + p.b2[h][o];
                            float mk = maskS[m];
                            if (h == 1) {
                                p.out[oDX + g * 3 + o]  = val;
                                p.out[oPTS + g * 3 + o] = p.pnt[g * 3 + o] + val * mk;
                            } else if (h == 2) {
                                p.out[oSCL + g * 3 + o] = p.scl[g * 3 + o] + val * mk;
                            } else if (h == 3) {
                                p.out[oROT + g * 4 + o] = p.rot[g * 4 + o] + val * mk;
                            } else {
                                p.out[oDSH + g * 48 + o] = val;
                                p.out[oSHS + g * 48 + o] = p.shs[g * 48 + o] + val * mk;
                            }
                        }
                    }
                }
            }
        }
    }
}

extern "C" void kernel_launch(void* const* d_in, const int* in_sizes, int n_in,
                              void* d_out, int out_size) {
    Params p;
    p.opa = (const float*)d_in[0];
    p.shs = (const float*)d_in[1];
    p.tim = (const float*)d_in[2];
    p.sem = (const float*)d_in[3];
    p.pnt = (const float*)d_in[4];
    p.scl = (const float*)d_in[5];
    p.rot = (const float*)d_in[6];
    p.dx  = (const float*)d_in[7];
    for (int h = 0; h < 5; h++) {
        p.w1[h] = (const float*)d_in[8 + h * 4 + 0];
        p.b1[h] = (const float*)d_in[8 + h * 4 + 1];
        p.w2[h] = (const float*)d_in[8 + h * 4 + 2];
        p.b2[h] = (const float*)d_in[8 + h * 4 + 3];
    }
    p.out = (float*)d_out;
    p.n   = in_sizes[0];

    prep_all<<<180, 256>>>(p.w1[0], p.w1[1], p.w1[2], p.w1[3], p.w1[4],
                           p.w2[0], p.w2[1], p.w2[2], p.w2[3], p.w2[4]);

    cudaFuncSetAttribute(deform3, cudaFuncAttributeMaxDynamicSharedMemorySize, SMEM_BYTES);
    const int grid = (p.n + 63) / 64;
    deform3<<<grid, 512, SMEM_BYTES>>>(p);
}

// round 8
// speedup vs baseline: 2.3354x; 1.0041x over previous
#include <cuda_runtime.h>
#include <cuda_bf16.h>
#include <cstdint>

// ============================================================================
// Deformation net, HMMA (mma.sync m16n8k16 bf16, bf16x3 split, fp32 accum).
// CTA = 128 points (mt=8), 512 threads (16 warps, 4/SMSP).
// Warp w owns GEMM1 output cols [w*16, w*16+16) (nt=2).
//  - A = relu(hidden) packed once into smem A-fragments (hi/lo), 131 KB.
//  - W1 pre-packed per-thread B-frag images in global; B via coalesced
//    LDG.128 straight to regs, double buffered. No syncs in mainloop.
//  - Heads 0-3 GEMM2: SIMT fp32 K-split from GEMM1 accumulators (all warps),
//    shfl + smem tree reduction. Head 4 GEMM2 on HMMA (H1 repacked into Apk).
// ============================================================================

#define DEVI __device__ __forceinline__

// W1 packed frags: [head][ks][part hi/lo][tid 0..511][16B] = 1.25MB
__device__ __align__(16) unsigned char g_w1pk[5 * 16 * 2 * 512 * 16];
// W2 packed frags (head 4 only used): [slot 0..9][ks2 0..15][lane][16B]
__device__ __align__(16) unsigned char g_w2pk[10 * 16 * 32 * 16];

DEVI void bsplit(float x, float y, uint32_t& hi, uint32_t& lo) {
    __nv_bfloat16 hx = __float2bfloat16(x), hy = __float2bfloat16(y);
    __nv_bfloat16 lx = __float2bfloat16(x - __bfloat162float(hx));
    __nv_bfloat16 ly = __float2bfloat16(y - __bfloat162float(hy));
    hi = ((uint32_t)__bfloat16_as_ushort(hy) << 16) | __bfloat16_as_ushort(hx);
    lo = ((uint32_t)__bfloat16_as_ushort(ly) << 16) | __bfloat16_as_ushort(lx);
}

__global__ void prep_all(const float* w10, const float* w11, const float* w12,
                         const float* w13, const float* w14,
                         const float* w20, const float* w21, const float* w22,
                         const float* w23, const float* w24) {
    int idx = blockIdx.x * blockDim.x + threadIdx.x;
    if (idx < 40960) {                 // 5 heads * 16 ks * 512 tid
        const float* ws[5] = {w10, w11, w12, w13, w14};
        int h = idx >> 13, ks = (idx >> 9) & 15, tid = idx & 511;
        int w = tid >> 5, lane = tid & 31;
        const float* W = ws[h];
        uint32_t hb[2][2], lb[2][2];
#pragma unroll
        for (int ntl = 0; ntl < 2; ntl++) {
            int nn = (w * 2 + ntl) * 8 + (lane >> 2);
            int k0 = ks * 16 + (lane & 3) * 2;
            float v[4];
            int kk[4] = {k0, k0 + 1, k0 + 8, k0 + 9};
#pragma unroll
            for (int j = 0; j < 4; j++)
                v[j] = (kk[j] < 255 && nn < 255) ? W[kk[j] * 255 + nn] : 0.0f;
            bsplit(v[0], v[1], hb[ntl][0], lb[ntl][0]);
            bsplit(v[2], v[3], hb[ntl][1], lb[ntl][1]);
        }
        uint4* base = (uint4*)(g_w1pk + (size_t)(h * 16 + ks) * 16384);
        base[0 * 512 + tid] = make_uint4(hb[0][0], hb[0][1], hb[1][0], hb[1][1]);
        base[1 * 512 + tid] = make_uint4(lb[0][0], lb[0][1], lb[1][0], lb[1][1]);
    } else if (idx < 40960 + 5120) {
        const float* ws[5] = {w20, w21, w22, w23, w24};
        const int ods[5] = {1, 3, 3, 4, 48};
        int j = idx - 40960;
        int slot = j >> 9, ks2 = (j >> 5) & 15, lane = j & 31;
        int head = (slot < 4) ? slot : 4;
        int nt2  = (slot < 4) ? 0 : slot - 4;
        int od = ods[head];
        const float* W = ws[head];
        int nn = nt2 * 8 + (lane >> 2);
        int k0 = ks2 * 16 + (lane & 3) * 2;
        float v[4];
        int kk[4] = {k0, k0 + 1, k0 + 8, k0 + 9};
#pragma unroll
        for (int q = 0; q < 4; q++)
            v[q] = (kk[q] < 255 && nn < od) ? W[kk[q] * od + nn] : 0.0f;
        uint32_t h0, h1, l0, l1;
        bsplit(v[0], v[1], h0, l0);
        bsplit(v[2], v[3], h1, l1);
        ((uint4*)g_w2pk)[(slot * 16 + ks2) * 32 + lane] = make_uint4(h0, h1, l0, l1);
    }
}

DEVI void mma16816(float* d, const uint32_t* a, uint32_t b0, uint32_t b1) {
    asm("mma.sync.aligned.m16n8k16.row.col.f32.bf16.bf16.f32 "
        "{%0,%1,%2,%3}, {%4,%5,%6,%7}, {%8,%9}, {%0,%1,%2,%3};"
        : "+f"(d[0]), "+f"(d[1]), "+f"(d[2]), "+f"(d[3])
        : "r"(a[0]), "r"(a[1]), "r"(a[2]), "r"(a[3]), "r"(b0), "r"(b1));
}

struct Params {
    const float* opa; const float* shs; const float* tim; const float* sem;
    const float* pnt; const float* scl; const float* rot; const float* dx;
    const float* w1[5]; const float* b1[5]; const float* w2[5]; const float* b2[5];
    float* out; int n;
};

// ---- smem layout (bytes) -----------------------------------------------------
// Apk: 16ks x 2split x 8mt x 32lane x 16B = 131072 (A frags; H1 frags for h=4)
// SCR: raw A staging 64x257 f32 (65792) at start; later red4 [128][16] float4
//      (32768) + w2S (4096 @ +33792)
#define OFF_APK   0
#define OFF_SCR   131072
#define OFF_W2S   (OFF_SCR + 33792)
#define OFF_MASK  (OFF_SCR + 66048)
#define OFF_TPE   (OFF_MASK + 512)
#define SMEM_BYTES (OFF_TPE + 256)

DEVI uint32_t apk_off(int ks, int s, int mt, int lane) {
    return (uint32_t)((((ks * 2 + s) * 8 + mt) * 32 + lane) * 16);
}

// ---- SIMT GEMM2 (heads 0-3) from GEMM1 accumulators, K-split over warps ----
template <int OD, int H>
DEVI void simt_g2(const float (*acc)[2][4], const float* b1r, const float* w2S,
                  float4* red4, float* maskS, const Params& p,
                  int w, int lane, int gq, int cc, int g0) {
    const int n = p.n;
    // per-thread W2 rows for its 4 k-values
    float wv[2][2][OD];
#pragma unroll
    for (int nt = 0; nt < 2; nt++)
#pragma unroll
        for (int e1 = 0; e1 < 2; e1++) {
            int k = w * 16 + nt * 8 + cc * 2 + e1;
#pragma unroll
            for (int o = 0; o < OD; o++)
                wv[nt][e1][o] = (k < 255) ? w2S[k * OD + o] : 0.0f;
        }
    float part[16][OD];
#pragma unroll
    for (int s = 0; s < 16; s++)
#pragma unroll
        for (int o = 0; o < OD; o++) part[s][o] = 0.0f;
#pragma unroll
    for (int mt = 0; mt < 8; mt++)
#pragma unroll
        for (int nt = 0; nt < 2; nt++)
#pragma unroll
            for (int e = 0; e < 4; e++) {
                float hv = fmaxf(acc[mt][nt][e] + b1r[nt * 2 + (e & 1)], 0.0f);
                int s = mt * 2 + (e >> 1);
#pragma unroll
                for (int o = 0; o < OD; o++)
                    part[s][o] += hv * wv[nt][e & 1][o];
            }
    // reduce over the 4 cc-lanes sharing (gq, m-set)
#pragma unroll
    for (int s = 0; s < 16; s++)
#pragma unroll
        for (int o = 0; o < OD; o++) {
            float v = part[s][o];
            v += __shfl_xor_sync(0xffffffffu, v, 1);
            v += __shfl_xor_sync(0xffffffffu, v, 2);
            part[s][o] = v;
        }
    if (cc == 0) {
#pragma unroll
        for (int s = 0; s < 16; s++) {
            int m = (s >> 1) * 16 + gq + (s & 1) * 8;
            float4 v = make_float4(part[s][0],
                                   OD > 1 ? part[s][1] : 0.0f,
                                   OD > 2 ? part[s][2] : 0.0f,
                                   OD > 3 ? part[s][3] : 0.0f);
            red4[m * 16 + w] = v;
        }
    }
    __syncthreads();
    int tid = w * 32 + lane;
    if (tid < 128) {
        int m = tid;
        float4 a4 = make_float4(0.f, 0.f, 0.f, 0.f);
#pragma unroll
        for (int wi = 0; wi < 16; wi++) {
            float4 r = red4[m * 16 + wi];
            a4.x += r.x; a4.y += r.y; a4.z += r.z; a4.w += r.w;
        }
        int g = g0 + m;
        if (H == 0) {
            maskS[m] = 1.0f / (1.0f + expf(-(a4.x + p.b2[0][0])));
        } else if (g < n) {
            float mk = maskS[m];
            float vo[4] = {a4.x, a4.y, a4.z, a4.w};
#pragma unroll
            for (int o = 0; o < OD; o++) {
                float val = vo[o] + p.b2[H][o];
                if (H == 1) {
                    p.out[59 * n + g * 3 + o] = val;                      // dx_out
                    p.out[g * 3 + o] = p.pnt[g * 3 + o] + val * mk;       // pts
                } else if (H == 2) {
                    p.out[3 * n + g * 3 + o] = p.scl[g * 3 + o] + val * mk;
                } else {
                    p.out[6 * n + g * 4 + o] = p.rot[g * 4 + o] + val * mk;
                }
            }
        }
    }
    __syncthreads();
}

__global__ __launch_bounds__(512, 1)
void deform4(Params p) {
    extern __shared__ __align__(16) unsigned char sm[];
    float*  H1raw = (float*)(sm + OFF_SCR);    // staging, stride 257 (64 rows)
    float4* red4  = (float4*)(sm + OFF_SCR);
    float*  w2S   = (float*)(sm + OFF_W2S);
    float*  maskS = (float*)(sm + OFF_MASK);
    float*  tpeS  = (float*)(sm + OFF_TPE);

    const int tid = threadIdx.x, w = tid >> 5, lane = tid & 31;
    const int gq = lane >> 2, cc = lane & 3;
    const int n = p.n, g0 = blockIdx.x * 128;
    const int oOP = 10 * n, oSHS = 11 * n, oDSH = 62 * n;

    if (tid < 32) {
        float t = p.tim[0];
        float freq = exp2f((float)(2 * tid) * (13.287712379549449f / 32.0f));
        float a = t / freq;
        tpeS[2 * tid] = sinf(a);
        tpeS[2 * tid + 1] = cosf(a);
    }
    __syncthreads();

    // ---- build A = relu(hidden), two 64-row halves; pack frags into Apk ----
#pragma unroll 1
    for (int half = 0; half < 2; half++) {
        for (int idx = tid; idx < 64 * 256; idx += 512) {
            int lr = idx >> 8, k = idx & 255;
            int g = g0 + half * 64 + lr;
            float v = 0.0f;
            if (g < n && k < 255) {
                if      (k < 3)    v = p.pnt[g * 3 + k];
                else if (k < 7)    v = p.rot[g * 4 + (k - 3)];
                else if (k < 10)   v = p.scl[g * 3 + (k - 7)];
                else if (k == 10)  v = p.opa[g];
                else if (k < 59)   v = p.shs[g * 48 + (k - 11)];
                else if (k < 187)  v = p.sem[g * 128 + (k - 59)];
                else if (k < 190)  v = p.dx[g * 3 + (k - 187)];
                else if (k == 190) v = p.tim[g];
                else               v = tpeS[k - 191];
            }
            H1raw[lr * 257 + k] = fmaxf(v, 0.0f);
        }
        __syncthreads();
#pragma unroll 1
        for (int j = 0; j < 4; j++) {
            int f = w * 4 + j;                 // 0..63 = ks*4 + mtl
            int ks = f >> 2, mtl = f & 3;
            int mt = half * 4 + mtl;
            int r0 = mtl * 16 + gq, r1 = r0 + 8;
            int k0 = ks * 16 + cc * 2;
            uint4 hi, lo;
            bsplit(H1raw[r0 * 257 + k0],     H1raw[r0 * 257 + k0 + 1], hi.x, lo.x);
            bsplit(H1raw[r1 * 257 + k0],     H1raw[r1 * 257 + k0 + 1], hi.y, lo.y);
            bsplit(H1raw[r0 * 257 + k0 + 8], H1raw[r0 * 257 + k0 + 9], hi.z, lo.z);
            bsplit(H1raw[r1 * 257 + k0 + 8], H1raw[r1 * 257 + k0 + 9], hi.w, lo.w);
            *(uint4*)(sm + OFF_APK + apk_off(ks, 0, mt, lane)) = hi;
            *(uint4*)(sm + OFF_APK + apk_off(ks, 1, mt, lane)) = lo;
        }
        __syncthreads();
    }
    if (tid < 128) { int g = g0 + tid; if (g < n) p.out[oOP + g] = p.opa[g]; }

    // prefetch B(h=0, ks=0)
    uint4 cb[2];
    {
        const uint4* b = (const uint4*)g_w1pk;
        cb[0] = b[tid];
        cb[1] = b[512 + tid];
    }

#pragma unroll 1
    for (int h = 0; h < 5; h++) {
        // stage W2 for SIMT heads while tensor work proceeds below
        if (h < 4) {
            const int od = (h == 3) ? 4 : ((h == 0) ? 1 : 3);
            for (int i = tid; i < 255 * od; i += 512) w2S[i] = p.w2[h][i];
        }

        float b1r[4];
#pragma unroll
        for (int nt = 0; nt < 2; nt++)
#pragma unroll
            for (int e = 0; e < 2; e++) {
                int nn = w * 16 + nt * 8 + cc * 2 + e;
                b1r[nt * 2 + e] = (nn < 255) ? p.b1[h][nn] : 0.0f;
            }

        float acc[8][2][4];
#pragma unroll
        for (int a = 0; a < 8; a++)
#pragma unroll
            for (int b = 0; b < 2; b++)
#pragma unroll
                for (int e = 0; e < 4; e++) acc[a][b][e] = 0.0f;

        // ---------- GEMM1 mainloop ----------
#pragma unroll 1
        for (int ks = 0; ks < 16; ks++) {
            uint4 nb0, nb1;
            if (ks < 15) {
                const uint4* b = (const uint4*)(g_w1pk + (size_t)(h * 16 + ks + 1) * 16384);
                nb0 = b[tid];
                nb1 = b[512 + tid];
            }
            const uint32_t bh[2][2] = {{cb[0].x, cb[0].y}, {cb[0].z, cb[0].w}};
            const uint32_t bl[2][2] = {{cb[1].x, cb[1].y}, {cb[1].z, cb[1].w}};
            // process mt in pairs: 12 MMAs per pair, pass-major (reuse dist 4)
#pragma unroll
            for (int mp = 0; mp < 4; mp++) {
                const int m0 = 2 * mp, m1 = 2 * mp + 1;
                uint4 h0 = *(const uint4*)(sm + OFF_APK + apk_off(ks, 0, m0, lane));
                uint4 h1v = *(const uint4*)(sm + OFF_APK + apk_off(ks, 0, m1, lane));
                uint4 l0 = *(const uint4*)(sm + OFF_APK + apk_off(ks, 1, m0, lane));
                uint4 l1 = *(const uint4*)(sm + OFF_APK + apk_off(ks, 1, m1, lane));
                uint32_t A0[4] = {h0.x, h0.y, h0.z, h0.w};
                uint32_t A1[4] = {h1v.x, h1v.y, h1v.z, h1v.w};
                uint32_t L0[4] = {l0.x, l0.y, l0.z, l0.w};
                uint32_t L1[4] = {l1.x, l1.y, l1.z, l1.w};
                // pass 0: Ahi*Bhi
                mma16816(acc[m0][0], A0, bh[0][0], bh[0][1]);
                mma16816(acc[m0][1], A0, bh[1][0], bh[1][1]);
                mma16816(acc[m1][0], A1, bh[0][0], bh[0][1]);
                mma16816(acc[m1][1], A1, bh[1][0], bh[1][1]);
                // pass 1: Ahi*Blo
                mma16816(acc[m0][0], A0, bl[0][0], bl[0][1]);
                mma16816(acc[m0][1], A0, bl[1][0], bl[1][1]);
                mma16816(acc[m1][0], A1, bl[0][0], bl[0][1]);
                mma16816(acc[m1][1], A1, bl[1][0], bl[1][1]);
                // pass 2: Alo*Bhi
                mma16816(acc[m0][0], L0, bh[0][0], bh[0][1]);
                mma16816(acc[m0][1], L0, bh[1][0], bh[1][1]);
                mma16816(acc[m1][0], L1, bh[0][0], bh[0][1]);
                mma16816(acc[m1][1], L1, bh[1][0], bh[1][1]);
            }
            if (ks < 15) { cb[0] = nb0; cb[1] = nb1; }
        }
        if (h < 4) {
            const uint4* b = (const uint4*)(g_w1pk + (size_t)((h + 1) * 16) * 16384);
            cb[0] = b[tid];
            cb[1] = b[512 + tid];
        }

        if (h < 4) {
            // ---------- SIMT GEMM2 (K-split over warps) ----------
            __syncthreads();   // w2S staged; red4 region free (prev readers done)
            if      (h == 0) simt_g2<1, 0>(acc, b1r, w2S, red4, maskS, p, w, lane, gq, cc, g0);
            else if (h == 1) simt_g2<3, 1>(acc, b1r, w2S, red4, maskS, p, w, lane, gq, cc, g0);
            else if (h == 2) simt_g2<3, 2>(acc, b1r, w2S, red4, maskS, p, w, lane, gq, cc, g0);
            else             simt_g2<4, 3>(acc, b1r, w2S, red4, maskS, p, w, lane, gq, cc, g0);
        } else {
            // ---------- head 4: pack H1 frags into Apk (A frags dead) --------
            __syncthreads();   // all warps done reading A frags
#pragma unroll
            for (int mt = 0; mt < 8; mt++) {
                float v00 = fmaxf(acc[mt][0][0] + b1r[0], 0.0f);
                float v01 = fmaxf(acc[mt][0][1] + b1r[1], 0.0f);
                float v10 = fmaxf(acc[mt][0][2] + b1r[0], 0.0f);
                float v11 = fmaxf(acc[mt][0][3] + b1r[1], 0.0f);
                float v20 = fmaxf(acc[mt][1][0] + b1r[2], 0.0f);
                float v21 = fmaxf(acc[mt][1][1] + b1r[3], 0.0f);
                float v30 = fmaxf(acc[mt][1][2] + b1r[2], 0.0f);
                float v31 = fmaxf(acc[mt][1][3] + b1r[3], 0.0f);
                uint4 hi, lo;
                bsplit(v00, v01, hi.x, lo.x);
                bsplit(v10, v11, hi.y, lo.y);
                bsplit(v20, v21, hi.z, lo.z);
                bsplit(v30, v31, hi.w, lo.w);
                *(uint4*)(sm + OFF_APK + apk_off(w, 0, mt, lane)) = hi;
                *(uint4*)(sm + OFF_APK + apk_off(w, 1, mt, lane)) = lo;
            }
            __syncthreads();

            // ---------- GEMM2 on HMMA: 48 jobs (8mt x 6nt2) over 16 warps ----
#pragma unroll 1
            for (int jb = 0; jb < 3; jb++) {
                int t = w + 16 * jb;           // 0..47
                int mt = t / 6, nt2 = t % 6;
                float d0[4] = {0, 0, 0, 0}, d1[4] = {0, 0, 0, 0}, d2[4] = {0, 0, 0, 0};
                const uint4* wb = (const uint4*)g_w2pk + (4 + nt2) * 16 * 32;
                uint4 B = wb[lane];
#pragma unroll 1
                for (int ks2 = 0; ks2 < 16; ks2++) {
                    uint4 Bn;
                    if (ks2 < 15) Bn = wb[(ks2 + 1) * 32 + lane];
                    uint4 ahi = *(const uint4*)(sm + OFF_APK + apk_off(ks2, 0, mt, lane));
                    uint4 alo = *(const uint4*)(sm + OFF_APK + apk_off(ks2, 1, mt, lane));
                    uint32_t ah[4] = {ahi.x, ahi.y, ahi.z, ahi.w};
                    uint32_t al[4] = {alo.x, alo.y, alo.z, alo.w};
                    mma16816(d0, ah, B.x, B.y);
                    mma16816(d1, ah, B.z, B.w);
                    mma16816(d2, al, B.x, B.y);
                    if (ks2 < 15) B = Bn;
                }
#pragma unroll
                for (int e = 0; e < 4; e++) {
                    int o = nt2 * 8 + cc * 2 + (e & 1);
                    int m = mt * 16 + gq + ((e >> 1) << 3);
                    int g = g0 + m;
                    if (g < n) {
                        float val = d0[e] + d1[e] + d2[e] + p.b2[4][o];
                        float mk = maskS[m];
                        p.out[oDSH + g * 48 + o] = val;
                        p.out[oSHS + g * 48 + o] = p.shs[g * 48 + o] + val * mk;
                    }
                }
            }
        }
    }
}

extern "C" void kernel_launch(void* const* d_in, const int* in_sizes, int n_in,
                              void* d_out, int out_size) {
    Params p;
    p.opa = (const float*)d_in[0];
    p.shs = (const float*)d_in[1];
    p.tim = (const float*)d_in[2];
    p.sem = (const float*)d_in[3];
    p.pnt = (const float*)d_in[4];
    p.scl = (const float*)d_in[5];
    p.rot = (const float*)d_in[6];
    p.dx  = (const float*)d_in[7];
    for (int h = 0; h < 5; h++) {
        p.w1[h] = (const float*)d_in[8 + h * 4 + 0];
        p.b1[h] = (const float*)d_in[8 + h * 4 + 1];
        p.w2[h] = (const float*)d_in[8 + h * 4 + 2];
        p.b2[h] = (const float*)d_in[8 + h * 4 + 3];
    }
    p.out = (float*)d_out;
    p.n   = in_sizes[0];

    prep_all<<<180, 256>>>(p.w1[0], p.w1[1], p.w1[2], p.w1[3], p.w1[4],
                           p.w2[0], p.w2[1], p.w2[2], p.w2[3], p.w2[4]);

    cudaFuncSetAttribute(deform4, cudaFuncAttributeMaxDynamicSharedMemorySize, SMEM_BYTES);
    const int grid = (p.n + 127) / 128;
    deform4<<<grid, 512, SMEM_BYTES>>>(p);
}

// round 9
// speedup vs baseline: 3.0674x; 1.3134x over previous
#include <cuda_runtime.h>
#include <cuda_bf16.h>
#include <cstdint>

// ============================================================================
// Deformation net, HMMA (mma.sync m16n8k16 bf16, bf16x3 split, fp32 accum).
// CTA = 64 points (mt=4), 256 threads (8 warps), 2 CTAs/SM for phase overlap.
// Warp w owns GEMM1 output cols [w*32, w*32+32) (nt=4).
//  - A = relu(hidden) packed once into smem A-fragments (hi/lo), 64 KB.
//  - W1 pre-packed per-thread B-frag images; B via LDG.128 double-buffered.
//  - Heads 0-3 GEMM2: SIMT fp32 K-split from GEMM1 accumulators.
//    Head 4 GEMM2 on HMMA (H1 repacked into Apk).
// ============================================================================

#define DEVI __device__ __forceinline__

// W1 packed frags: [head][ks][slot 0..3][tid 0..255] x uint4 = 1.25MB
//  slot0 = hi nt0,nt1; slot1 = hi nt2,nt3; slot2 = lo nt0,nt1; slot3 = lo nt2,nt3
__device__ __align__(16) unsigned char g_w1pk[5 * 16 * 4 * 256 * 16];
// W2 packed frags (head 4 uses slots 4..9): [slot][ks2][lane] x uint4
__device__ __align__(16) unsigned char g_w2pk[10 * 16 * 32 * 16];

DEVI void bsplit(float x, float y, uint32_t& hi, uint32_t& lo) {
    __nv_bfloat16 hx = __float2bfloat16(x), hy = __float2bfloat16(y);
    __nv_bfloat16 lx = __float2bfloat16(x - __bfloat162float(hx));
    __nv_bfloat16 ly = __float2bfloat16(y - __bfloat162float(hy));
    hi = ((uint32_t)__bfloat16_as_ushort(hy) << 16) | __bfloat16_as_ushort(hx);
    lo = ((uint32_t)__bfloat16_as_ushort(ly) << 16) | __bfloat16_as_ushort(lx);
}

__global__ void prep_all(const float* w10, const float* w11, const float* w12,
                         const float* w13, const float* w14,
                         const float* w20, const float* w21, const float* w22,
                         const float* w23, const float* w24) {
    int idx = blockIdx.x * blockDim.x + threadIdx.x;
    if (idx < 20480) {                 // 5 heads * 16 ks * 256 tid
        const float* ws[5] = {w10, w11, w12, w13, w14};
        int h = idx >> 12, ks = (idx >> 8) & 15, tid = idx & 255;
        int w = tid >> 5, lane = tid & 31;
        int gq = lane >> 2, cc = lane & 3;
        const float* W = ws[h];
        uint32_t hb[4][2], lb[4][2];
#pragma unroll
        for (int ntl = 0; ntl < 4; ntl++) {
            int nn = (w * 4 + ntl) * 8 + gq;
            int k0 = ks * 16 + cc * 2;
            float v[4];
            int kk[4] = {k0, k0 + 1, k0 + 8, k0 + 9};
#pragma unroll
            for (int j = 0; j < 4; j++)
                v[j] = (kk[j] < 255 && nn < 255) ? W[kk[j] * 255 + nn] : 0.0f;
            bsplit(v[0], v[1], hb[ntl][0], lb[ntl][0]);
            bsplit(v[2], v[3], hb[ntl][1], lb[ntl][1]);
        }
        uint4* base = (uint4*)(g_w1pk + (size_t)(h * 16 + ks) * 16384);
        base[0 * 256 + tid] = make_uint4(hb[0][0], hb[0][1], hb[1][0], hb[1][1]);
        base[1 * 256 + tid] = make_uint4(hb[2][0], hb[2][1], hb[3][0], hb[3][1]);
        base[2 * 256 + tid] = make_uint4(lb[0][0], lb[0][1], lb[1][0], lb[1][1]);
        base[3 * 256 + tid] = make_uint4(lb[2][0], lb[2][1], lb[3][0], lb[3][1]);
    } else if (idx < 20480 + 5120) {
        const float* ws[5] = {w20, w21, w22, w23, w24};
        const int ods[5] = {1, 3, 3, 4, 48};
        int j = idx - 20480;
        int slot = j >> 9, ks2 = (j >> 5) & 15, lane = j & 31;
        int head = (slot < 4) ? slot : 4;
        int nt2  = (slot < 4) ? 0 : slot - 4;
        int od = ods[head];
        const float* W = ws[head];
        int nn = nt2 * 8 + (lane >> 2);
        int k0 = ks2 * 16 + (lane & 3) * 2;
        float v[4];
        int kk[4] = {k0, k0 + 1, k0 + 8, k0 + 9};
#pragma unroll
        for (int q = 0; q < 4; q++)
            v[q] = (kk[q] < 255 && nn < od) ? W[kk[q] * od + nn] : 0.0f;
        uint32_t h0, h1, l0, l1;
        bsplit(v[0], v[1], h0, l0);
        bsplit(v[2], v[3], h1, l1);
        ((uint4*)g_w2pk)[(slot * 16 + ks2) * 32 + lane] = make_uint4(h0, h1, l0, l1);
    }
}

DEVI void mma16816(float* d, const uint32_t* a, uint32_t b0, uint32_t b1) {
    asm("mma.sync.aligned.m16n8k16.row.col.f32.bf16.bf16.f32 "
        "{%0,%1,%2,%3}, {%4,%5,%6,%7}, {%8,%9}, {%0,%1,%2,%3};"
        : "+f"(d[0]), "+f"(d[1]), "+f"(d[2]), "+f"(d[3])
        : "r"(a[0]), "r"(a[1]), "r"(a[2]), "r"(a[3]), "r"(b0), "r"(b1));
}

struct Params {
    const float* opa; const float* shs; const float* tim; const float* sem;
    const float* pnt; const float* scl; const float* rot; const float* dx;
    const float* w1[5]; const float* b1[5]; const float* w2[5]; const float* b2[5];
    float* out; int n;
};

// ---- smem layout (bytes), ~101 KB total (2 CTAs/SM) ---------------------------
// Apk: 16ks x 2split x 4mt x 32lane x 16B = 65536 (A frags; H1 frags for h=4)
// SCR: raw A staging 32x257 f32 (32896); later red4 [64][8] float4 (8192)
#define OFF_APK   0
#define OFF_SCR   65536
#define OFF_W2S   (OFF_SCR + 32896)
#define OFF_MASK  (OFF_W2S + 4096)
#define OFF_TPE   (OFF_MASK + 256)
#define SMEM_BYTES (OFF_TPE + 256)

DEVI uint32_t apk_off(int ks, int s, int mt, int lane) {
    return (uint32_t)((((ks * 2 + s) * 4 + mt) * 32 + lane) * 16);
}

// ---- SIMT GEMM2 (heads 0-3): K-split over 8 warps ----------------------------
template <int OD, int H>
DEVI void simt_g2(const float (*acc)[4][4], const float* b1r, const float* w2S,
                  float4* red4, float* maskS, const Params& p,
                  int w, int lane, int gq, int cc, int g0) {
    const int n = p.n;
    float wv[4][2][OD];
#pragma unroll
    for (int nt = 0; nt < 4; nt++)
#pragma unroll
        for (int e1 = 0; e1 < 2; e1++) {
            int k = w * 32 + nt * 8 + cc * 2 + e1;
#pragma unroll
            for (int o = 0; o < OD; o++)
                wv[nt][e1][o] = (k < 255) ? w2S[k * OD + o] : 0.0f;
        }
    float part[8][OD];
#pragma unroll
    for (int s = 0; s < 8; s++)
#pragma unroll
        for (int o = 0; o < OD; o++) part[s][o] = 0.0f;
#pragma unroll
    for (int mt = 0; mt < 4; mt++)
#pragma unroll
        for (int nt = 0; nt < 4; nt++)
#pragma unroll
            for (int e = 0; e < 4; e++) {
                float hv = fmaxf(acc[mt][nt][e] + b1r[nt * 2 + (e & 1)], 0.0f);
                int s = mt * 2 + (e >> 1);
#pragma unroll
                for (int o = 0; o < OD; o++)
                    part[s][o] += hv * wv[nt][e & 1][o];
            }
#pragma unroll
    for (int s = 0; s < 8; s++)
#pragma unroll
        for (int o = 0; o < OD; o++) {
            float v = part[s][o];
            v += __shfl_xor_sync(0xffffffffu, v, 1);
            v += __shfl_xor_sync(0xffffffffu, v, 2);
            part[s][o] = v;
        }
    if (cc == 0) {
#pragma unroll
        for (int s = 0; s < 8; s++) {
            int m = (s >> 1) * 16 + gq + (s & 1) * 8;
            red4[m * 8 + w] = make_float4(part[s][0],
                                          OD > 1 ? part[s][1] : 0.0f,
                                          OD > 2 ? part[s][2] : 0.0f,
                                          OD > 3 ? part[s][3] : 0.0f);
        }
    }
    __syncthreads();
    int tid = w * 32 + lane;
    if (tid < 64) {
        int m = tid;
        float4 a4 = make_float4(0.f, 0.f, 0.f, 0.f);
#pragma unroll
        for (int wi = 0; wi < 8; wi++) {
            float4 r = red4[m * 8 + wi];
            a4.x += r.x; a4.y += r.y; a4.z += r.z; a4.w += r.w;
        }
        int g = g0 + m;
        if (H == 0) {
            maskS[m] = 1.0f / (1.0f + expf(-(a4.x + p.b2[0][0])));
        } else if (g < n) {
            float mk = maskS[m];
            float vo[4] = {a4.x, a4.y, a4.z, a4.w};
#pragma unroll
            for (int o = 0; o < OD; o++) {
                float val = vo[o] + p.b2[H][o];
                if (H == 1) {
                    p.out[59 * n + g * 3 + o] = val;                  // dx_out
                    p.out[g * 3 + o] = p.pnt[g * 3 + o] + val * mk;   // pts
                } else if (H == 2) {
                    p.out[3 * n + g * 3 + o] = p.scl[g * 3 + o] + val * mk;
                } else {
                    p.out[6 * n + g * 4 + o] = p.rot[g * 4 + o] + val * mk;
                }
            }
        }
    }
    __syncthreads();
}

__global__ __launch_bounds__(256, 2)
void deform5(Params p) {
    extern __shared__ __align__(16) unsigned char sm[];
    float*  H1raw = (float*)(sm + OFF_SCR);    // staging, 32 rows x stride 257
    float4* red4  = (float4*)(sm + OFF_SCR);
    float*  w2S   = (float*)(sm + OFF_W2S);
    float*  maskS = (float*)(sm + OFF_MASK);
    float*  tpeS  = (float*)(sm + OFF_TPE);

    const int tid = threadIdx.x, w = tid >> 5, lane = tid & 31;
    const int gq = lane >> 2, cc = lane & 3;
    const int n = p.n, g0 = blockIdx.x * 64;
    const int oOP = 10 * n, oSHS = 11 * n, oDSH = 62 * n;

    if (tid < 32) {
        float t = p.tim[0];
        float freq = exp2f((float)(2 * tid) * (13.287712379549449f / 32.0f));
        float a = t / freq;
        tpeS[2 * tid] = sinf(a);
        tpeS[2 * tid + 1] = cosf(a);
    }
    __syncthreads();

    // ---- build A = relu(hidden), two 32-row halves; pack frags into Apk ----
#pragma unroll 1
    for (int half = 0; half < 2; half++) {
        for (int idx = tid; idx < 32 * 256; idx += 256) {
            int lr = idx >> 8, k = idx & 255;
            int g = g0 + half * 32 + lr;
            float v = 0.0f;
            if (g < n && k < 255) {
                if      (k < 3)    v = p.pnt[g * 3 + k];
                else if (k < 7)    v = p.rot[g * 4 + (k - 3)];
                else if (k < 10)   v = p.scl[g * 3 + (k - 7)];
                else if (k == 10)  v = p.opa[g];
                else if (k < 59)   v = p.shs[g * 48 + (k - 11)];
                else if (k < 187)  v = p.sem[g * 128 + (k - 59)];
                else if (k < 190)  v = p.dx[g * 3 + (k - 187)];
                else if (k == 190) v = p.tim[g];
                else               v = tpeS[k - 191];
            }
            H1raw[lr * 257 + k] = fmaxf(v, 0.0f);
        }
        __syncthreads();
        // 32 frag-sets per half: (ks 0..15, mtl 0..1); 4 per warp
#pragma unroll 1
        for (int j = 0; j < 4; j++) {
            int f = w * 4 + j;                 // 0..31
            int ks = f >> 1, mtl = f & 1;
            int mt = half * 2 + mtl;
            int r0 = mtl * 16 + gq, r1 = r0 + 8;
            int k0 = ks * 16 + cc * 2;
            uint4 hi, lo;
            bsplit(H1raw[r0 * 257 + k0],     H1raw[r0 * 257 + k0 + 1], hi.x, lo.x);
            bsplit(H1raw[r1 * 257 + k0],     H1raw[r1 * 257 + k0 + 1], hi.y, lo.y);
            bsplit(H1raw[r0 * 257 + k0 + 8], H1raw[r0 * 257 + k0 + 9], hi.z, lo.z);
            bsplit(H1raw[r1 * 257 + k0 + 8], H1raw[r1 * 257 + k0 + 9], hi.w, lo.w);
            *(uint4*)(sm + OFF_APK + apk_off(ks, 0, mt, lane)) = hi;
            *(uint4*)(sm + OFF_APK + apk_off(ks, 1, mt, lane)) = lo;
        }
        __syncthreads();
    }
    if (tid < 64) { int g = g0 + tid; if (g < n) p.out[oOP + g] = p.opa[g]; }

    // prefetch B(h=0, ks=0): slot0,1 = hi (nt0..3), slot2,3 = lo
    uint4 cbh0, cbh1, cbl0, cbl1;
    {
        const uint4* b = (const uint4*)g_w1pk;
        cbh0 = b[0 * 256 + tid]; cbh1 = b[1 * 256 + tid];
        cbl0 = b[2 * 256 + tid]; cbl1 = b[3 * 256 + tid];
    }

#pragma unroll 1
    for (int h = 0; h < 5; h++) {
        if (h < 4) {
            const int od = (h == 3) ? 4 : ((h == 0) ? 1 : 3);
            for (int i = tid; i < 255 * od; i += 256) w2S[i] = p.w2[h][i];
        }

        float b1r[8];
#pragma unroll
        for (int nt = 0; nt < 4; nt++)
#pragma unroll
            for (int e = 0; e < 2; e++) {
                int nn = w * 32 + nt * 8 + cc * 2 + e;
                b1r[nt * 2 + e] = (nn < 255) ? p.b1[h][nn] : 0.0f;
            }

        float acc[4][4][4];
#pragma unroll
        for (int a = 0; a < 4; a++)
#pragma unroll
            for (int b = 0; b < 4; b++)
#pragma unroll
                for (int e = 0; e < 4; e++) acc[a][b][e] = 0.0f;

        // ---------- GEMM1 mainloop (no syncs) ----------
#pragma unroll 1
        for (int ks = 0; ks < 16; ks++) {
            uint4 nh0, nh1, nl0, nl1;
            if (ks < 15) {
                const uint4* b = (const uint4*)(g_w1pk + (size_t)(h * 16 + ks + 1) * 16384);
                nh0 = b[0 * 256 + tid]; nh1 = b[1 * 256 + tid];
                nl0 = b[2 * 256 + tid]; nl1 = b[3 * 256 + tid];
            }
            const uint32_t bh[4][2] = {{cbh0.x, cbh0.y}, {cbh0.z, cbh0.w},
                                       {cbh1.x, cbh1.y}, {cbh1.z, cbh1.w}};
            const uint32_t bl[4][2] = {{cbl0.x, cbl0.y}, {cbl0.z, cbl0.w},
                                       {cbl1.x, cbl1.y}, {cbl1.z, cbl1.w}};
#pragma unroll
            for (int mp = 0; mp < 2; mp++) {
                const int m0 = 2 * mp, m1 = 2 * mp + 1;
                uint4 h0 = *(const uint4*)(sm + OFF_APK + apk_off(ks, 0, m0, lane));
                uint4 h1v = *(const uint4*)(sm + OFF_APK + apk_off(ks, 0, m1, lane));
                uint4 l0 = *(const uint4*)(sm + OFF_APK + apk_off(ks, 1, m0, lane));
                uint4 l1 = *(const uint4*)(sm + OFF_APK + apk_off(ks, 1, m1, lane));
                uint32_t A0[4] = {h0.x, h0.y, h0.z, h0.w};
                uint32_t A1[4] = {h1v.x, h1v.y, h1v.z, h1v.w};
                uint32_t L0[4] = {l0.x, l0.y, l0.z, l0.w};
                uint32_t L1[4] = {l1.x, l1.y, l1.z, l1.w};
                // pass 0: Ahi*Bhi (8 independent accs)
#pragma unroll
                for (int nt = 0; nt < 4; nt++) mma16816(acc[m0][nt], A0, bh[nt][0], bh[nt][1]);
#pragma unroll
                for (int nt = 0; nt < 4; nt++) mma16816(acc[m1][nt], A1, bh[nt][0], bh[nt][1]);
                // pass 1: Ahi*Blo
#pragma unroll
                for (int nt = 0; nt < 4; nt++) mma16816(acc[m0][nt], A0, bl[nt][0], bl[nt][1]);
#pragma unroll
                for (int nt = 0; nt < 4; nt++) mma16816(acc[m1][nt], A1, bl[nt][0], bl[nt][1]);
                // pass 2: Alo*Bhi
#pragma unroll
                for (int nt = 0; nt < 4; nt++) mma16816(acc[m0][nt], L0, bh[nt][0], bh[nt][1]);
#pragma unroll
                for (int nt = 0; nt < 4; nt++) mma16816(acc[m1][nt], L1, bh[nt][0], bh[nt][1]);
            }
            if (ks < 15) { cbh0 = nh0; cbh1 = nh1; cbl0 = nl0; cbl1 = nl1; }
        }
        if (h < 4) {
            const uint4* b = (const uint4*)(g_w1pk + (size_t)((h + 1) * 16) * 16384);
            cbh0 = b[0 * 256 + tid]; cbh1 = b[1 * 256 + tid];
            cbl0 = b[2 * 256 + tid]; cbl1 = b[3 * 256 + tid];
        }

        if (h < 4) {
            __syncthreads();   // w2S staged; red4 free
            if      (h == 0) simt_g2<1, 0>(acc, b1r, w2S, red4, maskS, p, w, lane, gq, cc, g0);
            else if (h == 1) simt_g2<3, 1>(acc, b1r, w2S, red4, maskS, p, w, lane, gq, cc, g0);
            else if (h == 2) simt_g2<3, 2>(acc, b1r, w2S, red4, maskS, p, w, lane, gq, cc, g0);
            else             simt_g2<4, 3>(acc, b1r, w2S, red4, maskS, p, w, lane, gq, cc, g0);
        } else {
            // ---- head 4: pack H1 frags into Apk (warp owns ks2 = 2w, 2w+1) --
            __syncthreads();   // all warps done reading A frags
#pragma unroll
            for (int q = 0; q < 2; q++) {
                const int ks2 = 2 * w + q;
#pragma unroll
                for (int mt = 0; mt < 4; mt++) {
                    float v00 = fmaxf(acc[mt][2 * q][0] + b1r[4 * q + 0], 0.0f);
                    float v01 = fmaxf(acc[mt][2 * q][1] + b1r[4 * q + 1], 0.0f);
                    float v10 = fmaxf(acc[mt][2 * q][2] + b1r[4 * q + 0], 0.0f);
                    float v11 = fmaxf(acc[mt][2 * q][3] + b1r[4 * q + 1], 0.0f);
                    float v20 = fmaxf(acc[mt][2 * q + 1][0] + b1r[4 * q + 2], 0.0f);
                    float v21 = fmaxf(acc[mt][2 * q + 1][1] + b1r[4 * q + 3], 0.0f);
                    float v30 = fmaxf(acc[mt][2 * q + 1][2] + b1r[4 * q + 2], 0.0f);
                    float v31 = fmaxf(acc[mt][2 * q + 1][3] + b1r[4 * q + 3], 0.0f);
                    uint4 hi, lo;
                    bsplit(v00, v01, hi.x, lo.x);
                    bsplit(v10, v11, hi.y, lo.y);
                    bsplit(v20, v21, hi.z, lo.z);
                    bsplit(v30, v31, hi.w, lo.w);
                    *(uint4*)(sm + OFF_APK + apk_off(ks2, 0, mt, lane)) = hi;
                    *(uint4*)(sm + OFF_APK + apk_off(ks2, 1, mt, lane)) = lo;
                }
            }
            __syncthreads();

            // ---- GEMM2 on HMMA: 24 jobs (4mt x 6nt2) over 8 warps ----
#pragma unroll 1
            for (int jb = 0; jb < 3; jb++) {
                int t = w + 8 * jb;            // 0..23
                int mt = t / 6, nt2 = t % 6;
                float d0[4] = {0, 0, 0, 0}, d1[4] = {0, 0, 0, 0}, d2[4] = {0, 0, 0, 0};
                const uint4* wb = (const uint4*)g_w2pk + (4 + nt2) * 16 * 32;
                uint4 B = wb[lane];
#pragma unroll 1
                for (int ks2 = 0; ks2 < 16; ks2++) {
                    uint4 Bn;
                    if (ks2 < 15) Bn = wb[(ks2 + 1) * 32 + lane];
                    uint4 ahi = *(const uint4*)(sm + OFF_APK + apk_off(ks2, 0, mt, lane));
                    uint4 alo = *(const uint4*)(sm + OFF_APK + apk_off(ks2, 1, mt, lane));
                    uint32_t ah[4] = {ahi.x, ahi.y, ahi.z, ahi.w};
                    uint32_t al[4] = {alo.x, alo.y, alo.z, alo.w};
                    mma16816(d0, ah, B.x, B.y);
                    mma16816(d1, ah, B.z, B.w);
                    mma16816(d2, al, B.x, B.y);
                    if (ks2 < 15) B = Bn;
                }
#pragma unroll
                for (int e = 0; e < 4; e++) {
                    int o = nt2 * 8 + cc * 2 + (e & 1);
                    int m = mt * 16 + gq + ((e >> 1) << 3);
                    int g = g0 + m;
                    if (g < n) {
                        float val = d0[e] + d1[e] + d2[e] + p.b2[4][o];
                        float mk = maskS[m];
                        p.out[oDSH + g * 48 + o] = val;
                        p.out[oSHS + g * 48 + o] = p.shs[g * 48 + o] + val * mk;
                    }
                }
            }
        }
    }
}

extern "C" void kernel_launch(void* const* d_in, const int* in_sizes, int n_in,
                              void* d_out, int out_size) {
    Params p;
    p.opa = (const float*)d_in[0];
    p.shs = (const float*)d_in[1];
    p.tim = (const float*)d_in[2];
    p.sem = (const float*)d_in[3];
    p.pnt = (const float*)d_in[4];
    p.scl = (const float*)d_in[5];
    p.rot = (const float*)d_in[6];
    p.dx  = (const float*)d_in[7];
    for (int h = 0; h < 5; h++) {
        p.w1[h] = (const float*)d_in[8 + h * 4 + 0];
        p.b1[h] = (const float*)d_in[8 + h * 4 + 1];
        p.w2[h] = (const float*)d_in[8 + h * 4 + 2];
        p.b2[h] = (const float*)d_in[8 + h * 4 + 3];
    }
    p.out = (float*)d_out;
    p.n   = in_sizes[0];

    prep_all<<<100, 256>>>(p.w1[0], p.w1[1], p.w1[2], p.w1[3], p.w1[4],
                           p.w2[0], p.w2[1], p.w2[2], p.w2[3], p.w2[4]);

    cudaFuncSetAttribute(deform5, cudaFuncAttributeMaxDynamicSharedMemorySize, SMEM_BYTES);
    const int grid = (p.n + 63) / 64;
    deform5<<<grid, 256, SMEM_BYTES>>>(p);
}

// round 10
// speedup vs baseline: 3.8169x; 1.2443x over previous
#include <cuda_runtime.h>
#include <cuda_fp16.h>
#include <cstdint>

// ============================================================================
// Deformation net, HMMA fp16 2-pass (A single fp16, B split hi+lo fp16 offline;
// D = A*Bhi + A*Blo, fp32 accum). CTA = 64 points, 256 threads, 2 CTAs/SM.
// Warp w owns GEMM1 cols [w*32, w*32+32) (nt=4).
//  - Heads 0-3 GEMM2: SIMT fp32 partials per head (syncless) into red4[h];
//    ALL reductions + outputs deferred to one combined phase.
//  - Head 4 GEMM2 on HMMA, 2-pass (H1 single fp16, W2 split offline).
// ============================================================================

#define DEVI __device__ __forceinline__

// W1 packed frags: [head][ks][slot 0..3][tid 0..255] x uint4 = 1.25MB
//  slot0 = hi nt0,nt1; slot1 = hi nt2,nt3; slot2 = lo nt0,nt1; slot3 = lo nt2,nt3
__device__ __align__(16) unsigned char g_w1pk[5 * 16 * 4 * 256 * 16];
// W2 packed frags (head 4 uses slots 4..9): [slot][ks2][lane] x uint4 (hi0,hi1,lo0,lo1)
__device__ __align__(16) unsigned char g_w2pk[10 * 16 * 32 * 16];

DEVI void hsplit(float x, float y, uint32_t& hi, uint32_t& lo) {
    __half hx = __float2half_rn(x), hy = __float2half_rn(y);
    __half lx = __float2half_rn(x - __half2float(hx));
    __half ly = __float2half_rn(y - __half2float(hy));
    hi = ((uint32_t)__half_as_ushort(hy) << 16) | __half_as_ushort(hx);
    lo = ((uint32_t)__half_as_ushort(ly) << 16) | __half_as_ushort(lx);
}
DEVI uint32_t f2h2(float x, float y) {
    __half2 h = __floats2half2_rn(x, y);    // low = x, high = y
    return *(uint32_t*)&h;
}

__global__ void prep_all(const float* w10, const float* w11, const float* w12,
                         const float* w13, const float* w14,
                         const float* w20, const float* w21, const float* w22,
                         const float* w23, const float* w24) {
    int idx = blockIdx.x * blockDim.x + threadIdx.x;
    if (idx < 20480) {                 // 5 heads * 16 ks * 256 tid
        const float* ws[5] = {w10, w11, w12, w13, w14};
        int h = idx >> 12, ks = (idx >> 8) & 15, tid = idx & 255;
        int w = tid >> 5, lane = tid & 31;
        int gq = lane >> 2, cc = lane & 3;
        const float* W = ws[h];
        uint32_t hb[4][2], lb[4][2];
#pragma unroll
        for (int ntl = 0; ntl < 4; ntl++) {
            int nn = (w * 4 + ntl) * 8 + gq;
            int k0 = ks * 16 + cc * 2;
            float v[4];
            int kk[4] = {k0, k0 + 1, k0 + 8, k0 + 9};
#pragma unroll
            for (int j = 0; j < 4; j++)
                v[j] = (kk[j] < 255 && nn < 255) ? W[kk[j] * 255 + nn] : 0.0f;
            hsplit(v[0], v[1], hb[ntl][0], lb[ntl][0]);
            hsplit(v[2], v[3], hb[ntl][1], lb[ntl][1]);
        }
        uint4* base = (uint4*)(g_w1pk + (size_t)(h * 16 + ks) * 16384);
        base[0 * 256 + tid] = make_uint4(hb[0][0], hb[0][1], hb[1][0], hb[1][1]);
        base[1 * 256 + tid] = make_uint4(hb[2][0], hb[2][1], hb[3][0], hb[3][1]);
        base[2 * 256 + tid] = make_uint4(lb[0][0], lb[0][1], lb[1][0], lb[1][1]);
        base[3 * 256 + tid] = make_uint4(lb[2][0], lb[2][1], lb[3][0], lb[3][1]);
    } else if (idx < 20480 + 5120) {
        const float* ws[5] = {w20, w21, w22, w23, w24};
        const int ods[5] = {1, 3, 3, 4, 48};
        int j = idx - 20480;
        int slot = j >> 9, ks2 = (j >> 5) & 15, lane = j & 31;
        int head = (slot < 4) ? slot : 4;
        int nt2  = (slot < 4) ? 0 : slot - 4;
        int od = ods[head];
        const float* W = ws[head];
        int nn = nt2 * 8 + (lane >> 2);
        int k0 = ks2 * 16 + (lane & 3) * 2;
        float v[4];
        int kk[4] = {k0, k0 + 1, k0 + 8, k0 + 9};
#pragma unroll
        for (int q = 0; q < 4; q++)
            v[q] = (kk[q] < 255 && nn < od) ? W[kk[q] * od + nn] : 0.0f;
        uint32_t h0, h1, l0, l1;
        hsplit(v[0], v[1], h0, l0);
        hsplit(v[2], v[3], h1, l1);
        ((uint4*)g_w2pk)[(slot * 16 + ks2) * 32 + lane] = make_uint4(h0, h1, l0, l1);
    }
}

DEVI void mma_f16(float* d, const uint32_t* a, uint32_t b0, uint32_t b1) {
    asm("mma.sync.aligned.m16n8k16.row.col.f32.f16.f16.f32 "
        "{%0,%1,%2,%3}, {%4,%5,%6,%7}, {%8,%9}, {%0,%1,%2,%3};"
        : "+f"(d[0]), "+f"(d[1]), "+f"(d[2]), "+f"(d[3])
        : "r"(a[0]), "r"(a[1]), "r"(a[2]), "r"(a[3]), "r"(b0), "r"(b1));
}

struct Params {
    const float* opa; const float* shs; const float* tim; const float* sem;
    const float* pnt; const float* scl; const float* rot; const float* dx;
    const float* w1[5]; const float* b1[5]; const float* w2[5]; const float* b2[5];
    float* out; int n;
};

// ---- smem layout (bytes), ~77 KB (2 CTAs/SM) ----------------------------------
// Apk: 16ks x 4mt x 32lane x 16B = 32768 (A frags fp16; H1 frags for h=4)
// SCR: raw A staging 32x257 f32 (32896); later red4[4] buffers 4x8192
#define OFF_APK   0
#define OFF_SCR   32768
#define OFF_W2S4  (OFF_SCR + 32896)
#define OFF_MASK  (OFF_W2S4 + 11264)
#define OFF_TPE   (OFF_MASK + 256)
#define SMEM_BYTES (OFF_TPE + 256)

DEVI uint32_t apk1(int ks, int mt, int lane) {
    return (uint32_t)(((ks * 4 + mt) * 32 + lane) * 16);
}

// ---- per-head SIMT GEMM2 partials (syncless): write red4h ---------------------
template <int OD>
DEVI void part_g2(const float (*acc)[4][4], const float* b1r, const float* w2h,
                  float4* red4h, int w, int gq, int cc) {
    float wv[4][2][OD];
#pragma unroll
    for (int nt = 0; nt < 4; nt++)
#pragma unroll
        for (int e1 = 0; e1 < 2; e1++) {
            int k = w * 32 + nt * 8 + cc * 2 + e1;
#pragma unroll
            for (int o = 0; o < OD; o++)
                wv[nt][e1][o] = (k < 255) ? w2h[k * OD + o] : 0.0f;
        }
    float part[8][OD];
#pragma unroll
    for (int s = 0; s < 8; s++)
#pragma unroll
        for (int o = 0; o < OD; o++) part[s][o] = 0.0f;
#pragma unroll
    for (int mt = 0; mt < 4; mt++)
#pragma unroll
        for (int nt = 0; nt < 4; nt++)
#pragma unroll
            for (int e = 0; e < 4; e++) {
                float hv = fmaxf(acc[mt][nt][e] + b1r[nt * 2 + (e & 1)], 0.0f);
                int s = mt * 2 + (e >> 1);
#pragma unroll
                for (int o = 0; o < OD; o++)
                    part[s][o] += hv * wv[nt][e & 1][o];
            }
#pragma unroll
    for (int s = 0; s < 8; s++)
#pragma unroll
        for (int o = 0; o < OD; o++) {
            float v = part[s][o];
            v += __shfl_xor_sync(0xffffffffu, v, 1);
            v += __shfl_xor_sync(0xffffffffu, v, 2);
            part[s][o] = v;
        }
    if (cc == 0) {
#pragma unroll
        for (int s = 0; s < 8; s++) {
            int m = (s >> 1) * 16 + gq + (s & 1) * 8;
            red4h[m * 8 + w] = make_float4(part[s][0],
                                           OD > 1 ? part[s][1] : 0.0f,
                                           OD > 2 ? part[s][2] : 0.0f,
                                           OD > 3 ? part[s][3] : 0.0f);
        }
    }
}

__global__ __launch_bounds__(256, 2)
void deform6(Params p) {
    extern __shared__ __align__(16) unsigned char sm[];
    float*  H1raw = (float*)(sm + OFF_SCR);     // staging, 32 rows x stride 257
    float*  w2S4  = (float*)(sm + OFF_W2S4);
    float*  maskS = (float*)(sm + OFF_MASK);
    float*  tpeS  = (float*)(sm + OFF_TPE);

    const int tid = threadIdx.x, w = tid >> 5, lane = tid & 31;
    const int gq = lane >> 2, cc = lane & 3;
    const int n = p.n, g0 = blockIdx.x * 64;
    const int oSHS = 11 * n, oDSH = 62 * n;
    const int w2off[4] = {0, 256, 1024, 1792};
    const int ods4[4] = {1, 3, 3, 4};

    if (tid < 32) {
        float t = p.tim[0];
        float freq = exp2f((float)(2 * tid) * (13.287712379549449f / 32.0f));
        float a = t / freq;
        tpeS[2 * tid] = sinf(a);
        tpeS[2 * tid + 1] = cosf(a);
    }
    // stage all 4 small-head W2 (separate region, no sync needed vs tpe)
#pragma unroll 1
    for (int hh = 0; hh < 4; hh++)
        for (int i = tid; i < 255 * ods4[hh]; i += 256)
            w2S4[w2off[hh] + i] = p.w2[hh][i];
    __syncthreads();

    // ---- build A = relu(hidden), two 32-row halves; pack fp16 frags ----
#pragma unroll 1
    for (int half = 0; half < 2; half++) {
        for (int idx = tid; idx < 32 * 256; idx += 256) {
            int lr = idx >> 8, k = idx & 255;
            int g = g0 + half * 32 + lr;
            float v = 0.0f;
            if (g < n && k < 255) {
                if      (k < 3)    v = p.pnt[g * 3 + k];
                else if (k < 7)    v = p.rot[g * 4 + (k - 3)];
                else if (k < 10)   v = p.scl[g * 3 + (k - 7)];
                else if (k == 10)  v = p.opa[g];
                else if (k < 59)   v = p.shs[g * 48 + (k - 11)];
                else if (k < 187)  v = p.sem[g * 128 + (k - 59)];
                else if (k < 190)  v = p.dx[g * 3 + (k - 187)];
                else if (k == 190) v = p.tim[g];
                else               v = tpeS[k - 191];
            }
            H1raw[lr * 257 + k] = fmaxf(v, 0.0f);
        }
        __syncthreads();
#pragma unroll 1
        for (int j = 0; j < 4; j++) {
            int f = w * 4 + j;                 // 0..31 = ks*2 + mtl
            int ks = f >> 1, mtl = f & 1;
            int mt = half * 2 + mtl;
            int r0 = mtl * 16 + gq, r1 = r0 + 8;
            int k0 = ks * 16 + cc * 2;
            uint4 fr;
            fr.x = f2h2(H1raw[r0 * 257 + k0],     H1raw[r0 * 257 + k0 + 1]);
            fr.y = f2h2(H1raw[r1 * 257 + k0],     H1raw[r1 * 257 + k0 + 1]);
            fr.z = f2h2(H1raw[r0 * 257 + k0 + 8], H1raw[r0 * 257 + k0 + 9]);
            fr.w = f2h2(H1raw[r1 * 257 + k0 + 8], H1raw[r1 * 257 + k0 + 9]);
            *(uint4*)(sm + OFF_APK + apk1(ks, mt, lane)) = fr;
        }
        __syncthreads();
    }
    if (tid < 64) { int g = g0 + tid; if (g < n) p.out[10 * n + g] = p.opa[g]; }

    // prefetch B(h=0, ks=0)
    uint4 cbh0, cbh1, cbl0, cbl1;
    {
        const uint4* b = (const uint4*)g_w1pk;
        cbh0 = b[0 * 256 + tid]; cbh1 = b[1 * 256 + tid];
        cbl0 = b[2 * 256 + tid]; cbl1 = b[3 * 256 + tid];
    }

    float mO1[4], mO2[4], mO3[4];   // deferred head outputs (combined phase)
    (void)mO1; (void)mO2; (void)mO3;

#pragma unroll 1
    for (int h = 0; h < 5; h++) {
        float b1r[8];
#pragma unroll
        for (int nt = 0; nt < 4; nt++)
#pragma unroll
            for (int e = 0; e < 2; e++) {
                int nn = w * 32 + nt * 8 + cc * 2 + e;
                b1r[nt * 2 + e] = (nn < 255) ? p.b1[h][nn] : 0.0f;
            }

        float acc[4][4][4];
#pragma unroll
        for (int a = 0; a < 4; a++)
#pragma unroll
            for (int b = 0; b < 4; b++)
#pragma unroll
                for (int e = 0; e < 4; e++) acc[a][b][e] = 0.0f;

        // ---------- GEMM1 mainloop: 2 passes (A*Bhi + A*Blo), no syncs ----------
#pragma unroll 1
        for (int ks = 0; ks < 16; ks++) {
            uint4 nh0, nh1, nl0, nl1;
            if (ks < 15) {
                const uint4* b = (const uint4*)(g_w1pk + (size_t)(h * 16 + ks + 1) * 16384);
                nh0 = b[0 * 256 + tid]; nh1 = b[1 * 256 + tid];
                nl0 = b[2 * 256 + tid]; nl1 = b[3 * 256 + tid];
            }
            const uint32_t bh[4][2] = {{cbh0.x, cbh0.y}, {cbh0.z, cbh0.w},
                                       {cbh1.x, cbh1.y}, {cbh1.z, cbh1.w}};
            const uint32_t bl[4][2] = {{cbl0.x, cbl0.y}, {cbl0.z, cbl0.w},
                                       {cbl1.x, cbl1.y}, {cbl1.z, cbl1.w}};
#pragma unroll
            for (int mp = 0; mp < 2; mp++) {
                const int m0 = 2 * mp, m1 = 2 * mp + 1;
                uint4 q0 = *(const uint4*)(sm + OFF_APK + apk1(ks, m0, lane));
                uint4 q1 = *(const uint4*)(sm + OFF_APK + apk1(ks, m1, lane));
                uint32_t A0[4] = {q0.x, q0.y, q0.z, q0.w};
                uint32_t A1[4] = {q1.x, q1.y, q1.z, q1.w};
                // pass hi (8 independent accs before any reuse)
#pragma unroll
                for (int nt = 0; nt < 4; nt++) mma_f16(acc[m0][nt], A0, bh[nt][0], bh[nt][1]);
#pragma unroll
                for (int nt = 0; nt < 4; nt++) mma_f16(acc[m1][nt], A1, bh[nt][0], bh[nt][1]);
                // pass lo
#pragma unroll
                for (int nt = 0; nt < 4; nt++) mma_f16(acc[m0][nt], A0, bl[nt][0], bl[nt][1]);
#pragma unroll
                for (int nt = 0; nt < 4; nt++) mma_f16(acc[m1][nt], A1, bl[nt][0], bl[nt][1]);
            }
            if (ks < 15) { cbh0 = nh0; cbh1 = nh1; cbl0 = nl0; cbl1 = nl1; }
        }

        if (h < 4) {
            // prefetch next head's B (latency hidden under partials)
            const uint4* b = (const uint4*)(g_w1pk + (size_t)((h + 1) * 16) * 16384);
            cbh0 = b[0 * 256 + tid]; cbh1 = b[1 * 256 + tid];
            cbl0 = b[2 * 256 + tid]; cbl1 = b[3 * 256 + tid];

            // ---------- per-head SIMT partials -> red4[h], NO sync ----------
            float4* red4h = (float4*)(sm + OFF_SCR + h * 8192);
            if      (h == 0) part_g2<1>(acc, b1r, w2S4 + w2off[0], red4h, w, gq, cc);
            else if (h == 3) part_g2<4>(acc, b1r, w2S4 + w2off[3], red4h, w, gq, cc);
            else if (h == 1) part_g2<3>(acc, b1r, w2S4 + w2off[1], red4h, w, gq, cc);
            else             part_g2<3>(acc, b1r, w2S4 + w2off[2], red4h, w, gq, cc);
        } else {
            // ---------- head 4: pack H1 fp16 frags into Apk ----------
            __syncthreads();   // all warps done reading A frags
#pragma unroll
            for (int q = 0; q < 2; q++) {
                const int ks2 = 2 * w + q;
#pragma unroll
                for (int mt = 0; mt < 4; mt++) {
                    uint4 fr;
                    fr.x = f2h2(fmaxf(acc[mt][2 * q][0] + b1r[4 * q + 0], 0.0f),
                                fmaxf(acc[mt][2 * q][1] + b1r[4 * q + 1], 0.0f));
                    fr.y = f2h2(fmaxf(acc[mt][2 * q][2] + b1r[4 * q + 0], 0.0f),
                                fmaxf(acc[mt][2 * q][3] + b1r[4 * q + 1], 0.0f));
                    fr.z = f2h2(fmaxf(acc[mt][2 * q + 1][0] + b1r[4 * q + 2], 0.0f),
                                fmaxf(acc[mt][2 * q + 1][1] + b1r[4 * q + 3], 0.0f));
                    fr.w = f2h2(fmaxf(acc[mt][2 * q + 1][2] + b1r[4 * q + 2], 0.0f),
                                fmaxf(acc[mt][2 * q + 1][3] + b1r[4 * q + 3], 0.0f));
                    *(uint4*)(sm + OFF_APK + apk1(ks2, mt, lane)) = fr;
                }
            }
            __syncthreads();

            // ---------- combined phase: reduce all 4 small heads + mask ------
            {
                const int hh = tid >> 6, m = tid & 63;
                const float4* rb = (const float4*)(sm + OFF_SCR + hh * 8192);
                float4 a4 = make_float4(0.f, 0.f, 0.f, 0.f);
#pragma unroll
                for (int wi = 0; wi < 8; wi++) {
                    float4 r = rb[m * 8 + wi];
                    a4.x += r.x; a4.y += r.y; a4.z += r.z; a4.w += r.w;
                }
                if (hh == 0)
                    maskS[m] = 1.0f / (1.0f + expf(-(a4.x + p.b2[0][0])));
                __syncthreads();    // maskS visible
                int g = g0 + m;
                if (hh >= 1 && g < n) {
                    float mk = maskS[m];
                    float vo[4] = {a4.x, a4.y, a4.z, a4.w};
                    if (hh == 1) {
#pragma unroll
                        for (int o = 0; o < 3; o++) {
                            float val = vo[o] + p.b2[1][o];
                            p.out[59 * n + g * 3 + o] = val;                   // dx_out
                            p.out[g * 3 + o] = p.pnt[g * 3 + o] + val * mk;    // pts
                        }
                    } else if (hh == 2) {
#pragma unroll
                        for (int o = 0; o < 3; o++) {
                            float val = vo[o] + p.b2[2][o];
                            p.out[3 * n + g * 3 + o] = p.scl[g * 3 + o] + val * mk;
                        }
                    } else {
#pragma unroll
                        for (int o = 0; o < 4; o++) {
                            float val = vo[o] + p.b2[3][o];
                            p.out[6 * n + g * 4 + o] = p.rot[g * 4 + o] + val * mk;
                        }
                    }
                }
            }

            // ---------- head 4 GEMM2 on HMMA (2-pass) + epilogue ----------
#pragma unroll 1
            for (int jb = 0; jb < 3; jb++) {
                int t = w + 8 * jb;            // 0..23
                int mt = t / 6, nt2 = t % 6;
                float d0[4] = {0, 0, 0, 0}, d1[4] = {0, 0, 0, 0};
                const uint4* wb = (const uint4*)g_w2pk + (4 + nt2) * 16 * 32;
                uint4 B = wb[lane];
#pragma unroll 1
                for (int ks2 = 0; ks2 < 16; ks2++) {
                    uint4 Bn;
                    if (ks2 < 15) Bn = wb[(ks2 + 1) * 32 + lane];
                    uint4 ah4 = *(const uint4*)(sm + OFF_APK + apk1(ks2, mt, lane));
                    uint32_t ah[4] = {ah4.x, ah4.y, ah4.z, ah4.w};
                    mma_f16(d0, ah, B.x, B.y);    // H1*Bhi
                    mma_f16(d1, ah, B.z, B.w);    // H1*Blo
                    if (ks2 < 15) B = Bn;
                }
#pragma unroll
                for (int e = 0; e < 4; e++) {
                    int o = nt2 * 8 + cc * 2 + (e & 1);
                    int m = mt * 16 + gq + ((e >> 1) << 3);
                    int g = g0 + m;
                    if (g < n) {
                        float val = d0[e] + d1[e] + p.b2[4][o];
                        float mk = maskS[m];
                        p.out[oDSH + g * 48 + o] = val;
                        p.out[oSHS + g * 48 + o] = p.shs[g * 48 + o] + val * mk;
                    }
                }
            }
        }
    }
}

extern "C" void kernel_launch(void* const* d_in, const int* in_sizes, int n_in,
                              void* d_out, int out_size) {
    Params p;
    p.opa = (const float*)d_in[0];
    p.shs = (const float*)d_in[1];
    p.tim = (const float*)d_in[2];
    p.sem = (const float*)d_in[3];
    p.pnt = (const float*)d_in[4];
    p.scl = (const float*)d_in[5];
    p.rot = (const float*)d_in[6];
    p.dx  = (const float*)d_in[7];
    for (int h = 0; h < 5; h++) {
        p.w1[h] = (const float*)d_in[8 + h * 4 + 0];
        p.b1[h] = (const float*)d_in[8 + h * 4 + 1];
        p.w2[h] = (const float*)d_in[8 + h * 4 + 2];
        p.b2[h] = (const float*)d_in[8 + h * 4 + 3];
    }
    p.out = (float*)d_out;
    p.n   = in_sizes[0];

    prep_all<<<100, 256>>>(p.w1[0], p.w1[1], p.w1[2], p.w1[3], p.w1[4],
                           p.w2[0], p.w2[1], p.w2[2], p.w2[3], p.w2[4]);

    cudaFuncSetAttribute(deform6, cudaFuncAttributeMaxDynamicSharedMemorySize, SMEM_BYTES);
    const int grid = (p.n + 63) / 64;
    deform6<<<grid, 256, SMEM_BYTES>>>(p);
}

// round 11
// speedup vs baseline: 6.3199x; 1.6558x over previous
#include <cuda_runtime.h>
#include <cuda_fp16.h>
#include <cstdint>

// ============================================================================
// Deformation net, HMMA fp16 single-pass (A fp16, B fp16, fp32 accum).
// CTA = 64 points, 256 threads (8 warps), 2 CTAs/SM.
// Warp w owns GEMM1 cols [w*32, w*32+32) (nt=4).
//  - A staged via coalesced per-array copies (branch-free), ReLU in pack.
//  - W1 pre-packed per-thread fp16 B-frag images; LDG.128 double-buffered.
//  - Heads 0-3 GEMM2: SIMT fp32 partials (syncless) into red4[h]; all
//    reductions + outputs in one combined phase. Head 4 GEMM2 on HMMA.
// ============================================================================

#define DEVI __device__ __forceinline__

// W1 packed frags: [head][ks][slot 0..1][tid 0..255] x uint4 = 640KB
//  slot0 = nt0,nt1 ; slot1 = nt2,nt3
__device__ __align__(16) unsigned char g_w1pk[5 * 16 * 2 * 256 * 16];
// W2 packed frags (head 4 uses slots 4..9): [slot][ks2][lane] x uint2
__device__ __align__(8) unsigned char g_w2pk[10 * 16 * 32 * 8];

DEVI uint32_t f2h2(float x, float y) {
    __half2 h = __floats2half2_rn(x, y);    // low = x, high = y
    return *(uint32_t*)&h;
}

__global__ void prep_all(const float* w10, const float* w11, const float* w12,
                         const float* w13, const float* w14,
                         const float* w20, const float* w21, const float* w22,
                         const float* w23, const float* w24) {
    int idx = blockIdx.x * blockDim.x + threadIdx.x;
    if (idx < 20480) {                 // 5 heads * 16 ks * 256 tid
        const float* ws[5] = {w10, w11, w12, w13, w14};
        int h = idx >> 12, ks = (idx >> 8) & 15, tid = idx & 255;
        int w = tid >> 5, lane = tid & 31;
        int gq = lane >> 2, cc = lane & 3;
        const float* W = ws[h];
        uint32_t hb[4][2];
#pragma unroll
        for (int ntl = 0; ntl < 4; ntl++) {
            int nn = (w * 4 + ntl) * 8 + gq;
            int k0 = ks * 16 + cc * 2;
            float v[4];
            int kk[4] = {k0, k0 + 1, k0 + 8, k0 + 9};
#pragma unroll
            for (int j = 0; j < 4; j++)
                v[j] = (kk[j] < 255 && nn < 255) ? W[kk[j] * 255 + nn] : 0.0f;
            hb[ntl][0] = f2h2(v[0], v[1]);
            hb[ntl][1] = f2h2(v[2], v[3]);
        }
        uint4* base = (uint4*)(g_w1pk + (size_t)(h * 16 + ks) * 8192);
        base[0 * 256 + tid] = make_uint4(hb[0][0], hb[0][1], hb[1][0], hb[1][1]);
        base[1 * 256 + tid] = make_uint4(hb[2][0], hb[2][1], hb[3][0], hb[3][1]);
    } else if (idx < 20480 + 5120) {
        const float* ws[5] = {w20, w21, w22, w23, w24};
        const int ods[5] = {1, 3, 3, 4, 48};
        int j = idx - 20480;
        int slot = j >> 9, ks2 = (j >> 5) & 15, lane = j & 31;
        int head = (slot < 4) ? slot : 4;
        int nt2  = (slot < 4) ? 0 : slot - 4;
        int od = ods[head];
        const float* W = ws[head];
        int nn = nt2 * 8 + (lane >> 2);
        int k0 = ks2 * 16 + (lane & 3) * 2;
        float v[4];
        int kk[4] = {k0, k0 + 1, k0 + 8, k0 + 9};
#pragma unroll
        for (int q = 0; q < 4; q++)
            v[q] = (kk[q] < 255 && nn < od) ? W[kk[q] * od + nn] : 0.0f;
        ((uint2*)g_w2pk)[(slot * 16 + ks2) * 32 + lane] =
            make_uint2(f2h2(v[0], v[1]), f2h2(v[2], v[3]));
    }
}

DEVI void mma_f16(float* d, const uint32_t* a, uint32_t b0, uint32_t b1) {
    asm("mma.sync.aligned.m16n8k16.row.col.f32.f16.f16.f32 "
        "{%0,%1,%2,%3}, {%4,%5,%6,%7}, {%8,%9}, {%0,%1,%2,%3};"
        : "+f"(d[0]), "+f"(d[1]), "+f"(d[2]), "+f"(d[3])
        : "r"(a[0]), "r"(a[1]), "r"(a[2]), "r"(a[3]), "r"(b0), "r"(b1));
}

struct Params {
    const float* opa; const float* shs; const float* tim; const float* sem;
    const float* pnt; const float* scl; const float* rot; const float* dx;
    const float* w1[5]; const float* b1[5]; const float* w2[5]; const float* b2[5];
    float* out; int n;
};

// ---- smem layout (bytes), ~77 KB (2 CTAs/SM) ----------------------------------
#define OFF_APK   0                    // 16ks x 4mt x 32lane x 16B = 32768
#define OFF_SCR   32768                // staging 32x257 f32; later red4[4] x 8KB
#define OFF_W2S4  (OFF_SCR + 32896)
#define OFF_MASK  (OFF_W2S4 + 11264)
#define OFF_TPE   (OFF_MASK + 256)
#define SMEM_BYTES (OFF_TPE + 256)

DEVI uint32_t apk1(int ks, int mt, int lane) {
    return (uint32_t)(((ks * 4 + mt) * 32 + lane) * 16);
}

// ---- per-head SIMT GEMM2 partials (syncless): write red4h ---------------------
template <int OD>
DEVI void part_g2(const float (*acc)[4][4], const float* b1r, const float* w2h,
                  float4* red4h, int w, int gq, int cc) {
    float wv[4][2][OD];
#pragma unroll
    for (int nt = 0; nt < 4; nt++)
#pragma unroll
        for (int e1 = 0; e1 < 2; e1++) {
            int k = w * 32 + nt * 8 + cc * 2 + e1;
#pragma unroll
            for (int o = 0; o < OD; o++)
                wv[nt][e1][o] = (k < 255) ? w2h[k * OD + o] : 0.0f;
        }
    float part[8][OD];
#pragma unroll
    for (int s = 0; s < 8; s++)
#pragma unroll
        for (int o = 0; o < OD; o++) part[s][o] = 0.0f;
#pragma unroll
    for (int mt = 0; mt < 4; mt++)
#pragma unroll
        for (int nt = 0; nt < 4; nt++)
#pragma unroll
            for (int e = 0; e < 4; e++) {
                float hv = fmaxf(acc[mt][nt][e] + b1r[nt * 2 + (e & 1)], 0.0f);
                int s = mt * 2 + (e >> 1);
#pragma unroll
                for (int o = 0; o < OD; o++)
                    part[s][o] += hv * wv[nt][e & 1][o];
            }
#pragma unroll
    for (int s = 0; s < 8; s++)
#pragma unroll
        for (int o = 0; o < OD; o++) {
            float v = part[s][o];
            v += __shfl_xor_sync(0xffffffffu, v, 1);
            v += __shfl_xor_sync(0xffffffffu, v, 2);
            part[s][o] = v;
        }
    if (cc == 0) {
#pragma unroll
        for (int s = 0; s < 8; s++) {
            int m = (s >> 1) * 16 + gq + (s & 1) * 8;
            red4h[m * 8 + w] = make_float4(part[s][0],
                                           OD > 1 ? part[s][1] : 0.0f,
                                           OD > 2 ? part[s][2] : 0.0f,
                                           OD > 3 ? part[s][3] : 0.0f);
        }
    }
}

__global__ __launch_bounds__(256, 2)
void deform7(Params p) {
    extern __shared__ __align__(16) unsigned char sm[];
    float*  H1raw = (float*)(sm + OFF_SCR);     // staging, 32 rows x stride 257
    float*  w2S4  = (float*)(sm + OFF_W2S4);
    float*  maskS = (float*)(sm + OFF_MASK);
    float*  tpeS  = (float*)(sm + OFF_TPE);

    const int tid = threadIdx.x, w = tid >> 5, lane = tid & 31;
    const int gq = lane >> 2, cc = lane & 3;
    const int n = p.n, g0 = blockIdx.x * 64;
    const int oSHS = 11 * n, oDSH = 62 * n;
    const int w2off[4] = {0, 256, 1024, 1792};
    const int ods4[4] = {1, 3, 3, 4};

    if (tid < 32) {
        float t = p.tim[0];
        float freq = exp2f((float)(2 * tid) * (13.287712379549449f / 32.0f));
        float a = t / freq;
        tpeS[2 * tid] = sinf(a);
        tpeS[2 * tid + 1] = cosf(a);
    }
#pragma unroll 1
    for (int hh = 0; hh < 4; hh++)
        for (int i = tid; i < 255 * ods4[hh]; i += 256)
            w2S4[w2off[hh] + i] = p.w2[hh][i];
    __syncthreads();

    // ---- build A (raw, no relu), two 32-row halves; pack fp16 frags -------
#pragma unroll 1
    for (int half = 0; half < 2; half++) {
        const int base = g0 + half * 32;
        if (base + 32 <= n) {
            // ---- coalesced branch-free staging ----
            const float4* sem4 = (const float4*)p.sem;
            const float4* shs4 = (const float4*)p.shs;
#pragma unroll 1
            for (int i = tid; i < 1024; i += 256) {      // sem: 32 x 128
                int r = i & 31, c = i >> 5;
                float4 v = sem4[(base + r) * 32 + c];
                float* d = H1raw + r * 257 + 59 + c * 4;
                d[0] = v.x; d[1] = v.y; d[2] = v.z; d[3] = v.w;
            }
#pragma unroll 1
            for (int i = tid; i < 384; i += 256) {       // shs: 32 x 48
                int r = i & 31, c = i >> 5;
                float4 v = shs4[(base + r) * 12 + c];
                float* d = H1raw + r * 257 + 11 + c * 4;
                d[0] = v.x; d[1] = v.y; d[2] = v.z; d[3] = v.w;
            }
#pragma unroll 1
            for (int i = tid; i < 416; i += 256) {       // pnt/rot/scl/dx: 13/row
                int r = i % 32, j = i / 32;
                int g = base + r;
                if (j < 3)       H1raw[r * 257 + j] = p.pnt[g * 3 + j];
                else if (j < 7)  H1raw[r * 257 + j] = p.rot[g * 4 + j - 3];
                else if (j < 10) H1raw[r * 257 + j] = p.scl[g * 3 + j - 7];
                else             H1raw[r * 257 + 177 + j] = p.dx[g * 3 + j - 10];
            }
            if (tid < 32) {
                int g = base + tid;
                H1raw[tid * 257 + 10]  = p.opa[g];
                H1raw[tid * 257 + 190] = p.tim[g];
                H1raw[tid * 257 + 255] = 0.0f;
            }
#pragma unroll 1
            for (int i = tid; i < 2048; i += 256) {      // tpe: 32 x 64
                int r = i & 31, j = i >> 5;
                H1raw[r * 257 + 191 + j] = tpeS[j];
            }
        } else {
            // ---- fallback (tail CTA when n % 64 != 0) ----
            for (int idx = tid; idx < 32 * 256; idx += 256) {
                int lr = idx >> 8, k = idx & 255;
                int g = base + lr;
                float v = 0.0f;
                if (g < n && k < 255) {
                    if      (k < 3)    v = p.pnt[g * 3 + k];
                    else if (k < 7)    v = p.rot[g * 4 + (k - 3)];
                    else if (k < 10)   v = p.scl[g * 3 + (k - 7)];
                    else if (k == 10)  v = p.opa[g];
                    else if (k < 59)   v = p.shs[g * 48 + (k - 11)];
                    else if (k < 187)  v = p.sem[g * 128 + (k - 59)];
                    else if (k < 190)  v = p.dx[g * 3 + (k - 187)];
                    else if (k == 190) v = p.tim[g];
                    else               v = tpeS[k - 191];
                }
                H1raw[lr * 257 + k] = v;
            }
            if (tid < 32) H1raw[tid * 257 + 255] = 0.0f;
        }
        __syncthreads();
        // pack: relu applied here
#pragma unroll 1
        for (int j = 0; j < 4; j++) {
            int f = w * 4 + j;                 // 0..31 = ks*2 + mtl
            int ks = f >> 1, mtl = f & 1;
            int mt = half * 2 + mtl;
            int r0 = mtl * 16 + gq, r1 = r0 + 8;
            int k0 = ks * 16 + cc * 2;
            uint4 fr;
            fr.x = f2h2(fmaxf(H1raw[r0 * 257 + k0],     0.0f),
                        fmaxf(H1raw[r0 * 257 + k0 + 1], 0.0f));
            fr.y = f2h2(fmaxf(H1raw[r1 * 257 + k0],     0.0f),
                        fmaxf(H1raw[r1 * 257 + k0 + 1], 0.0f));
            fr.z = f2h2(fmaxf(H1raw[r0 * 257 + k0 + 8], 0.0f),
                        fmaxf(H1raw[r0 * 257 + k0 + 9], 0.0f));
            fr.w = f2h2(fmaxf(H1raw[r1 * 257 + k0 + 8], 0.0f),
                        fmaxf(H1raw[r1 * 257 + k0 + 9], 0.0f));
            *(uint4*)(sm + OFF_APK + apk1(ks, mt, lane)) = fr;
        }
        __syncthreads();
    }
    if (tid < 64) { int g = g0 + tid; if (g < n) p.out[10 * n + g] = p.opa[g]; }

    // prefetch B(h=0, ks=0)
    uint4 cb0, cb1;
    {
        const uint4* b = (const uint4*)g_w1pk;
        cb0 = b[tid]; cb1 = b[256 + tid];
    }

#pragma unroll 1
    for (int h = 0; h < 5; h++) {
        float b1r[8];
#pragma unroll
        for (int nt = 0; nt < 4; nt++)
#pragma unroll
            for (int e = 0; e < 2; e++) {
                int nn = w * 32 + nt * 8 + cc * 2 + e;
                b1r[nt * 2 + e] = (nn < 255) ? p.b1[h][nn] : 0.0f;
            }

        float acc[4][4][4];
#pragma unroll
        for (int a = 0; a < 4; a++)
#pragma unroll
            for (int b = 0; b < 4; b++)
#pragma unroll
                for (int e = 0; e < 4; e++) acc[a][b][e] = 0.0f;

        // ---------- GEMM1 mainloop: single fp16 pass, no syncs ----------
#pragma unroll 1
        for (int ks = 0; ks < 16; ks++) {
            uint4 nb0, nb1;
            if (ks < 15) {
                const uint4* b = (const uint4*)(g_w1pk + (size_t)(h * 16 + ks + 1) * 8192);
                nb0 = b[tid]; nb1 = b[256 + tid];
            }
            const uint32_t bh[4][2] = {{cb0.x, cb0.y}, {cb0.z, cb0.w},
                                       {cb1.x, cb1.y}, {cb1.z, cb1.w}};
#pragma unroll
            for (int mp = 0; mp < 2; mp++) {
                const int m0 = 2 * mp, m1 = 2 * mp + 1;
                uint4 q0 = *(const uint4*)(sm + OFF_APK + apk1(ks, m0, lane));
                uint4 q1 = *(const uint4*)(sm + OFF_APK + apk1(ks, m1, lane));
                uint32_t A0[4] = {q0.x, q0.y, q0.z, q0.w};
                uint32_t A1[4] = {q1.x, q1.y, q1.z, q1.w};
#pragma unroll
                for (int nt = 0; nt < 4; nt++) mma_f16(acc[m0][nt], A0, bh[nt][0], bh[nt][1]);
#pragma unroll
                for (int nt = 0; nt < 4; nt++) mma_f16(acc[m1][nt], A1, bh[nt][0], bh[nt][1]);
            }
            if (ks < 15) { cb0 = nb0; cb1 = nb1; }
        }

        if (h < 4) {
            // prefetch next head's B (latency hidden under partials)
            const uint4* b = (const uint4*)(g_w1pk + (size_t)((h + 1) * 16) * 8192);
            cb0 = b[tid]; cb1 = b[256 + tid];

            // ---------- per-head SIMT partials -> red4[h], NO sync ----------
            float4* red4h = (float4*)(sm + OFF_SCR + h * 8192);
            if      (h == 0) part_g2<1>(acc, b1r, w2S4 + w2off[0], red4h, w, gq, cc);
            else if (h == 3) part_g2<4>(acc, b1r, w2S4 + w2off[3], red4h, w, gq, cc);
            else if (h == 1) part_g2<3>(acc, b1r, w2S4 + w2off[1], red4h, w, gq, cc);
            else             part_g2<3>(acc, b1r, w2S4 + w2off[2], red4h, w, gq, cc);
        } else {
            // ---------- head 4: pack H1 fp16 frags into Apk ----------
            __syncthreads();   // all warps done reading A frags
#pragma unroll
            for (int q = 0; q < 2; q++) {
                const int ks2 = 2 * w + q;
#pragma unroll
                for (int mt = 0; mt < 4; mt++) {
                    uint4 fr;
                    fr.x = f2h2(fmaxf(acc[mt][2 * q][0] + b1r[4 * q + 0], 0.0f),
                                fmaxf(acc[mt][2 * q][1] + b1r[4 * q + 1], 0.0f));
                    fr.y = f2h2(fmaxf(acc[mt][2 * q][2] + b1r[4 * q + 0], 0.0f),
                                fmaxf(acc[mt][2 * q][3] + b1r[4 * q + 1], 0.0f));
                    fr.z = f2h2(fmaxf(acc[mt][2 * q + 1][0] + b1r[4 * q + 2], 0.0f),
                                fmaxf(acc[mt][2 * q + 1][1] + b1r[4 * q + 3], 0.0f));
                    fr.w = f2h2(fmaxf(acc[mt][2 * q + 1][2] + b1r[4 * q + 2], 0.0f),
                                fmaxf(acc[mt][2 * q + 1][3] + b1r[4 * q + 3], 0.0f));
                    *(uint4*)(sm + OFF_APK + apk1(ks2, mt, lane)) = fr;
                }
            }
            __syncthreads();

            // ---------- combined phase: reduce all 4 small heads + mask ------
            {
                const int hh = tid >> 6, m = tid & 63;
                const float4* rb = (const float4*)(sm + OFF_SCR + hh * 8192);
                float4 a4 = make_float4(0.f, 0.f, 0.f, 0.f);
#pragma unroll
                for (int wi = 0; wi < 8; wi++) {
                    float4 r = rb[m * 8 + wi];
                    a4.x += r.x; a4.y += r.y; a4.z += r.z; a4.w += r.w;
                }
                if (hh == 0)
                    maskS[m] = 1.0f / (1.0f + expf(-(a4.x + p.b2[0][0])));
                __syncthreads();    // maskS visible
                int g = g0 + m;
                if (hh >= 1 && g < n) {
                    float mk = maskS[m];
                    float vo[4] = {a4.x, a4.y, a4.z, a4.w};
                    if (hh == 1) {
#pragma unroll
                        for (int o = 0; o < 3; o++) {
                            float val = vo[o] + p.b2[1][o];
                            p.out[59 * n + g * 3 + o] = val;                   // dx_out
                            p.out[g * 3 + o] = p.pnt[g * 3 + o] + val * mk;    // pts
                        }
                    } else if (hh == 2) {
#pragma unroll
                        for (int o = 0; o < 3; o++) {
                            float val = vo[o] + p.b2[2][o];
                            p.out[3 * n + g * 3 + o] = p.scl[g * 3 + o] + val * mk;
                        }
                    } else {
#pragma unroll
                        for (int o = 0; o < 4; o++) {
                            float val = vo[o] + p.b2[3][o];
                            p.out[6 * n + g * 4 + o] = p.rot[g * 4 + o] + val * mk;
                        }
                    }
                }
            }

            // ---------- head 4 GEMM2 on HMMA (single pass) + epilogue --------
#pragma unroll 1
            for (int jb = 0; jb < 3; jb++) {
                int t = w + 8 * jb;            // 0..23
                int mt = t / 6, nt2 = t % 6;
                float d0[4] = {0, 0, 0, 0};
                const uint2* wb = (const uint2*)g_w2pk + (4 + nt2) * 16 * 32;
                uint2 B = wb[lane];
#pragma unroll 1
                for (int ks2 = 0; ks2 < 16; ks2++) {
                    uint2 Bn;
                    if (ks2 < 15) Bn = wb[(ks2 + 1) * 32 + lane];
                    uint4 ah4 = *(const uint4*)(sm + OFF_APK + apk1(ks2, mt, lane));
                    uint32_t ah[4] = {ah4.x, ah4.y, ah4.z, ah4.w};
                    mma_f16(d0, ah, B.x, B.y);
                    if (ks2 < 15) B = Bn;
                }
#pragma unroll
                for (int e = 0; e < 4; e++) {
                    int o = nt2 * 8 + cc * 2 + (e & 1);
                    int m = mt * 16 + gq + ((e >> 1) << 3);
                    int g = g0 + m;
                    if (g < n) {
                        float val = d0[e] + p.b2[4][o];
                        float mk = maskS[m];
                        p.out[oDSH + g * 48 + o] = val;
                        p.out[oSHS + g * 48 + o] = p.shs[g * 48 + o] + val * mk;
                    }
                }
            }
        }
    }
}

extern "C" void kernel_launch(void* const* d_in, const int* in_sizes, int n_in,
                              void* d_out, int out_size) {
    Params p;
    p.opa = (const float*)d_in[0];
    p.shs = (const float*)d_in[1];
    p.tim = (const float*)d_in[2];
    p.sem = (const float*)d_in[3];
    p.pnt = (const float*)d_in[4];
    p.scl = (const float*)d_in[5];
    p.rot = (const float*)d_in[6];
    p.dx  = (const float*)d_in[7];
    for (int h = 0; h < 5; h++) {
        p.w1[h] = (const float*)d_in[8 + h * 4 + 0];
        p.b1[h] = (const float*)d_in[8 + h * 4 + 1];
        p.w2[h] = (const float*)d_in[8 + h * 4 + 2];
        p.b2[h] = (const float*)d_in[8 + h * 4 + 3];
    }
    p.out = (float*)d_out;
    p.n   = in_sizes[0];

    prep_all<<<100, 256>>>(p.w1[0], p.w1[1], p.w1[2], p.w1[3], p.w1[4],
                           p.w2[0], p.w2[1], p.w2[2], p.w2[3], p.w2[4]);

    cudaFuncSetAttribute(deform7, cudaFuncAttributeMaxDynamicSharedMemorySize, SMEM_BYTES);
    const int grid = (p.n + 63) / 64;
    deform7<<<grid, 256, SMEM_BYTES>>>(p);
}

// round 12
// speedup vs baseline: 6.4927x; 1.0273x over previous
#include <cuda_runtime.h>
#include <cuda_fp16.h>
#include <cstdint>

// ============================================================================
// Deformation net, HMMA fp16 single-pass (fp32 accum).
// CTA = 32 points, 128 threads (4 warps), 4 CTAs/SM (phase-overlap streams).
// Warp w owns GEMM1 cols [w*64, w*64+64) (nt=8), mt=2 (rows 0..31).
//  - A staged coalesced (16-row chunks), ReLU in pack, fp16 frags in smem.
//  - W1 pre-packed per-thread fp16 B-frag images; 4x LDG.128/ks double-buffer.
//  - Heads 0-3 GEMM2: SIMT fp32 partials, K-split over 4 warps -> red[h];
//    one combined reduce/output phase. Head 4 GEMM2 on HMMA.
// ============================================================================

#define DEVI __device__ __forceinline__

// W1 packed frags: [head][ks][slot 0..3][tid 0..127] x uint4 = 640KB
//  slot s holds nt-frags {2s, 2s+1} for thread tid.
__device__ __align__(16) unsigned char g_w1pk[5 * 16 * 4 * 128 * 16];
// W2 packed frags (head 4 uses slots 4..9): [slot][ks2][lane] x uint2
__device__ __align__(8) unsigned char g_w2pk[10 * 16 * 32 * 8];

DEVI uint32_t f2h2(float x, float y) {
    __half2 h = __floats2half2_rn(x, y);    // low = x, high = y
    return *(uint32_t*)&h;
}

__global__ void prep_all(const float* w10, const float* w11, const float* w12,
                         const float* w13, const float* w14,
                         const float* w20, const float* w21, const float* w22,
                         const float* w23, const float* w24) {
    int idx = blockIdx.x * blockDim.x + threadIdx.x;
    if (idx < 10240) {                 // 5 heads * 16 ks * 128 tid
        const float* ws[5] = {w10, w11, w12, w13, w14};
        int h = idx >> 11, ks = (idx >> 7) & 15, tid = idx & 127;
        int w = tid >> 5, lane = tid & 31;
        int gq = lane >> 2, cc = lane & 3;
        const float* W = ws[h];
        uint4* base = (uint4*)(g_w1pk + (size_t)(h * 16 + ks) * 8192);
#pragma unroll
        for (int s = 0; s < 4; s++) {
            uint32_t fr[4];
#pragma unroll
            for (int half = 0; half < 2; half++) {
                int ntl = 2 * s + half;
                int nn = w * 64 + ntl * 8 + gq;
                int k0 = ks * 16 + cc * 2;
                float v[4];
                int kk[4] = {k0, k0 + 1, k0 + 8, k0 + 9};
#pragma unroll
                for (int j = 0; j < 4; j++)
                    v[j] = (kk[j] < 255 && nn < 255) ? W[kk[j] * 255 + nn] : 0.0f;
                fr[half * 2 + 0] = f2h2(v[0], v[1]);
                fr[half * 2 + 1] = f2h2(v[2], v[3]);
            }
            base[s * 128 + tid] = make_uint4(fr[0], fr[1], fr[2], fr[3]);
        }
    } else if (idx < 10240 + 5120) {
        const float* ws[5] = {w20, w21, w22, w23, w24};
        const int ods[5] = {1, 3, 3, 4, 48};
        int j = idx - 10240;
        int slot = j >> 9, ks2 = (j >> 5) & 15, lane = j & 31;
        int head = (slot < 4) ? slot : 4;
        int nt2  = (slot < 4) ? 0 : slot - 4;
        int od = ods[head];
        const float* W = ws[head];
        int nn = nt2 * 8 + (lane >> 2);
        int k0 = ks2 * 16 + (lane & 3) * 2;
        float v[4];
        int kk[4] = {k0, k0 + 1, k0 + 8, k0 + 9};
#pragma unroll
        for (int q = 0; q < 4; q++)
            v[q] = (kk[q] < 255 && nn < od) ? W[kk[q] * od + nn] : 0.0f;
        ((uint2*)g_w2pk)[(slot * 16 + ks2) * 32 + lane] =
            make_uint2(f2h2(v[0], v[1]), f2h2(v[2], v[3]));
    }
}

DEVI void mma_f16(float* d, const uint32_t* a, uint32_t b0, uint32_t b1) {
    asm("mma.sync.aligned.m16n8k16.row.col.f32.f16.f16.f32 "
        "{%0,%1,%2,%3}, {%4,%5,%6,%7}, {%8,%9}, {%0,%1,%2,%3};"
        : "+f"(d[0]), "+f"(d[1]), "+f"(d[2]), "+f"(d[3])
        : "r"(a[0]), "r"(a[1]), "r"(a[2]), "r"(a[3]), "r"(b0), "r"(b1));
}

struct Params {
    const float* opa; const float* shs; const float* tim; const float* sem;
    const float* pnt; const float* scl; const float* rot; const float* dx;
    const float* w1[5]; const float* b1[5]; const float* w2[5]; const float* b2[5];
    float* out; int n;
};

// ---- smem layout (bytes), ~44.5 KB (4 CTAs/SM) --------------------------------
#define OFF_APK   0                    // 16ks x 2mt x 32lane x 16B = 16384
#define OFF_SCR   16384                // staging 16x257 f32 (16448); later red[4]x2KB
#define OFF_W2S4  (OFF_SCR + 16448)
#define OFF_MASK  (OFF_W2S4 + 11264)
#define OFF_TPE   (OFF_MASK + 128)
#define SMEM_BYTES (OFF_TPE + 256)

DEVI uint32_t apk1(int ks, int mt, int lane) {
    return (uint32_t)(((ks * 2 + mt) * 32 + lane) * 16);
}

// ---- per-head SIMT GEMM2 partials (syncless): K-split over 4 warps ------------
template <int OD>
DEVI void part_g2(const float (*acc)[8][4], const float* b1r, const float* w2h,
                  float4* redh, int w, int gq, int cc) {
    float part[4][OD];
#pragma unroll
    for (int s = 0; s < 4; s++)
#pragma unroll
        for (int o = 0; o < OD; o++) part[s][o] = 0.0f;
#pragma unroll
    for (int nt = 0; nt < 8; nt++) {
        float wv[2][OD];
#pragma unroll
        for (int e1 = 0; e1 < 2; e1++) {
            int k = w * 64 + nt * 8 + cc * 2 + e1;
#pragma unroll
            for (int o = 0; o < OD; o++)
                wv[e1][o] = (k < 255) ? w2h[k * OD + o] : 0.0f;
        }
#pragma unroll
        for (int mt = 0; mt < 2; mt++)
#pragma unroll
            for (int e = 0; e < 4; e++) {
                float hv = fmaxf(acc[mt][nt][e] + b1r[nt * 2 + (e & 1)], 0.0f);
                int s = mt * 2 + (e >> 1);
#pragma unroll
                for (int o = 0; o < OD; o++)
                    part[s][o] += hv * wv[e & 1][o];
            }
    }
#pragma unroll
    for (int s = 0; s < 4; s++)
#pragma unroll
        for (int o = 0; o < OD; o++) {
            float v = part[s][o];
            v += __shfl_xor_sync(0xffffffffu, v, 1);
            v += __shfl_xor_sync(0xffffffffu, v, 2);
            part[s][o] = v;
        }
    if (cc == 0) {
#pragma unroll
        for (int s = 0; s < 4; s++) {
            int m = (s >> 1) * 16 + gq + (s & 1) * 8;
            redh[m * 4 + w] = make_float4(part[s][0],
                                          OD > 1 ? part[s][1] : 0.0f,
                                          OD > 2 ? part[s][2] : 0.0f,
                                          OD > 3 ? part[s][3] : 0.0f);
        }
    }
}

__global__ __launch_bounds__(128, 4)
void deform8(Params p) {
    extern __shared__ __align__(16) unsigned char sm[];
    float*  H1raw = (float*)(sm + OFF_SCR);     // 16 rows x stride 257
    float*  w2S4  = (float*)(sm + OFF_W2S4);
    float*  maskS = (float*)(sm + OFF_MASK);
    float*  tpeS  = (float*)(sm + OFF_TPE);

    const int tid = threadIdx.x, w = tid >> 5, lane = tid & 31;
    const int gq = lane >> 2, cc = lane & 3;
    const int n = p.n, g0 = blockIdx.x * 32;
    const int oSHS = 11 * n, oDSH = 62 * n;
    const int w2off[4] = {0, 256, 1024, 1792};
    const int ods4[4] = {1, 3, 3, 4};

    // prefetch B(h=0, ks=0) early
    uint4 cb[4];
    {
        const uint4* b = (const uint4*)g_w1pk;
#pragma unroll
        for (int i = 0; i < 4; i++) cb[i] = b[i * 128 + tid];
    }

    if (tid < 32) {
        float t = p.tim[0];
        float freq = exp2f((float)(2 * tid) * (13.287712379549449f / 32.0f));
        float a = t / freq;
        tpeS[2 * tid] = sinf(a);
        tpeS[2 * tid + 1] = cosf(a);
    }
#pragma unroll 1
    for (int hh = 0; hh < 4; hh++)
        for (int i = tid; i < 255 * ods4[hh]; i += 128)
            w2S4[w2off[hh] + i] = p.w2[hh][i];
    __syncthreads();

    // ---- build A (raw), two 16-row chunks; pack fp16 frags into Apk --------
#pragma unroll 1
    for (int half = 0; half < 2; half++) {
        const int base = g0 + half * 16;
        if (base + 16 <= n) {
            const float4* sem4 = (const float4*)p.sem;
            const float4* shs4 = (const float4*)p.shs;
#pragma unroll 1
            for (int i = tid; i < 512; i += 128) {       // sem: 16 x 128
                int r = i & 15, c = i >> 4;
                float4 v = sem4[(base + r) * 32 + c];
                float* d = H1raw + r * 257 + 59 + c * 4;
                d[0] = v.x; d[1] = v.y; d[2] = v.z; d[3] = v.w;
            }
#pragma unroll 1
            for (int i = tid; i < 192; i += 128) {       // shs: 16 x 48
                int r = i & 15, c = i >> 4;
                float4 v = shs4[(base + r) * 12 + c];
                float* d = H1raw + r * 257 + 11 + c * 4;
                d[0] = v.x; d[1] = v.y; d[2] = v.z; d[3] = v.w;
            }
#pragma unroll 1
            for (int i = tid; i < 208; i += 128) {       // pnt/rot/scl/dx: 13/row
                int r = i & 15, j = i >> 4;
                int g = base + r;
                if (j < 3)       H1raw[r * 257 + j] = p.pnt[g * 3 + j];
                else if (j < 7)  H1raw[r * 257 + j] = p.rot[g * 4 + j - 3];
                else if (j < 10) H1raw[r * 257 + j] = p.scl[g * 3 + j - 7];
                else             H1raw[r * 257 + 177 + j] = p.dx[g * 3 + j - 10];
            }
            if (tid < 16) {
                int g = base + tid;
                H1raw[tid * 257 + 10]  = p.opa[g];
                H1raw[tid * 257 + 190] = p.tim[g];
                H1raw[tid * 257 + 255] = 0.0f;
            }
#pragma unroll 1
            for (int i = tid; i < 1024; i += 128) {      // tpe: 16 x 64
                int r = i & 15, j = i >> 4;
                H1raw[r * 257 + 191 + j] = tpeS[j];
            }
        } else {
            for (int idx = tid; idx < 16 * 256; idx += 128) {
                int lr = idx >> 8, k = idx & 255;
                int g = base + lr;
                float v = 0.0f;
                if (g < n && k < 255) {
                    if      (k < 3)    v = p.pnt[g * 3 + k];
                    else if (k < 7)    v = p.rot[g * 4 + (k - 3)];
                    else if (k < 10)   v = p.scl[g * 3 + (k - 7)];
                    else if (k == 10)  v = p.opa[g];
                    else if (k < 59)   v = p.shs[g * 48 + (k - 11)];
                    else if (k < 187)  v = p.sem[g * 128 + (k - 59)];
                    else if (k < 190)  v = p.dx[g * 3 + (k - 187)];
                    else if (k == 190) v = p.tim[g];
                    else               v = tpeS[k - 191];
                }
                H1raw[lr * 257 + k] = v;
            }
            if (tid < 16) H1raw[tid * 257 + 255] = 0.0f;
        }
        __syncthreads();
        // pack 16 frag-sets (ks 0..15, mt = half), 4 per warp; relu here
#pragma unroll 1
        for (int j = 0; j < 4; j++) {
            int ks = w * 4 + j;
            int r0 = gq, r1 = gq + 8;
            int k0 = ks * 16 + cc * 2;
            uint4 fr;
            fr.x = f2h2(fmaxf(H1raw[r0 * 257 + k0],     0.0f),
                        fmaxf(H1raw[r0 * 257 + k0 + 1], 0.0f));
            fr.y = f2h2(fmaxf(H1raw[r1 * 257 + k0],     0.0f),
                        fmaxf(H1raw[r1 * 257 + k0 + 1], 0.0f));
            fr.z = f2h2(fmaxf(H1raw[r0 * 257 + k0 + 8], 0.0f),
                        fmaxf(H1raw[r0 * 257 + k0 + 9], 0.0f));
            fr.w = f2h2(fmaxf(H1raw[r1 * 257 + k0 + 8], 0.0f),
                        fmaxf(H1raw[r1 * 257 + k0 + 9], 0.0f));
            *(uint4*)(sm + OFF_APK + apk1(ks, half, lane)) = fr;
        }
        __syncthreads();
    }
    if (tid < 32) { int g = g0 + tid; if (g < n) p.out[10 * n + g] = p.opa[g]; }

#pragma unroll 1
    for (int h = 0; h < 5; h++) {
        float acc[2][8][4];
#pragma unroll
        for (int a = 0; a < 2; a++)
#pragma unroll
            for (int b = 0; b < 8; b++)
#pragma unroll
                for (int e = 0; e < 4; e++) acc[a][b][e] = 0.0f;

        // ---------- GEMM1 mainloop: single fp16 pass, no syncs ----------
#pragma unroll 1
        for (int ks = 0; ks < 16; ks++) {
            uint4 nb[4];
            if (ks < 15) {
                const uint4* b = (const uint4*)(g_w1pk + (size_t)(h * 16 + ks + 1) * 8192);
#pragma unroll
                for (int i = 0; i < 4; i++) nb[i] = b[i * 128 + tid];
            }
            // B frags: nt -> (cb[nt>>1].x,.y) if even, (.z,.w) if odd
            const uint32_t bf[8][2] = {
                {cb[0].x, cb[0].y}, {cb[0].z, cb[0].w},
                {cb[1].x, cb[1].y}, {cb[1].z, cb[1].w},
                {cb[2].x, cb[2].y}, {cb[2].z, cb[2].w},
                {cb[3].x, cb[3].y}, {cb[3].z, cb[3].w}};
#pragma unroll
            for (int mt = 0; mt < 2; mt++) {
                uint4 q = *(const uint4*)(sm + OFF_APK + apk1(ks, mt, lane));
                uint32_t A[4] = {q.x, q.y, q.z, q.w};
#pragma unroll
                for (int nt = 0; nt < 8; nt++)
                    mma_f16(acc[mt][nt], A, bf[nt][0], bf[nt][1]);
            }
            if (ks < 15) {
#pragma unroll
                for (int i = 0; i < 4; i++) cb[i] = nb[i];
            }
        }
        if (h < 4) {
            const uint4* b = (const uint4*)(g_w1pk + (size_t)((h + 1) * 16) * 8192);
#pragma unroll
            for (int i = 0; i < 4; i++) cb[i] = b[i * 128 + tid];
        }

        // b1 for this warp's n-slice (needed by partials / pack)
        float b1r[16];
#pragma unroll
        for (int nt = 0; nt < 8; nt++)
#pragma unroll
            for (int e = 0; e < 2; e++) {
                int nn = w * 64 + nt * 8 + cc * 2 + e;
                b1r[nt * 2 + e] = (nn < 255) ? p.b1[h][nn] : 0.0f;
            }

        if (h < 4) {
            // ---------- SIMT partials -> red[h], NO sync ----------
            float4* redh = (float4*)(sm + OFF_SCR + h * 2048);
            if      (h == 0) part_g2<1>(acc, b1r, w2S4 + w2off[0], redh, w, gq, cc);
            else if (h == 3) part_g2<4>(acc, b1r, w2S4 + w2off[3], redh, w, gq, cc);
            else if (h == 1) part_g2<3>(acc, b1r, w2S4 + w2off[1], redh, w, gq, cc);
            else             part_g2<3>(acc, b1r, w2S4 + w2off[2], redh, w, gq, cc);
        } else {
            // ---------- head 4: pack H1 fp16 frags into Apk ----------
            __syncthreads();   // all warps done reading A frags
#pragma unroll
            for (int j = 0; j < 4; j++) {
                const int ks2 = 4 * w + j;   // k-window = nt {2j, 2j+1}
#pragma unroll
                for (int mt = 0; mt < 2; mt++) {
                    uint4 fr;
                    fr.x = f2h2(fmaxf(acc[mt][2 * j][0] + b1r[4 * j + 0], 0.0f),
                                fmaxf(acc[mt][2 * j][1] + b1r[4 * j + 1], 0.0f));
                    fr.y = f2h2(fmaxf(acc[mt][2 * j][2] + b1r[4 * j + 0], 0.0f),
                                fmaxf(acc[mt][2 * j][3] + b1r[4 * j + 1], 0.0f));
                    fr.z = f2h2(fmaxf(acc[mt][2 * j + 1][0] + b1r[4 * j + 2], 0.0f),
                                fmaxf(acc[mt][2 * j + 1][1] + b1r[4 * j + 3], 0.0f));
                    fr.w = f2h2(fmaxf(acc[mt][2 * j + 1][2] + b1r[4 * j + 2], 0.0f),
                                fmaxf(acc[mt][2 * j + 1][3] + b1r[4 * j + 3], 0.0f));
                    *(uint4*)(sm + OFF_APK + apk1(ks2, mt, lane)) = fr;
                }
            }
            __syncthreads();

            // ---------- combined: reduce heads 0-3 (warp = head) + mask ------
            {
                const int hh = w, m = lane;
                const float4* rb = (const float4*)(sm + OFF_SCR + hh * 2048);
                float4 a4 = make_float4(0.f, 0.f, 0.f, 0.f);
#pragma unroll
                for (int wi = 0; wi < 4; wi++) {
                    float4 r = rb[m * 4 + wi];
                    a4.x += r.x; a4.y += r.y; a4.z += r.z; a4.w += r.w;
                }
                if (hh == 0)
                    maskS[m] = 1.0f / (1.0f + expf(-(a4.x + p.b2[0][0])));
                __syncthreads();    // maskS visible
                int g = g0 + m;
                if (hh >= 1 && g < n) {
                    float mk = maskS[m];
                    float vo[4] = {a4.x, a4.y, a4.z, a4.w};
                    if (hh == 1) {
#pragma unroll
                        for (int o = 0; o < 3; o++) {
                            float val = vo[o] + p.b2[1][o];
                            p.out[59 * n + g * 3 + o] = val;                   // dx_out
                            p.out[g * 3 + o] = p.pnt[g * 3 + o] + val * mk;    // pts
                        }
                    } else if (hh == 2) {
#pragma unroll
                        for (int o = 0; o < 3; o++) {
                            float val = vo[o] + p.b2[2][o];
                            p.out[3 * n + g * 3 + o] = p.scl[g * 3 + o] + val * mk;
                        }
                    } else {
#pragma unroll
                        for (int o = 0; o < 4; o++) {
                            float val = vo[o] + p.b2[3][o];
                            p.out[6 * n + g * 4 + o] = p.rot[g * 4 + o] + val * mk;
                        }
                    }
                }
            }

            // ---------- head 4 GEMM2 on HMMA: 12 jobs over 4 warps ----------
#pragma unroll 1
            for (int jb = 0; jb < 3; jb++) {
                int t = w + 4 * jb;            // 0..11
                int mt = t / 6, nt2 = t % 6;
                float d0[4] = {0, 0, 0, 0};
                const uint2* wb = (const uint2*)g_w2pk + (4 + nt2) * 16 * 32;
                uint2 B = wb[lane];
#pragma unroll 1
                for (int ks2 = 0; ks2 < 16; ks2++) {
                    uint2 Bn;
                    if (ks2 < 15) Bn = wb[(ks2 + 1) * 32 + lane];
                    uint4 ah4 = *(const uint4*)(sm + OFF_APK + apk1(ks2, mt, lane));
                    uint32_t ah[4] = {ah4.x, ah4.y, ah4.z, ah4.w};
                    mma_f16(d0, ah, B.x, B.y);
                    if (ks2 < 15) B = Bn;
                }
#pragma unroll
                for (int e = 0; e < 4; e++) {
                    int o = nt2 * 8 + cc * 2 + (e & 1);
                    int m = mt * 16 + gq + ((e >> 1) << 3);
                    int g = g0 + m;
                    if (g < n) {
                        float val = d0[e] + p.b2[4][o];
                        float mk = maskS[m];
                        p.out[oDSH + g * 48 + o] = val;
                        p.out[oSHS + g * 48 + o] = p.shs[g * 48 + o] + val * mk;
                    }
                }
            }
        }
    }
}

extern "C" void kernel_launch(void* const* d_in, const int* in_sizes, int n_in,
                              void* d_out, int out_size) {
    Params p;
    p.opa = (const float*)d_in[0];
    p.shs = (const float*)d_in[1];
    p.tim = (const float*)d_in[2];
    p.sem = (const float*)d_in[3];
    p.pnt = (const float*)d_in[4];
    p.scl = (const float*)d_in[5];
    p.rot = (const float*)d_in[6];
    p.dx  = (const float*)d_in[7];
    for (int h = 0; h < 5; h++) {
        p.w1[h] = (const float*)d_in[8 + h * 4 + 0];
        p.b1[h] = (const float*)d_in[8 + h * 4 + 1];
        p.w2[h] = (const float*)d_in[8 + h * 4 + 2];
        p.b2[h] = (const float*)d_in[8 + h * 4 + 3];
    }
    p.out = (float*)d_out;
    p.n   = in_sizes[0];

    prep_all<<<60, 256>>>(p.w1[0], p.w1[1], p.w1[2], p.w1[3], p.w1[4],
                          p.w2[0], p.w2[1], p.w2[2], p.w2[3], p.w2[4]);

    cudaFuncSetAttribute(deform8, cudaFuncAttributeMaxDynamicSharedMemorySize, SMEM_BYTES);
    const int grid = (p.n + 31) / 32;   // 6250
    deform8<<<grid, 128, SMEM_BYTES>>>(p);
}